// round 2
// baseline (speedup 1.0000x reference)
#include <cuda_runtime.h>
#include <math.h>

// Problem constants
#define B_  4
#define T_  2048
#define D_  1024
#define H_  16
#define HD_ 64
#define F_  128
#define C_  64
#define N_  32            // T/C
#define BT_ (B_*T_)       // 8192
#define BHT_ (B_*H_*T_)   // 131072
#define NCHUNK_ (B_*H_*N_) // 2048

// ---------------- scratch (device globals; no allocations allowed) ----------
__device__ float g_x [BT_*D_];        // normalized x
__device__ float g_q [BT_*D_];        // q projection [BT, D]
__device__ float g_k [BT_*D_];        // k projection
__device__ float g_v [BT_*D_];        // v projection
__device__ float g_qf[BHT_*F_];       // hedgehog q features [b,h,t,f]
__device__ float g_kf[BHT_*F_];       // hedgehog k features
__device__ float g_kv[NCHUNK_*F_*HD_];// per-chunk kv states -> exclusive cumsum
__device__ float g_o [BT_*D_];        // attention output in [B,T,H*HD]

// ---------------- packed f32x2 helpers (Blackwell FFMA2 path) ---------------
typedef unsigned long long u64;

__device__ __forceinline__ void ffma2(u64& d, u64 a, u64 b) {
    asm("fma.rn.f32x2 %0, %1, %2, %0;" : "+l"(d) : "l"(a), "l"(b));
}
__device__ __forceinline__ u64 pack2(float x, float y) {
    u64 r; asm("mov.b64 %0, {%1, %2};" : "=l"(r) : "f"(x), "f"(y)); return r;
}
__device__ __forceinline__ void unpack2(u64 v, float& lo, float& hi) {
    asm("mov.b64 {%0, %1}, %2;" : "=f"(lo), "=f"(hi) : "l"(v));
}

// ---------------- fused add + RMSNorm --------------------------------------
__global__ __launch_bounds__(256)
void addnorm_kernel(const float* __restrict__ hs, const float* __restrict__ res,
                    const float* __restrict__ w, float* __restrict__ resid_out,
                    float* __restrict__ x_out)
{
    __shared__ float red[8];
    const int row = blockIdx.x;
    const int t = threadIdx.x;
    const float4* h4 = (const float4*)(hs  + (size_t)row*D_);
    const float4* r4 = (const float4*)(res + (size_t)row*D_);
    float4*      ro4 = (float4*)(resid_out + (size_t)row*D_);
    float4*      xo4 = (float4*)(x_out     + (size_t)row*D_);

    float4 h = h4[t], r = r4[t];
    float4 s = make_float4(h.x+r.x, h.y+r.y, h.z+r.z, h.w+r.w);
    ro4[t] = s;
    float ss = s.x*s.x + s.y*s.y + s.z*s.z + s.w*s.w;
    #pragma unroll
    for (int o = 16; o; o >>= 1) ss += __shfl_xor_sync(0xffffffffu, ss, o);
    if ((t & 31) == 0) red[t >> 5] = ss;
    __syncthreads();
    float tot = 0.f;
    #pragma unroll
    for (int i = 0; i < 8; i++) tot += red[i];
    float rstd = rsqrtf(tot * (1.0f/1024.0f) + 1e-5f);
    float4 wv = ((const float4*)w)[t];
    xo4[t] = make_float4(s.x*rstd*wv.x, s.y*rstd*wv.y, s.z*rstd*wv.z, s.w*rstd*wv.w);
}

// ---------------- fp32 SGEMM with packed FFMA2 ------------------------------
// C[M,N] = A[M,K] @ B[K,N]. 128x128 tile, BK=8, 256 threads, 8x8 per thread.
// Accumulators are row-paired f32x2; A pairs load natively from As (row-major
// within As[k]); B broadcasts packed with mov.b64 (alu pipe, parallel to fma).
__global__ __launch_bounds__(256)
void sgemm128(const float* __restrict__ A, const float* __restrict__ B,
              float* __restrict__ C, int M, int N, int K)
{
    __shared__ __align__(16) float As[8][128];
    __shared__ __align__(16) float Bs[8][128];
    const int tid = threadIdx.x;
    const int bx = blockIdx.x, by = blockIdx.y;
    const int tx = tid & 15, ty = tid >> 4;

    const int aRow = tid >> 1;
    const int aCol = (tid & 1) * 4;
    const int bRow = tid >> 5;
    const int bCol = (tid & 31) * 4;

    const float* Ap = A + (size_t)(by*128 + aRow) * K + aCol;
    const float* Bp = B + (size_t)bRow * N + bx*128 + bCol;

    u64 acc[4][8];
    #pragma unroll
    for (int i = 0; i < 4; i++)
        #pragma unroll
        for (int j = 0; j < 8; j++) acc[i][j] = 0ull;

    // prologue: tile 0 -> smem
    {
        float4 a = *(const float4*)(Ap);
        As[aCol+0][aRow] = a.x; As[aCol+1][aRow] = a.y;
        As[aCol+2][aRow] = a.z; As[aCol+3][aRow] = a.w;
        *(float4*)&Bs[bRow][bCol] = *(const float4*)(Bp);
    }

    const int ntiles = K >> 3;
    for (int t = 0; t < ntiles; t++) {
        __syncthreads();
        // prefetch next tile into registers while computing on smem
        float4 na, nb;
        if (t + 1 < ntiles) {
            na = *(const float4*)(Ap + (t+1)*8);
            nb = *(const float4*)(Bp + (size_t)(t+1)*8 * N);
        }
        #pragma unroll
        for (int k = 0; k < 8; k++) {
            const u64* a0 = (const u64*)&As[k][ty*4];
            const u64* a1 = (const u64*)&As[k][ty*4 + 64];
            u64 ap[4] = { a0[0], a0[1], a1[0], a1[1] };
            float4 b0 = *(const float4*)&Bs[k][tx*4];
            float4 b1 = *(const float4*)&Bs[k][tx*4 + 64];
            u64 bb[8] = { pack2(b0.x,b0.x), pack2(b0.y,b0.y),
                          pack2(b0.z,b0.z), pack2(b0.w,b0.w),
                          pack2(b1.x,b1.x), pack2(b1.y,b1.y),
                          pack2(b1.z,b1.z), pack2(b1.w,b1.w) };
            #pragma unroll
            for (int i = 0; i < 4; i++)
                #pragma unroll
                for (int j = 0; j < 8; j++)
                    ffma2(acc[i][j], ap[i], bb[j]);
        }
        __syncthreads();
        if (t + 1 < ntiles) {
            As[aCol+0][aRow] = na.x; As[aCol+1][aRow] = na.y;
            As[aCol+2][aRow] = na.z; As[aCol+3][aRow] = na.w;
            *(float4*)&Bs[bRow][bCol] = nb;
        }
    }

    // epilogue: unpack row pairs and store
    #pragma unroll
    for (int p = 0; p < 4; p++) {
        int row = by*128 + ((p < 2) ? (ty*4 + 2*p) : (64 + ty*4 + 2*(p-2)));
        float lo[8], hi[8];
        #pragma unroll
        for (int j = 0; j < 8; j++) unpack2(acc[p][j], lo[j], hi[j]);
        float* Cp0 = C + (size_t)row * N + bx*128;
        *(float4*)(Cp0 + tx*4)      = make_float4(lo[0],lo[1],lo[2],lo[3]);
        *(float4*)(Cp0 + 64 + tx*4) = make_float4(lo[4],lo[5],lo[6],lo[7]);
        float* Cp1 = Cp0 + N;
        *(float4*)(Cp1 + tx*4)      = make_float4(hi[0],hi[1],hi[2],hi[3]);
        *(float4*)(Cp1 + 64 + tx*4) = make_float4(hi[4],hi[5],hi[6],hi[7]);
    }
}

// ---------------- hedgehog feature map --------------------------------------
__global__ __launch_bounds__(256)
void hedgehog_kernel(const float* __restrict__ proj, const float* __restrict__ w,
                     const float* __restrict__ bias, float* __restrict__ feat,
                     float scale)
{
    __shared__ float ws[64*65];
    __shared__ float xs[8][64];
    __shared__ float bs[64];
    const int tid = threadIdx.x;
    for (int i = tid; i < 4096; i += 256) { int e = i >> 6, d = i & 63; ws[e*65+d] = w[i]; }
    if (tid < 64) bs[tid] = bias[tid];
    const int warp = tid >> 5, lane = tid & 31;
    const int g = blockIdx.x*8 + warp;          // (b*H+h)*T + t
    const int b = g >> 15;
    const int h = (g >> 11) & 15;
    const int t = g & 2047;
    const float* xp = proj + ((size_t)(b*T_ + t))*D_ + h*HD_;
    xs[warp][lane]      = xp[lane];
    xs[warp][lane + 32] = xp[lane + 32];
    __syncthreads();

    float y0 = bs[lane], y1 = bs[lane+32];
    const float* w0 = &ws[lane*65];
    const float* w1 = &ws[(lane+32)*65];
    #pragma unroll
    for (int d = 0; d < 64; d++) {
        float xv = xs[warp][d];
        y0 = fmaf(w0[d], xv, y0);
        y1 = fmaf(w1[d], xv, y1);
    }
    float m = fmaxf(fabsf(y0), fabsf(y1));
    #pragma unroll
    for (int o = 16; o; o >>= 1) m = fmaxf(m, __shfl_xor_sync(0xffffffffu, m, o));
    float e0 = __expf(y0 - m), e1 = __expf(y1 - m);
    float e2 = __expf(-y0 - m), e3 = __expf(-y1 - m);
    float z = e0 + e1 + e2 + e3;
    #pragma unroll
    for (int o = 16; o; o >>= 1) z += __shfl_xor_sync(0xffffffffu, z, o);
    float inv = scale / z;
    float* fp = feat + (size_t)g * F_;
    fp[lane]      = e0 * inv;
    fp[lane + 32] = e1 * inv;
    fp[lane + 64] = e2 * inv;
    fp[lane + 96] = e3 * inv;
}

// ---------------- phase A: per-chunk kv[f,d] = sum_c k[c,f] v[c,d] ----------
__global__ __launch_bounds__(256)
void chunk_kv_kernel(const float* __restrict__ kfeat, const float* __restrict__ vproj,
                     float* __restrict__ kv)
{
    __shared__ float ks[64][128];
    __shared__ float vs[64][68];
    const int blk = blockIdx.x;          // bh*N + n
    const int n = blk & 31, bh = blk >> 5;
    const int b = bh >> 4, h = bh & 15;
    const int tid = threadIdx.x;
    const float* kp = kfeat + ((size_t)bh*T_ + n*C_)*F_;
    for (int i = tid; i < 64*128; i += 256) ks[i>>7][i&127] = kp[i];
    const float* vp = vproj + ((size_t)(b*T_ + n*C_))*D_ + h*HD_;
    for (int i = tid; i < 64*64; i += 256) vs[i>>6][i&63] = vp[(i>>6)*D_ + (i&63)];
    __syncthreads();
    const int tx = tid & 15, ty = tid >> 4;
    float acc[8][4] = {};
    for (int c = 0; c < 64; c++) {
        float kr[8], vr[4];
        #pragma unroll
        for (int i = 0; i < 8; i++) kr[i] = ks[c][ty*8+i];
        #pragma unroll
        for (int j = 0; j < 4; j++) vr[j] = vs[c][tx*4+j];
        #pragma unroll
        for (int i = 0; i < 8; i++)
            #pragma unroll
            for (int j = 0; j < 4; j++)
                acc[i][j] = fmaf(kr[i], vr[j], acc[i][j]);
    }
    float* out = kv + (size_t)blk * (F_*HD_);
    #pragma unroll
    for (int i = 0; i < 8; i++) {
        float4 v = make_float4(acc[i][0], acc[i][1], acc[i][2], acc[i][3]);
        *(float4*)&out[(ty*8+i)*64 + tx*4] = v;
    }
}

// ---------------- phase B: exclusive cumsum over chunks (in place) ----------
__global__ __launch_bounds__(1024)
void kv_scan_kernel(float* __restrict__ kv)
{
    const int blk = blockIdx.x;          // 512 blocks: bh = blk>>3, seg = blk&7
    const int bh = blk >> 3, seg = blk & 7;
    const int e = seg*1024 + threadIdx.x;
    size_t base = (size_t)bh * N_ * (F_*HD_) + e;
    float acc = 0.f;
    for (int n = 0; n < N_; n++) {
        size_t idx = base + (size_t)n * (F_*HD_);
        float t = kv[idx];
        kv[idx] = acc;
        acc += t;
    }
}

// ---------------- phase C: out = q@S_excl + tril(q@k^T)@v -------------------
__global__ __launch_bounds__(256)
void chunk_out_kernel(const float* __restrict__ qfeat, const float* __restrict__ kfeat,
                      const float* __restrict__ vproj, const float* __restrict__ kv,
                      float* __restrict__ o_flat)
{
    extern __shared__ float sm[];
    float* qs = sm;                 // [64][129] = 8256
    float* kS = qs + 64*129;        // union: kc [64][129] then S [128][65]; size 8320
    float* vs = kS + 8320;          // [64][65] = 4160
    float* sc = vs + 64*65;         // [64][65] = 4160
    const int blk = blockIdx.x;
    const int n = blk & 31, bh = blk >> 5;
    const int b = bh >> 4, h = bh & 15;
    const int tid = threadIdx.x;
    const float* qp = qfeat + ((size_t)bh*T_ + n*C_)*F_;
    const float* kp = kfeat + ((size_t)bh*T_ + n*C_)*F_;
    for (int i = tid; i < 8192; i += 256) {
        int c = i >> 7, f = i & 127;
        qs[c*129 + f] = qp[i];
        kS[c*129 + f] = kp[i];
    }
    const float* vp = vproj + ((size_t)(b*T_ + n*C_))*D_ + h*HD_;
    for (int i = tid; i < 4096; i += 256) { int c = i>>6, d = i&63; vs[c*65+d] = vp[c*D_+d]; }
    __syncthreads();

    const int tx = tid & 15, ty = tid >> 4;
    // scores s[c,m] = sum_f q[c,f] k[m,f], masked to m <= c
    float a1[4][4] = {};
    for (int f = 0; f < 128; f++) {
        float qr[4], kr[4];
        #pragma unroll
        for (int i = 0; i < 4; i++) qr[i] = qs[(ty*4+i)*129 + f];
        #pragma unroll
        for (int j = 0; j < 4; j++) kr[j] = kS[(tx*4+j)*129 + f];
        #pragma unroll
        for (int i = 0; i < 4; i++)
            #pragma unroll
            for (int j = 0; j < 4; j++)
                a1[i][j] = fmaf(qr[i], kr[j], a1[i][j]);
    }
    #pragma unroll
    for (int i = 0; i < 4; i++)
        #pragma unroll
        for (int j = 0; j < 4; j++) {
            int c = ty*4+i, m = tx*4+j;
            sc[c*65 + m] = (m <= c) ? a1[i][j] : 0.f;
        }
    __syncthreads();
    // overwrite kc region with S_excl [F,HD]
    const float* Sp = kv + (size_t)blk * (F_*HD_);
    for (int i = tid; i < 8192; i += 256) { int f = i>>6, d = i&63; kS[f*65+d] = Sp[i]; }
    __syncthreads();

    float acc[4][4] = {};
    for (int f = 0; f < 128; f++) {       // inter: q @ S_excl
        float qr[4], sr[4];
        #pragma unroll
        for (int i = 0; i < 4; i++) qr[i] = qs[(ty*4+i)*129 + f];
        #pragma unroll
        for (int j = 0; j < 4; j++) sr[j] = kS[f*65 + tx*4 + j];
        #pragma unroll
        for (int i = 0; i < 4; i++)
            #pragma unroll
            for (int j = 0; j < 4; j++)
                acc[i][j] = fmaf(qr[i], sr[j], acc[i][j]);
    }
    for (int m = 0; m < 64; m++) {        // intra: scores @ v
        float scr[4], vr[4];
        #pragma unroll
        for (int i = 0; i < 4; i++) scr[i] = sc[(ty*4+i)*65 + m];
        #pragma unroll
        for (int j = 0; j < 4; j++) vr[j] = vs[m*65 + tx*4 + j];
        #pragma unroll
        for (int i = 0; i < 4; i++)
            #pragma unroll
            for (int j = 0; j < 4; j++)
                acc[i][j] = fmaf(scr[i], vr[j], acc[i][j]);
    }
    // write directly in [B, T, H*HD] layout (folds the transpose)
    float* op = o_flat + ((size_t)(b*T_ + n*C_))*D_ + h*HD_;
    #pragma unroll
    for (int i = 0; i < 4; i++) {
        int c = ty*4 + i;
        float4 v = make_float4(acc[i][0], acc[i][1], acc[i][2], acc[i][3]);
        *(float4*)&op[(size_t)c*D_ + tx*4] = v;
    }
}

// ---------------- launcher ---------------------------------------------------
extern "C" void kernel_launch(void* const* d_in, const int* in_sizes, int n_in,
                              void* d_out, int out_size)
{
    const float* hs   = (const float*)d_in[0];
    const float* res  = (const float*)d_in[1];
    const float* nw   = (const float*)d_in[2];
    const float* w_q  = (const float*)d_in[3];
    const float* w_k  = (const float*)d_in[4];
    const float* w_v  = (const float*)d_in[5];
    const float* w_o  = (const float*)d_in[6];
    const float* hqw  = (const float*)d_in[7];
    const float* hqb  = (const float*)d_in[8];
    const float* hkw  = (const float*)d_in[9];
    const float* hkb  = (const float*)d_in[10];
    float* out = (float*)d_out;              // [o (BT*D), resid (BT*D)]

    float *px, *pq, *pk, *pv, *pqf, *pkf, *pkv, *po;
    cudaGetSymbolAddress((void**)&px,  g_x);
    cudaGetSymbolAddress((void**)&pq,  g_q);
    cudaGetSymbolAddress((void**)&pk,  g_k);
    cudaGetSymbolAddress((void**)&pv,  g_v);
    cudaGetSymbolAddress((void**)&pqf, g_qf);
    cudaGetSymbolAddress((void**)&pkf, g_kf);
    cudaGetSymbolAddress((void**)&pkv, g_kv);
    cudaGetSymbolAddress((void**)&po,  g_o);

    const int smem_c = (64*129 + 8320 + 64*65 + 64*65) * 4;   // 99584 bytes
    cudaFuncSetAttribute(chunk_out_kernel,
                         cudaFuncAttributeMaxDynamicSharedMemorySize, smem_c);

    // 1) fused add + RMSNorm; resid -> second half of d_out
    addnorm_kernel<<<BT_, 256>>>(hs, res, nw, out + (size_t)BT_*D_, px);

    // 2) QKV projections
    dim3 ggrid(D_/128, BT_/128);
    sgemm128<<<ggrid, 256>>>(px, w_q, pq, BT_, D_, D_);
    sgemm128<<<ggrid, 256>>>(px, w_k, pk, BT_, D_, D_);
    sgemm128<<<ggrid, 256>>>(px, w_v, pv, BT_, D_, D_);

    // 3) hedgehog features (q gets the F^-0.5 scale)
    hedgehog_kernel<<<BHT_/8, 256>>>(pq, hqw, hqb, pqf, 0.08838834764831845f);
    hedgehog_kernel<<<BHT_/8, 256>>>(pk, hkw, hkb, pkf, 1.0f);

    // 4) chunked linear attention
    chunk_kv_kernel<<<NCHUNK_, 256>>>(pkf, pv, pkv);
    kv_scan_kernel<<<512, 1024>>>(pkv);
    chunk_out_kernel<<<NCHUNK_, 256, smem_c>>>(pqf, pkf, pv, pkv, po);

    // 5) output projection -> first half of d_out
    sgemm128<<<ggrid, 256>>>(po, w_o, out, BT_, D_, D_);
}

// round 4
// speedup vs baseline: 1.6367x; 1.6367x over previous
#include <cuda_runtime.h>
#include <cuda_bf16.h>
#include <stdint.h>
#include <math.h>

// Problem constants
#define B_  4
#define T_  2048
#define D_  1024
#define H_  16
#define HD_ 64
#define F_  128
#define C_  64
#define N_  32
#define BT_ (B_*T_)        // 8192
#define BHT_ (B_*H_*T_)    // 131072
#define NCHUNK_ (B_*H_*N_) // 2048

// ---------------- scratch (device globals) ----------------------------------
__device__ float g_q [BT_*D_];
__device__ float g_k [BT_*D_];
__device__ float g_v [BT_*D_];
__device__ float g_qf[BHT_*F_];
__device__ float g_kf[BHT_*F_];
__device__ float g_kv[NCHUNK_*F_*HD_];
__device__ float g_o [BT_*D_];
__device__ __nv_bfloat16 g_xhi[BT_*D_];
__device__ __nv_bfloat16 g_xlo[BT_*D_];
__device__ __nv_bfloat16 g_ohi[BT_*D_];
__device__ __nv_bfloat16 g_olo[BT_*D_];
__device__ __nv_bfloat16 g_wqT[2*D_*D_];  // [hi | lo], transposed [N,K]
__device__ __nv_bfloat16 g_wkT[2*D_*D_];
__device__ __nv_bfloat16 g_wvT[2*D_*D_];
__device__ __nv_bfloat16 g_woT[2*D_*D_];

// ---------------- PTX helpers ------------------------------------------------
__device__ __forceinline__ uint32_t smem_u32(const void* p) {
    uint32_t a;
    asm("{ .reg .u64 t; cvta.to.shared.u64 t, %1; cvt.u32.u64 %0, t; }" : "=r"(a) : "l"(p));
    return a;
}
__device__ __forceinline__ void cp_async16(uint32_t saddr, const void* gaddr) {
    asm volatile("cp.async.cg.shared.global [%0], [%1], 16;" :: "r"(saddr), "l"(gaddr));
}
__device__ __forceinline__ void cp_commit() {
    asm volatile("cp.async.commit_group;" ::: "memory");
}
template <int NN>
__device__ __forceinline__ void cp_wait() {
    asm volatile("cp.async.wait_group %0;" :: "n"(NN) : "memory");
}
__device__ __forceinline__ void ldm_x4(uint32_t addr, uint32_t& r0, uint32_t& r1,
                                       uint32_t& r2, uint32_t& r3) {
    asm volatile("ldmatrix.sync.aligned.m8n8.x4.shared.b16 {%0,%1,%2,%3}, [%4];"
                 : "=r"(r0), "=r"(r1), "=r"(r2), "=r"(r3) : "r"(addr));
}
__device__ __forceinline__ void mma16816(float& d0, float& d1, float& d2, float& d3,
                                         uint32_t a0, uint32_t a1, uint32_t a2, uint32_t a3,
                                         uint32_t b0, uint32_t b1) {
    asm volatile("mma.sync.aligned.m16n8k16.row.col.f32.bf16.bf16.f32 "
                 "{%0,%1,%2,%3}, {%4,%5,%6,%7}, {%8,%9}, {%0,%1,%2,%3};"
                 : "+f"(d0), "+f"(d1), "+f"(d2), "+f"(d3)
                 : "r"(a0), "r"(a1), "r"(a2), "r"(a3), "r"(b0), "r"(b1));
}

// ---------------- fused add + RMSNorm -> resid + bf16 split x ---------------
__global__ __launch_bounds__(256)
void addnorm_kernel(const float* __restrict__ hs, const float* __restrict__ res,
                    const float* __restrict__ w, float* __restrict__ resid_out,
                    __nv_bfloat16* __restrict__ xhi, __nv_bfloat16* __restrict__ xlo)
{
    __shared__ float red[8];
    const int row = blockIdx.x;
    const int t = threadIdx.x;
    const float4* h4 = (const float4*)(hs  + (size_t)row*D_);
    const float4* r4 = (const float4*)(res + (size_t)row*D_);
    float4*      ro4 = (float4*)(resid_out + (size_t)row*D_);

    float4 h = h4[t], r = r4[t];
    float4 s = make_float4(h.x+r.x, h.y+r.y, h.z+r.z, h.w+r.w);
    ro4[t] = s;
    float ss = s.x*s.x + s.y*s.y + s.z*s.z + s.w*s.w;
    #pragma unroll
    for (int o = 16; o; o >>= 1) ss += __shfl_xor_sync(0xffffffffu, ss, o);
    if ((t & 31) == 0) red[t >> 5] = ss;
    __syncthreads();
    float tot = 0.f;
    #pragma unroll
    for (int i = 0; i < 8; i++) tot += red[i];
    float rstd = rsqrtf(tot * (1.0f/1024.0f) + 1e-5f);
    float4 wv = ((const float4*)w)[t];
    float v[4] = { s.x*rstd*wv.x, s.y*rstd*wv.y, s.z*rstd*wv.z, s.w*rstd*wv.w };
    __nv_bfloat16 hi[4], lo[4];
    #pragma unroll
    for (int i = 0; i < 4; i++) {
        hi[i] = __float2bfloat16_rn(v[i]);
        lo[i] = __float2bfloat16_rn(v[i] - __bfloat162float(hi[i]));
    }
    size_t idx = (size_t)row*D_ + t*4;
    *(__nv_bfloat162*)(xhi+idx)   = __nv_bfloat162(hi[0], hi[1]);
    *(__nv_bfloat162*)(xhi+idx+2) = __nv_bfloat162(hi[2], hi[3]);
    *(__nv_bfloat162*)(xlo+idx)   = __nv_bfloat162(lo[0], lo[1]);
    *(__nv_bfloat162*)(xlo+idx+2) = __nv_bfloat162(lo[2], lo[3]);
}

// ---------------- weight transpose + bf16 split ------------------------------
__global__ __launch_bounds__(256)
void wsplit_kernel(const float* __restrict__ W, __nv_bfloat16* __restrict__ wT)
{
    __shared__ float t[32][33];
    const int bx = blockIdx.x*32, by = blockIdx.y*32;
    const int tx = threadIdx.x & 31, ty = threadIdx.x >> 5;
    #pragma unroll
    for (int i = ty; i < 32; i += 8) t[i][tx] = W[(size_t)(by+i)*D_ + bx + tx];
    __syncthreads();
    #pragma unroll
    for (int i = ty; i < 32; i += 8) {
        float v = t[tx][i];               // = W[by+tx][bx+i]
        __nv_bfloat16 hi = __float2bfloat16_rn(v);
        __nv_bfloat16 lo = __float2bfloat16_rn(v - __bfloat162float(hi));
        size_t idx = (size_t)(bx+i)*D_ + by + tx;
        wT[idx] = hi;
        wT[idx + (size_t)D_*D_] = lo;
    }
}

// ---------------- o fp32 -> bf16 split ---------------------------------------
__global__ __launch_bounds__(256)
void osplit_kernel(const float* __restrict__ o, __nv_bfloat16* __restrict__ hi,
                   __nv_bfloat16* __restrict__ lo)
{
    size_t i = (size_t)blockIdx.x*1024 + threadIdx.x*4;
    float4 v = *(const float4*)(o + i);
    float a[4] = { v.x, v.y, v.z, v.w };
    __nv_bfloat16 h[4], l[4];
    #pragma unroll
    for (int j = 0; j < 4; j++) {
        h[j] = __float2bfloat16_rn(a[j]);
        l[j] = __float2bfloat16_rn(a[j] - __bfloat162float(h[j]));
    }
    *(__nv_bfloat162*)(hi+i)   = __nv_bfloat162(h[0], h[1]);
    *(__nv_bfloat162*)(hi+i+2) = __nv_bfloat162(h[2], h[3]);
    *(__nv_bfloat162*)(lo+i)   = __nv_bfloat162(l[0], l[1]);
    *(__nv_bfloat162*)(lo+i+2) = __nv_bfloat162(l[2], l[3]);
}

// ---------------- bf16x3 GEMM on mma.sync (HMMA) ------------------------------
// C[M,N] fp32 = (Ahi+Alo)[M,K] @ (Bhi+Blo)^T  with B stored [N,K] bf16.
// CTA 128x128, K-tile 32, 8 warps (2m x 4n), cp.async double buffer.
// smem pitch 40 bf16 (80B) -> conflict-free ldmatrix.
#define PITCH 40
#define MAT_BYTES (128*PITCH*2)          // 10240
#define STAGE_BYTES (4*MAT_BYTES)        // 40960
#define GSMEM (2*STAGE_BYTES)            // 81920

__global__ __launch_bounds__(256, 2)
void gemm_bf16x3(const __nv_bfloat16* __restrict__ Ahi, const __nv_bfloat16* __restrict__ Alo,
                 const __nv_bfloat16* __restrict__ BT, float* __restrict__ Cout)
{
    extern __shared__ __align__(16) char smem[];
    const uint32_t sbase = smem_u32(smem);
    const int tid = threadIdx.x, wid = tid >> 5, lane = tid & 31;
    const int bx = blockIdx.x, by = blockIdx.y;
    const int wm = wid & 1, wn = wid >> 1;          // 2 x 4 warp grid
    const __nv_bfloat16* Bhi = BT;
    const __nv_bfloat16* Blo = BT + (size_t)D_*D_;

    // loader mapping: thread t handles row t>>1, two 16B chunks c = (t&1)*2 + {0,1}
    const int lrow = tid >> 1;
    const int lc   = (tid & 1) * 2;
    const size_t gA = (size_t)(by*128 + lrow) * D_;   // + k0 + c*8
    const size_t gB = (size_t)(bx*128 + lrow) * D_;
    const uint32_t sRow = (uint32_t)lrow * 80;        // + c*16

    float acc[4][4][4];
    #pragma unroll
    for (int i = 0; i < 4; i++)
        #pragma unroll
        for (int j = 0; j < 4; j++)
            #pragma unroll
            for (int l = 0; l < 4; l++) acc[i][j][l] = 0.f;

    // prefetch helper (inlined twice below via lambda-style macro)
    #define PREFETCH(kt, buf) do {                                              \
        const int k0 = (kt) * 32;                                               \
        const uint32_t b0 = sbase + (uint32_t)(buf) * STAGE_BYTES;              \
        _Pragma("unroll")                                                       \
        for (int u = 0; u < 2; u++) {                                           \
            const int c = lc + u;                                               \
            const uint32_t so = sRow + (uint32_t)c * 16;                        \
            const size_t go = (size_t)k0 + c * 8;                               \
            cp_async16(b0 + 0*MAT_BYTES + so, Ahi + gA + go);                   \
            cp_async16(b0 + 1*MAT_BYTES + so, Alo + gA + go);                   \
            cp_async16(b0 + 2*MAT_BYTES + so, Bhi + gB + go);                   \
            cp_async16(b0 + 3*MAT_BYTES + so, Blo + gB + go);                   \
        }                                                                       \
        cp_commit();                                                            \
    } while (0)

    PREFETCH(0, 0);
    PREFETCH(1, 1);

    // ldmatrix lane addressing (constant per thread)
    const uint32_t aRow = (uint32_t)(wm*64 + (lane & 15)) * 80 + (uint32_t)(lane >> 4) * 16;
    const uint32_t bRow = (uint32_t)(wn*32 + ((lane >> 4) & 1)*8 + (lane & 7)) * 80
                        + (uint32_t)((lane >> 3) & 1) * 16;

    const int TILES = D_ / 32;   // 32
    #pragma unroll 1
    for (int kt = 0; kt < TILES; kt++) {
        const int cur = kt & 1;
        if (kt == TILES - 1) cp_wait<0>(); else cp_wait<1>();
        __syncthreads();
        const uint32_t sb = sbase + (uint32_t)cur * STAGE_BYTES;

        #pragma unroll
        for (int kk = 0; kk < 2; kk++) {
            const uint32_t koff = (uint32_t)kk * 32;
            // B fragments: 2 x ldmatrix.x4 per matrix, covering 32n x 16k
            uint32_t bh[2][4], bl[2][4];
            #pragma unroll
            for (int nt2 = 0; nt2 < 2; nt2++) {
                const uint32_t ba = bRow + (uint32_t)nt2 * 16 * 80 + koff;
                ldm_x4(sb + 2*MAT_BYTES + ba, bh[nt2][0], bh[nt2][1], bh[nt2][2], bh[nt2][3]);
                ldm_x4(sb + 3*MAT_BYTES + ba, bl[nt2][0], bl[nt2][1], bl[nt2][2], bl[nt2][3]);
            }
            #pragma unroll
            for (int mt = 0; mt < 4; mt++) {
                const uint32_t aa = aRow + (uint32_t)mt * 16 * 80 + koff;
                uint32_t ah[4], al[4];
                ldm_x4(sb + 0*MAT_BYTES + aa, ah[0], ah[1], ah[2], ah[3]);
                ldm_x4(sb + 1*MAT_BYTES + aa, al[0], al[1], al[2], al[3]);
                #pragma unroll
                for (int nt = 0; nt < 4; nt++) {
                    const uint32_t* bhp = &bh[nt >> 1][(nt & 1) * 2];
                    const uint32_t* blp = &bl[nt >> 1][(nt & 1) * 2];
                    float* d = acc[mt][nt];
                    mma16816(d[0], d[1], d[2], d[3], ah[0], ah[1], ah[2], ah[3], bhp[0], bhp[1]);
                    mma16816(d[0], d[1], d[2], d[3], ah[0], ah[1], ah[2], ah[3], blp[0], blp[1]);
                    mma16816(d[0], d[1], d[2], d[3], al[0], al[1], al[2], al[3], bhp[0], bhp[1]);
                }
            }
        }
        __syncthreads();
        if (kt + 2 < TILES) PREFETCH(kt + 2, cur);
    }
    #undef PREFETCH

    // epilogue
    const int g = lane >> 2, tq = lane & 3;
    #pragma unroll
    for (int mt = 0; mt < 4; mt++) {
        const int r0 = by*128 + wm*64 + mt*16 + g;
        #pragma unroll
        for (int nt = 0; nt < 4; nt++) {
            const int col = bx*128 + wn*32 + nt*8 + tq*2;
            float* d = acc[mt][nt];
            *(float2*)(Cout + (size_t)r0*D_ + col)     = make_float2(d[0], d[1]);
            *(float2*)(Cout + (size_t)(r0+8)*D_ + col) = make_float2(d[2], d[3]);
        }
    }
}

// ---------------- hedgehog feature map ---------------------------------------
__global__ __launch_bounds__(256)
void hedgehog_kernel(const float* __restrict__ proj, const float* __restrict__ w,
                     const float* __restrict__ bias, float* __restrict__ feat,
                     float scale)
{
    __shared__ float ws[64*65];
    __shared__ float xs[8][64];
    __shared__ float bs[64];
    const int tid = threadIdx.x;
    for (int i = tid; i < 4096; i += 256) { int e = i >> 6, d = i & 63; ws[e*65+d] = w[i]; }
    if (tid < 64) bs[tid] = bias[tid];
    const int warp = tid >> 5, lane = tid & 31;
    const int g = blockIdx.x*8 + warp;
    const int b = g >> 15;
    const int h = (g >> 11) & 15;
    const int t = g & 2047;
    const float* xp = proj + ((size_t)(b*T_ + t))*D_ + h*HD_;
    xs[warp][lane]      = xp[lane];
    xs[warp][lane + 32] = xp[lane + 32];
    __syncthreads();

    float y0 = bs[lane], y1 = bs[lane+32];
    const float* w0 = &ws[lane*65];
    const float* w1 = &ws[(lane+32)*65];
    #pragma unroll
    for (int d = 0; d < 64; d++) {
        float xv = xs[warp][d];
        y0 = fmaf(w0[d], xv, y0);
        y1 = fmaf(w1[d], xv, y1);
    }
    float m = fmaxf(fabsf(y0), fabsf(y1));
    #pragma unroll
    for (int o = 16; o; o >>= 1) m = fmaxf(m, __shfl_xor_sync(0xffffffffu, m, o));
    float e0 = __expf(y0 - m), e1 = __expf(y1 - m);
    float e2 = __expf(-y0 - m), e3 = __expf(-y1 - m);
    float z = e0 + e1 + e2 + e3;
    #pragma unroll
    for (int o = 16; o; o >>= 1) z += __shfl_xor_sync(0xffffffffu, z, o);
    float inv = scale / z;
    float* fp = feat + (size_t)g * F_;
    fp[lane]      = e0 * inv;
    fp[lane + 32] = e1 * inv;
    fp[lane + 64] = e2 * inv;
    fp[lane + 96] = e3 * inv;
}

// ---------------- phase A: per-chunk kv[f,d] = sum_c k[c,f] v[c,d] ----------
__global__ __launch_bounds__(256)
void chunk_kv_kernel(const float* __restrict__ kfeat, const float* __restrict__ vproj,
                     float* __restrict__ kv)
{
    __shared__ float ks[64][128];
    __shared__ float vs[64][68];
    const int blk = blockIdx.x;
    const int n = blk & 31, bh = blk >> 5;
    const int b = bh >> 4, h = bh & 15;
    const int tid = threadIdx.x;
    const float* kp = kfeat + ((size_t)bh*T_ + n*C_)*F_;
    for (int i = tid; i < 64*128; i += 256) ks[i>>7][i&127] = kp[i];
    const float* vp = vproj + ((size_t)(b*T_ + n*C_))*D_ + h*HD_;
    for (int i = tid; i < 64*64; i += 256) vs[i>>6][i&63] = vp[(i>>6)*D_ + (i&63)];
    __syncthreads();
    const int tx = tid & 15, ty = tid >> 4;
    float acc[8][4] = {};
    for (int c = 0; c < 64; c++) {
        float kr[8], vr[4];
        #pragma unroll
        for (int i = 0; i < 8; i++) kr[i] = ks[c][ty*8+i];
        #pragma unroll
        for (int j = 0; j < 4; j++) vr[j] = vs[c][tx*4+j];
        #pragma unroll
        for (int i = 0; i < 8; i++)
            #pragma unroll
            for (int j = 0; j < 4; j++)
                acc[i][j] = fmaf(kr[i], vr[j], acc[i][j]);
    }
    float* out = kv + (size_t)blk * (F_*HD_);
    #pragma unroll
    for (int i = 0; i < 8; i++) {
        float4 v = make_float4(acc[i][0], acc[i][1], acc[i][2], acc[i][3]);
        *(float4*)&out[(ty*8+i)*64 + tx*4] = v;
    }
}

// ---------------- phase B: exclusive cumsum over chunks ---------------------
__global__ __launch_bounds__(1024)
void kv_scan_kernel(float* __restrict__ kv)
{
    const int blk = blockIdx.x;
    const int bh = blk >> 3, seg = blk & 7;
    const int e = seg*1024 + threadIdx.x;
    size_t base = (size_t)bh * N_ * (F_*HD_) + e;
    float acc = 0.f;
    for (int n = 0; n < N_; n++) {
        size_t idx = base + (size_t)n * (F_*HD_);
        float t = kv[idx];
        kv[idx] = acc;
        acc += t;
    }
}

// ---------------- phase C: out = q@S_excl + tril(q@k^T)@v -------------------
__global__ __launch_bounds__(256)
void chunk_out_kernel(const float* __restrict__ qfeat, const float* __restrict__ kfeat,
                      const float* __restrict__ vproj, const float* __restrict__ kv,
                      float* __restrict__ o_flat)
{
    extern __shared__ float sm[];
    float* qs = sm;
    float* kS = qs + 64*129;
    float* vs = kS + 8320;
    float* sc = vs + 64*65;
    const int blk = blockIdx.x;
    const int n = blk & 31, bh = blk >> 5;
    const int b = bh >> 4, h = bh & 15;
    const int tid = threadIdx.x;
    const float* qp = qfeat + ((size_t)bh*T_ + n*C_)*F_;
    const float* kp = kfeat + ((size_t)bh*T_ + n*C_)*F_;
    for (int i = tid; i < 8192; i += 256) {
        int c = i >> 7, f = i & 127;
        qs[c*129 + f] = qp[i];
        kS[c*129 + f] = kp[i];
    }
    const float* vp = vproj + ((size_t)(b*T_ + n*C_))*D_ + h*HD_;
    for (int i = tid; i < 4096; i += 256) { int c = i>>6, d = i&63; vs[c*65+d] = vp[c*D_+d]; }
    __syncthreads();

    const int tx = tid & 15, ty = tid >> 4;
    float a1[4][4] = {};
    for (int f = 0; f < 128; f++) {
        float qr[4], kr[4];
        #pragma unroll
        for (int i = 0; i < 4; i++) qr[i] = qs[(ty*4+i)*129 + f];
        #pragma unroll
        for (int j = 0; j < 4; j++) kr[j] = kS[(tx*4+j)*129 + f];
        #pragma unroll
        for (int i = 0; i < 4; i++)
            #pragma unroll
            for (int j = 0; j < 4; j++)
                a1[i][j] = fmaf(qr[i], kr[j], a1[i][j]);
    }
    #pragma unroll
    for (int i = 0; i < 4; i++)
        #pragma unroll
        for (int j = 0; j < 4; j++) {
            int c = ty*4+i, m = tx*4+j;
            sc[c*65 + m] = (m <= c) ? a1[i][j] : 0.f;
        }
    __syncthreads();
    const float* Sp = kv + (size_t)blk * (F_*HD_);
    for (int i = tid; i < 8192; i += 256) { int f = i>>6, d = i&63; kS[f*65+d] = Sp[i]; }
    __syncthreads();

    float acc[4][4] = {};
    for (int f = 0; f < 128; f++) {
        float qr[4], sr[4];
        #pragma unroll
        for (int i = 0; i < 4; i++) qr[i] = qs[(ty*4+i)*129 + f];
        #pragma unroll
        for (int j = 0; j < 4; j++) sr[j] = kS[f*65 + tx*4 + j];
        #pragma unroll
        for (int i = 0; i < 4; i++)
            #pragma unroll
            for (int j = 0; j < 4; j++)
                acc[i][j] = fmaf(qr[i], sr[j], acc[i][j]);
    }
    for (int m = 0; m < 64; m++) {
        float scr[4], vr[4];
        #pragma unroll
        for (int i = 0; i < 4; i++) scr[i] = sc[(ty*4+i)*65 + m];
        #pragma unroll
        for (int j = 0; j < 4; j++) vr[j] = vs[m*65 + tx*4 + j];
        #pragma unroll
        for (int i = 0; i < 4; i++)
            #pragma unroll
            for (int j = 0; j < 4; j++)
                acc[i][j] = fmaf(scr[i], vr[j], acc[i][j]);
    }
    float* op = o_flat + ((size_t)(b*T_ + n*C_))*D_ + h*HD_;
    #pragma unroll
    for (int i = 0; i < 4; i++) {
        int c = ty*4 + i;
        float4 v = make_float4(acc[i][0], acc[i][1], acc[i][2], acc[i][3]);
        *(float4*)&op[(size_t)c*D_ + tx*4] = v;
    }
}

// ---------------- launcher ----------------------------------------------------
extern "C" void kernel_launch(void* const* d_in, const int* in_sizes, int n_in,
                              void* d_out, int out_size)
{
    const float* hs   = (const float*)d_in[0];
    const float* res  = (const float*)d_in[1];
    const float* nw   = (const float*)d_in[2];
    const float* w_q  = (const float*)d_in[3];
    const float* w_k  = (const float*)d_in[4];
    const float* w_v  = (const float*)d_in[5];
    const float* w_o  = (const float*)d_in[6];
    const float* hqw  = (const float*)d_in[7];
    const float* hqb  = (const float*)d_in[8];
    const float* hkw  = (const float*)d_in[9];
    const float* hkb  = (const float*)d_in[10];
    float* out = (float*)d_out;

    float *pq, *pk, *pv, *pqf, *pkf, *pkv, *po;
    __nv_bfloat16 *pxhi, *pxlo, *pohi, *polo, *pwq, *pwk, *pwv, *pwo;
    cudaGetSymbolAddress((void**)&pq,   g_q);
    cudaGetSymbolAddress((void**)&pk,   g_k);
    cudaGetSymbolAddress((void**)&pv,   g_v);
    cudaGetSymbolAddress((void**)&pqf,  g_qf);
    cudaGetSymbolAddress((void**)&pkf,  g_kf);
    cudaGetSymbolAddress((void**)&pkv,  g_kv);
    cudaGetSymbolAddress((void**)&po,   g_o);
    cudaGetSymbolAddress((void**)&pxhi, g_xhi);
    cudaGetSymbolAddress((void**)&pxlo, g_xlo);
    cudaGetSymbolAddress((void**)&pohi, g_ohi);
    cudaGetSymbolAddress((void**)&polo, g_olo);
    cudaGetSymbolAddress((void**)&pwq,  g_wqT);
    cudaGetSymbolAddress((void**)&pwk,  g_wkT);
    cudaGetSymbolAddress((void**)&pwv,  g_wvT);
    cudaGetSymbolAddress((void**)&pwo,  g_woT);

    const int smem_c = (64*129 + 8320 + 64*65 + 64*65) * 4;
    cudaFuncSetAttribute(chunk_out_kernel,
                         cudaFuncAttributeMaxDynamicSharedMemorySize, smem_c);
    cudaFuncSetAttribute(gemm_bf16x3,
                         cudaFuncAttributeMaxDynamicSharedMemorySize, GSMEM);

    // 1) fused add + RMSNorm -> resid (2nd half of out) + split x
    addnorm_kernel<<<BT_, 256>>>(hs, res, nw, out + (size_t)BT_*D_, pxhi, pxlo);

    // 2) weight transpose+split
    dim3 wgrid(32, 32);
    wsplit_kernel<<<wgrid, 256>>>(w_q, pwq);
    wsplit_kernel<<<wgrid, 256>>>(w_k, pwk);
    wsplit_kernel<<<wgrid, 256>>>(w_v, pwv);
    wsplit_kernel<<<wgrid, 256>>>(w_o, pwo);

    // 3) QKV projections on tensor cores (legacy HMMA path)
    dim3 ggrid(D_/128, BT_/128);
    gemm_bf16x3<<<ggrid, 256, GSMEM>>>(pxhi, pxlo, pwq, pq);
    gemm_bf16x3<<<ggrid, 256, GSMEM>>>(pxhi, pxlo, pwk, pk);
    gemm_bf16x3<<<ggrid, 256, GSMEM>>>(pxhi, pxlo, pwv, pv);

    // 4) hedgehog features
    hedgehog_kernel<<<BHT_/8, 256>>>(pq, hqw, hqb, pqf, 0.08838834764831845f);
    hedgehog_kernel<<<BHT_/8, 256>>>(pk, hkw, hkb, pkf, 1.0f);

    // 5) chunked linear attention
    chunk_kv_kernel<<<NCHUNK_, 256>>>(pkf, pv, pkv);
    kv_scan_kernel<<<512, 1024>>>(pkv);
    chunk_out_kernel<<<NCHUNK_, 256, smem_c>>>(pqf, pkf, pv, pkv, po);

    // 6) output projection
    osplit_kernel<<<BT_, 256>>>(po, pohi, polo);
    gemm_bf16x3<<<ggrid, 256, GSMEM>>>(pohi, polo, pwo, out);
}

// round 5
// speedup vs baseline: 1.8910x; 1.1554x over previous
#include <cuda_runtime.h>
#include <cuda_bf16.h>
#include <stdint.h>
#include <math.h>

// Problem constants
#define B_  4
#define T_  2048
#define D_  1024
#define H_  16
#define HD_ 64
#define F_  128
#define C_  64
#define N_  32
#define BT_ (B_*T_)        // 8192
#define BHT_ (B_*H_*T_)    // 131072
#define NCHUNK_ (B_*H_*N_) // 2048

// ---------------- scratch (device globals) ----------------------------------
__device__ float g_q [BT_*D_];
__device__ float g_k [BT_*D_];
__device__ float g_v [BT_*D_];
__device__ float g_kv[NCHUNK_*F_*HD_];          // kv^T per chunk: [d][f]
__device__ __nv_bfloat16 g_STh[NCHUNK_*F_*HD_]; // S_excl^T hi [d][f]
__device__ __nv_bfloat16 g_STl[NCHUNK_*F_*HD_];
__device__ __nv_bfloat16 g_qfh[BHT_*F_];
__device__ __nv_bfloat16 g_qfl[BHT_*F_];
__device__ __nv_bfloat16 g_kfh[BHT_*F_];
__device__ __nv_bfloat16 g_kfl[BHT_*F_];
__device__ __nv_bfloat16 g_vh [BT_*D_];
__device__ __nv_bfloat16 g_vl [BT_*D_];
__device__ __nv_bfloat16 g_xhi[BT_*D_];
__device__ __nv_bfloat16 g_xlo[BT_*D_];
__device__ __nv_bfloat16 g_ohi[BT_*D_];
__device__ __nv_bfloat16 g_olo[BT_*D_];
__device__ __nv_bfloat16 g_wqT[2*D_*D_];
__device__ __nv_bfloat16 g_wkT[2*D_*D_];
__device__ __nv_bfloat16 g_wvT[2*D_*D_];
__device__ __nv_bfloat16 g_woT[2*D_*D_];

// ---------------- PTX helpers ------------------------------------------------
__device__ __forceinline__ uint32_t smem_u32(const void* p) {
    uint32_t a;
    asm("{ .reg .u64 t; cvta.to.shared.u64 t, %1; cvt.u32.u64 %0, t; }" : "=r"(a) : "l"(p));
    return a;
}
__device__ __forceinline__ void cp_async16(uint32_t saddr, const void* gaddr) {
    asm volatile("cp.async.cg.shared.global [%0], [%1], 16;" :: "r"(saddr), "l"(gaddr));
}
__device__ __forceinline__ void cp_commit() {
    asm volatile("cp.async.commit_group;" ::: "memory");
}
template <int NN>
__device__ __forceinline__ void cp_wait() {
    asm volatile("cp.async.wait_group %0;" :: "n"(NN) : "memory");
}
__device__ __forceinline__ void ldm_x4(uint32_t addr, uint32_t& r0, uint32_t& r1,
                                       uint32_t& r2, uint32_t& r3) {
    asm volatile("ldmatrix.sync.aligned.m8n8.x4.shared.b16 {%0,%1,%2,%3}, [%4];"
                 : "=r"(r0), "=r"(r1), "=r"(r2), "=r"(r3) : "r"(addr));
}
__device__ __forceinline__ void mma16816(float& d0, float& d1, float& d2, float& d3,
                                         uint32_t a0, uint32_t a1, uint32_t a2, uint32_t a3,
                                         uint32_t b0, uint32_t b1) {
    asm volatile("mma.sync.aligned.m16n8k16.row.col.f32.bf16.bf16.f32 "
                 "{%0,%1,%2,%3}, {%4,%5,%6,%7}, {%8,%9}, {%0,%1,%2,%3};"
                 : "+f"(d0), "+f"(d1), "+f"(d2), "+f"(d3)
                 : "r"(a0), "r"(a1), "r"(a2), "r"(a3), "r"(b0), "r"(b1));
}
__device__ __forceinline__ void bsplit(float v, __nv_bfloat16& h, __nv_bfloat16& l) {
    h = __float2bfloat16_rn(v);
    l = __float2bfloat16_rn(v - __bfloat162float(h));
}

// ---------------- fused add + RMSNorm -> resid + bf16 split x ---------------
__global__ __launch_bounds__(256)
void addnorm_kernel(const float* __restrict__ hs, const float* __restrict__ res,
                    const float* __restrict__ w, float* __restrict__ resid_out,
                    __nv_bfloat16* __restrict__ xhi, __nv_bfloat16* __restrict__ xlo)
{
    __shared__ float red[8];
    const int row = blockIdx.x;
    const int t = threadIdx.x;
    const float4* h4 = (const float4*)(hs  + (size_t)row*D_);
    const float4* r4 = (const float4*)(res + (size_t)row*D_);
    float4*      ro4 = (float4*)(resid_out + (size_t)row*D_);

    float4 h = h4[t], r = r4[t];
    float4 s = make_float4(h.x+r.x, h.y+r.y, h.z+r.z, h.w+r.w);
    ro4[t] = s;
    float ss = s.x*s.x + s.y*s.y + s.z*s.z + s.w*s.w;
    #pragma unroll
    for (int o = 16; o; o >>= 1) ss += __shfl_xor_sync(0xffffffffu, ss, o);
    if ((t & 31) == 0) red[t >> 5] = ss;
    __syncthreads();
    float tot = 0.f;
    #pragma unroll
    for (int i = 0; i < 8; i++) tot += red[i];
    float rstd = rsqrtf(tot * (1.0f/1024.0f) + 1e-5f);
    float4 wv = ((const float4*)w)[t];
    float v[4] = { s.x*rstd*wv.x, s.y*rstd*wv.y, s.z*rstd*wv.z, s.w*rstd*wv.w };
    __nv_bfloat16 hi[4], lo[4];
    #pragma unroll
    for (int i = 0; i < 4; i++) bsplit(v[i], hi[i], lo[i]);
    size_t idx = (size_t)row*D_ + t*4;
    *(__nv_bfloat162*)(xhi+idx)   = __nv_bfloat162(hi[0], hi[1]);
    *(__nv_bfloat162*)(xhi+idx+2) = __nv_bfloat162(hi[2], hi[3]);
    *(__nv_bfloat162*)(xlo+idx)   = __nv_bfloat162(lo[0], lo[1]);
    *(__nv_bfloat162*)(xlo+idx+2) = __nv_bfloat162(lo[2], lo[3]);
}

// ---------------- weight transpose + bf16 split ------------------------------
__global__ __launch_bounds__(256)
void wsplit_kernel(const float* __restrict__ W, __nv_bfloat16* __restrict__ wT)
{
    __shared__ float t[32][33];
    const int bx = blockIdx.x*32, by = blockIdx.y*32;
    const int tx = threadIdx.x & 31, ty = threadIdx.x >> 5;
    #pragma unroll
    for (int i = ty; i < 32; i += 8) t[i][tx] = W[(size_t)(by+i)*D_ + bx + tx];
    __syncthreads();
    #pragma unroll
    for (int i = ty; i < 32; i += 8) {
        float v = t[tx][i];
        __nv_bfloat16 hi, lo;
        bsplit(v, hi, lo);
        size_t idx = (size_t)(bx+i)*D_ + by + tx;
        wT[idx] = hi;
        wT[idx + (size_t)D_*D_] = lo;
    }
}

// ---------------- generic fp32 -> bf16 split ---------------------------------
__global__ __launch_bounds__(256)
void fsplit_kernel(const float* __restrict__ o, __nv_bfloat16* __restrict__ hi,
                   __nv_bfloat16* __restrict__ lo)
{
    size_t i = (size_t)blockIdx.x*1024 + threadIdx.x*4;
    float4 v = *(const float4*)(o + i);
    float a[4] = { v.x, v.y, v.z, v.w };
    __nv_bfloat16 h[4], l[4];
    #pragma unroll
    for (int j = 0; j < 4; j++) bsplit(a[j], h[j], l[j]);
    *(__nv_bfloat162*)(hi+i)   = __nv_bfloat162(h[0], h[1]);
    *(__nv_bfloat162*)(hi+i+2) = __nv_bfloat162(h[2], h[3]);
    *(__nv_bfloat162*)(lo+i)   = __nv_bfloat162(l[0], l[1]);
    *(__nv_bfloat162*)(lo+i+2) = __nv_bfloat162(l[2], l[3]);
}

// ---------------- bf16x3 GEMM on mma.sync (HMMA) ------------------------------
#define PITCH 40
#define MAT_BYTES (128*PITCH*2)
#define STAGE_BYTES (4*MAT_BYTES)
#define GSMEM (2*STAGE_BYTES)

__global__ __launch_bounds__(256, 2)
void gemm_bf16x3(const __nv_bfloat16* __restrict__ Ahi, const __nv_bfloat16* __restrict__ Alo,
                 const __nv_bfloat16* __restrict__ BT, float* __restrict__ Cout)
{
    extern __shared__ __align__(16) char smem[];
    const uint32_t sbase = smem_u32(smem);
    const int tid = threadIdx.x, wid = tid >> 5, lane = tid & 31;
    const int bx = blockIdx.x, by = blockIdx.y;
    const int wm = wid & 1, wn = wid >> 1;
    const __nv_bfloat16* Bhi = BT;
    const __nv_bfloat16* Blo = BT + (size_t)D_*D_;

    const int lrow = tid >> 1;
    const int lc   = (tid & 1) * 2;
    const size_t gA = (size_t)(by*128 + lrow) * D_;
    const size_t gB = (size_t)(bx*128 + lrow) * D_;
    const uint32_t sRow = (uint32_t)lrow * 80;

    float acc[4][4][4];
    #pragma unroll
    for (int i = 0; i < 4; i++)
        #pragma unroll
        for (int j = 0; j < 4; j++)
            #pragma unroll
            for (int l = 0; l < 4; l++) acc[i][j][l] = 0.f;

    #define PREFETCH(kt, buf) do {                                              \
        const int k0 = (kt) * 32;                                               \
        const uint32_t b0 = sbase + (uint32_t)(buf) * STAGE_BYTES;              \
        _Pragma("unroll")                                                       \
        for (int u = 0; u < 2; u++) {                                           \
            const int c = lc + u;                                               \
            const uint32_t so = sRow + (uint32_t)c * 16;                        \
            const size_t go = (size_t)k0 + c * 8;                               \
            cp_async16(b0 + 0*MAT_BYTES + so, Ahi + gA + go);                   \
            cp_async16(b0 + 1*MAT_BYTES + so, Alo + gA + go);                   \
            cp_async16(b0 + 2*MAT_BYTES + so, Bhi + gB + go);                   \
            cp_async16(b0 + 3*MAT_BYTES + so, Blo + gB + go);                   \
        }                                                                       \
        cp_commit();                                                            \
    } while (0)

    PREFETCH(0, 0);
    PREFETCH(1, 1);

    const uint32_t aRow = (uint32_t)(wm*64 + (lane & 15)) * 80 + (uint32_t)(lane >> 4) * 16;
    const uint32_t bRow = (uint32_t)(wn*32 + ((lane >> 4) & 1)*8 + (lane & 7)) * 80
                        + (uint32_t)((lane >> 3) & 1) * 16;

    const int TILES = D_ / 32;
    #pragma unroll 1
    for (int kt = 0; kt < TILES; kt++) {
        const int cur = kt & 1;
        if (kt == TILES - 1) cp_wait<0>(); else cp_wait<1>();
        __syncthreads();
        const uint32_t sb = sbase + (uint32_t)cur * STAGE_BYTES;

        #pragma unroll
        for (int kk = 0; kk < 2; kk++) {
            const uint32_t koff = (uint32_t)kk * 32;
            uint32_t bh[2][4], bl[2][4];
            #pragma unroll
            for (int nt2 = 0; nt2 < 2; nt2++) {
                const uint32_t ba = bRow + (uint32_t)nt2 * 16 * 80 + koff;
                ldm_x4(sb + 2*MAT_BYTES + ba, bh[nt2][0], bh[nt2][1], bh[nt2][2], bh[nt2][3]);
                ldm_x4(sb + 3*MAT_BYTES + ba, bl[nt2][0], bl[nt2][1], bl[nt2][2], bl[nt2][3]);
            }
            #pragma unroll
            for (int mt = 0; mt < 4; mt++) {
                const uint32_t aa = aRow + (uint32_t)mt * 16 * 80 + koff;
                uint32_t ah[4], al[4];
                ldm_x4(sb + 0*MAT_BYTES + aa, ah[0], ah[1], ah[2], ah[3]);
                ldm_x4(sb + 1*MAT_BYTES + aa, al[0], al[1], al[2], al[3]);
                #pragma unroll
                for (int nt = 0; nt < 4; nt++) {
                    const uint32_t* bhp = &bh[nt >> 1][(nt & 1) * 2];
                    const uint32_t* blp = &bl[nt >> 1][(nt & 1) * 2];
                    float* d = acc[mt][nt];
                    mma16816(d[0], d[1], d[2], d[3], ah[0], ah[1], ah[2], ah[3], bhp[0], bhp[1]);
                    mma16816(d[0], d[1], d[2], d[3], ah[0], ah[1], ah[2], ah[3], blp[0], blp[1]);
                    mma16816(d[0], d[1], d[2], d[3], al[0], al[1], al[2], al[3], bhp[0], bhp[1]);
                }
            }
        }
        __syncthreads();
        if (kt + 2 < TILES) PREFETCH(kt + 2, cur);
    }
    #undef PREFETCH

    const int g = lane >> 2, tq = lane & 3;
    #pragma unroll
    for (int mt = 0; mt < 4; mt++) {
        const int r0 = by*128 + wm*64 + mt*16 + g;
        #pragma unroll
        for (int nt = 0; nt < 4; nt++) {
            const int col = bx*128 + wn*32 + nt*8 + tq*2;
            float* d = acc[mt][nt];
            *(float2*)(Cout + (size_t)r0*D_ + col)     = make_float2(d[0], d[1]);
            *(float2*)(Cout + (size_t)(r0+8)*D_ + col) = make_float2(d[2], d[3]);
        }
    }
}

// ---------------- hedgehog feature map (emits bf16 hi/lo) --------------------
__global__ __launch_bounds__(256)
void hedgehog_kernel(const float* __restrict__ proj, const float* __restrict__ w,
                     const float* __restrict__ bias,
                     __nv_bfloat16* __restrict__ fh, __nv_bfloat16* __restrict__ fl,
                     float scale)
{
    __shared__ float ws[64*65];
    __shared__ float xs[8][64];
    __shared__ float bs[64];
    const int tid = threadIdx.x;
    for (int i = tid; i < 4096; i += 256) { int e = i >> 6, d = i & 63; ws[e*65+d] = w[i]; }
    if (tid < 64) bs[tid] = bias[tid];
    const int warp = tid >> 5, lane = tid & 31;
    const int g = blockIdx.x*8 + warp;
    const int b = g >> 15;
    const int h = (g >> 11) & 15;
    const int t = g & 2047;
    const float* xp = proj + ((size_t)(b*T_ + t))*D_ + h*HD_;
    xs[warp][lane]      = xp[lane];
    xs[warp][lane + 32] = xp[lane + 32];
    __syncthreads();

    float y0 = bs[lane], y1 = bs[lane+32];
    const float* w0 = &ws[lane*65];
    const float* w1 = &ws[(lane+32)*65];
    #pragma unroll
    for (int d = 0; d < 64; d++) {
        float xv = xs[warp][d];
        y0 = fmaf(w0[d], xv, y0);
        y1 = fmaf(w1[d], xv, y1);
    }
    float m = fmaxf(fabsf(y0), fabsf(y1));
    #pragma unroll
    for (int o = 16; o; o >>= 1) m = fmaxf(m, __shfl_xor_sync(0xffffffffu, m, o));
    float e0 = __expf(y0 - m), e1 = __expf(y1 - m);
    float e2 = __expf(-y0 - m), e3 = __expf(-y1 - m);
    float z = e0 + e1 + e2 + e3;
    #pragma unroll
    for (int o = 16; o; o >>= 1) z += __shfl_xor_sync(0xffffffffu, z, o);
    float inv = scale / z;
    float vals[4] = { e0*inv, e1*inv, e2*inv, e3*inv };
    __nv_bfloat16* fph = fh + (size_t)g * F_;
    __nv_bfloat16* fpl = fl + (size_t)g * F_;
    #pragma unroll
    for (int i = 0; i < 4; i++) {
        __nv_bfloat16 hv, lv;
        bsplit(vals[i], hv, lv);
        fph[lane + i*32] = hv;
        fpl[lane + i*32] = lv;
    }
}

// ---------------- phase A: kv^T[d][f] = sum_c v[c,d] k[c,f]  (tensor core) ---
// smem: kT hi/lo [128 f][64 c] pitch 144B; vT hi/lo [64 d][64 c] pitch 144B
#define CKV_KTH 0u
#define CKV_KTL 18432u
#define CKV_VTH 36864u
#define CKV_VTL 46080u
#define CKV_SMEM 55296u

__global__ __launch_bounds__(256, 2)
void chunk_kv_kernel(const __nv_bfloat16* __restrict__ kfh, const __nv_bfloat16* __restrict__ kfl,
                     const __nv_bfloat16* __restrict__ vh, const __nv_bfloat16* __restrict__ vl,
                     float* __restrict__ kvT)
{
    extern __shared__ __align__(16) char smem[];
    const uint32_t sb = smem_u32(smem);
    const int blk = blockIdx.x;
    const int n = blk & 31, bh = blk >> 5;
    const int b = bh >> 4, h = bh & 15;
    const int tid = threadIdx.x, wid = tid >> 5, lane = tid & 31;

    // transposed staging: k features [c][f] -> kT[f][c]
    {
        const int c = tid >> 2, fg = (tid & 3) * 32;
        const size_t src = ((size_t)bh*T_ + n*C_ + c)*F_ + fg;
        union { uint4 u; __nv_bfloat16 b[8]; } r;
        #pragma unroll
        for (int q = 0; q < 4; q++) {
            r.u = *(const uint4*)(kfh + src + q*8);
            #pragma unroll
            for (int i = 0; i < 8; i++)
                *(__nv_bfloat16*)(smem + CKV_KTH + (fg+q*8+i)*144 + c*2) = r.b[i];
            r.u = *(const uint4*)(kfl + src + q*8);
            #pragma unroll
            for (int i = 0; i < 8; i++)
                *(__nv_bfloat16*)(smem + CKV_KTL + (fg+q*8+i)*144 + c*2) = r.b[i];
        }
    }
    // v [c][d] -> vT[d][c]
    {
        const int c = tid >> 2, dg = (tid & 3) * 16;
        const size_t src = ((size_t)(b*T_) + n*C_ + c)*D_ + h*HD_ + dg;
        union { uint4 u; __nv_bfloat16 b[8]; } r;
        #pragma unroll
        for (int q = 0; q < 2; q++) {
            r.u = *(const uint4*)(vh + src + q*8);
            #pragma unroll
            for (int i = 0; i < 8; i++)
                *(__nv_bfloat16*)(smem + CKV_VTH + (dg+q*8+i)*144 + c*2) = r.b[i];
            r.u = *(const uint4*)(vl + src + q*8);
            #pragma unroll
            for (int i = 0; i < 8; i++)
                *(__nv_bfloat16*)(smem + CKV_VTL + (dg+q*8+i)*144 + c*2) = r.b[i];
        }
    }
    __syncthreads();

    // warps: 4 m-tiles (d, 16 each) x 2 n-halves (f, 64 each)
    const int wm = wid & 3, wn = wid >> 2;
    float acc[8][4];
    #pragma unroll
    for (int i = 0; i < 8; i++)
        #pragma unroll
        for (int j = 0; j < 4; j++) acc[i][j] = 0.f;

    const uint32_t aBase = sb + CKV_VTH + (uint32_t)(wm*16 + (lane & 15))*144
                         + (uint32_t)(lane >> 4)*16;
    const uint32_t bBase = sb + CKV_KTH + (uint32_t)(wn*64 + ((lane >> 4) & 1)*8 + (lane & 7))*144
                         + (uint32_t)((lane >> 3) & 1)*16;

    #pragma unroll
    for (int ks = 0; ks < 4; ks++) {
        const uint32_t koff = (uint32_t)ks*32;
        uint32_t ah[4], al[4];
        ldm_x4(aBase + koff, ah[0], ah[1], ah[2], ah[3]);
        ldm_x4(aBase + (CKV_VTL - CKV_VTH) + koff, al[0], al[1], al[2], al[3]);
        uint32_t bhf[4][4], blf[4][4];
        #pragma unroll
        for (int p = 0; p < 4; p++) {
            const uint32_t ba = bBase + (uint32_t)p*16*144 + koff;
            ldm_x4(ba, bhf[p][0], bhf[p][1], bhf[p][2], bhf[p][3]);
            ldm_x4(ba + (CKV_KTL - CKV_KTH), blf[p][0], blf[p][1], blf[p][2], blf[p][3]);
        }
        #pragma unroll
        for (int nt = 0; nt < 8; nt++) {
            const uint32_t* bhp = &bhf[nt >> 1][(nt & 1)*2];
            const uint32_t* blp = &blf[nt >> 1][(nt & 1)*2];
            float* d = acc[nt];
            mma16816(d[0], d[1], d[2], d[3], ah[0], ah[1], ah[2], ah[3], bhp[0], bhp[1]);
            mma16816(d[0], d[1], d[2], d[3], ah[0], ah[1], ah[2], ah[3], blp[0], blp[1]);
            mma16816(d[0], d[1], d[2], d[3], al[0], al[1], al[2], al[3], bhp[0], bhp[1]);
        }
    }
    const int g = lane >> 2, tq = lane & 3;
    float* out = kvT + (size_t)blk * (F_*HD_);
    #pragma unroll
    for (int nt = 0; nt < 8; nt++) {
        const int f = wn*64 + nt*8 + tq*2;
        const int d0 = wm*16 + g;
        *(float2*)(out + (size_t)d0*F_ + f)     = make_float2(acc[nt][0], acc[nt][1]);
        *(float2*)(out + (size_t)(d0+8)*F_ + f) = make_float2(acc[nt][2], acc[nt][3]);
    }
}

// ---------------- phase B: exclusive cumsum -> bf16 hi/lo --------------------
__global__ __launch_bounds__(1024)
void kv_scan_kernel(const float* __restrict__ kvT,
                    __nv_bfloat16* __restrict__ STh, __nv_bfloat16* __restrict__ STl)
{
    const int blk = blockIdx.x;
    const int bh = blk >> 3, seg = blk & 7;
    const int e = seg*1024 + threadIdx.x;
    size_t base = (size_t)bh * N_ * (F_*HD_) + e;
    float acc = 0.f;
    for (int n = 0; n < N_; n++) {
        size_t idx = base + (size_t)n * (F_*HD_);
        __nv_bfloat16 hv, lv;
        bsplit(acc, hv, lv);
        STh[idx] = hv;
        STl[idx] = lv;
        acc += kvT[idx];
    }
}

// ---------------- phase C: out = q@S_excl + tril(q@k^T)@v  (tensor core) -----
// smem layout (bytes):
//  QH 0, QL 17408           : q hi/lo [64 c][128 f] pitch 272
//  KH 34816, KL 52224       : k hi/lo [64][128] p272, later ST hi/lo [64 d][128 f]
//  VTH 69632, VTL 78848     : vT hi/lo [64 d][64 c] pitch 144
//  SCH 88064, SCL 97280     : masked scores hi/lo [64 c][64 m] pitch 144
#define CO_QH 0u
#define CO_QL 17408u
#define CO_KH 34816u
#define CO_KL 52224u
#define CO_VTH 69632u
#define CO_VTL 78848u
#define CO_SCH 88064u
#define CO_SCL 97280u
#define CO_SMEM 106496u

__global__ __launch_bounds__(256, 1)
void chunk_out_kernel(const __nv_bfloat16* __restrict__ qfh, const __nv_bfloat16* __restrict__ qfl,
                      const __nv_bfloat16* __restrict__ kfh, const __nv_bfloat16* __restrict__ kfl,
                      const __nv_bfloat16* __restrict__ vh,  const __nv_bfloat16* __restrict__ vl,
                      const __nv_bfloat16* __restrict__ STh, const __nv_bfloat16* __restrict__ STl,
                      __nv_bfloat16* __restrict__ ohi, __nv_bfloat16* __restrict__ olo)
{
    extern __shared__ __align__(16) char smem[];
    const uint32_t sb = smem_u32(smem);
    const int blk = blockIdx.x;
    const int n = blk & 31, bh = blk >> 5;
    const int b = bh >> 4, h = bh & 15;
    const int tid = threadIdx.x, wid = tid >> 5, lane = tid & 31;

    // load q, k (row-major [c][f], pitch 272)
    {
        const int c = tid >> 2, fg = (tid & 3) * 32;
        const size_t src = ((size_t)bh*T_ + n*C_ + c)*F_ + fg;
        uint4* dq  = (uint4*)(smem + CO_QH + c*272 + fg*2);
        uint4* dql = (uint4*)(smem + CO_QL + c*272 + fg*2);
        uint4* dk  = (uint4*)(smem + CO_KH + c*272 + fg*2);
        uint4* dkl = (uint4*)(smem + CO_KL + c*272 + fg*2);
        #pragma unroll
        for (int q = 0; q < 4; q++) {
            dq [q] = *(const uint4*)(qfh + src + q*8);
            dql[q] = *(const uint4*)(qfl + src + q*8);
            dk [q] = *(const uint4*)(kfh + src + q*8);
            dkl[q] = *(const uint4*)(kfl + src + q*8);
        }
    }
    // v -> vT
    {
        const int c = tid >> 2, dg = (tid & 3) * 16;
        const size_t src = ((size_t)(b*T_) + n*C_ + c)*D_ + h*HD_ + dg;
        union { uint4 u; __nv_bfloat16 bb[8]; } r;
        #pragma unroll
        for (int q = 0; q < 2; q++) {
            r.u = *(const uint4*)(vh + src + q*8);
            #pragma unroll
            for (int i = 0; i < 8; i++)
                *(__nv_bfloat16*)(smem + CO_VTH + (dg+q*8+i)*144 + c*2) = r.bb[i];
            r.u = *(const uint4*)(vl + src + q*8);
            #pragma unroll
            for (int i = 0; i < 8; i++)
                *(__nv_bfloat16*)(smem + CO_VTL + (dg+q*8+i)*144 + c*2) = r.bb[i];
        }
    }
    __syncthreads();

    const int wm = wid & 3, wn = wid >> 2;   // 4 m-tiles x 2 n-halves(32)
    const int g = lane >> 2, tq = lane & 3;

    const uint32_t aQ = sb + CO_QH + (uint32_t)(wm*16 + (lane & 15))*272 + (uint32_t)(lane >> 4)*16;
    const uint32_t bK = sb + CO_KH + (uint32_t)(wn*32 + ((lane >> 4) & 1)*8 + (lane & 7))*272
                      + (uint32_t)((lane >> 3) & 1)*16;

    // ---- scores = q @ k^T ----
    float sacc[4][4];
    #pragma unroll
    for (int i = 0; i < 4; i++)
        #pragma unroll
        for (int j = 0; j < 4; j++) sacc[i][j] = 0.f;

    #pragma unroll
    for (int ks = 0; ks < 8; ks++) {
        const uint32_t koff = (uint32_t)ks*32;
        uint32_t ah[4], al[4];
        ldm_x4(aQ + koff, ah[0], ah[1], ah[2], ah[3]);
        ldm_x4(aQ + (CO_QL - CO_QH) + koff, al[0], al[1], al[2], al[3]);
        uint32_t bhf[2][4], blf[2][4];
        #pragma unroll
        for (int p = 0; p < 2; p++) {
            const uint32_t ba = bK + (uint32_t)p*16*272 + koff;
            ldm_x4(ba, bhf[p][0], bhf[p][1], bhf[p][2], bhf[p][3]);
            ldm_x4(ba + (CO_KL - CO_KH), blf[p][0], blf[p][1], blf[p][2], blf[p][3]);
        }
        #pragma unroll
        for (int nt = 0; nt < 4; nt++) {
            const uint32_t* bhp = &bhf[nt >> 1][(nt & 1)*2];
            const uint32_t* blp = &blf[nt >> 1][(nt & 1)*2];
            float* d = sacc[nt];
            mma16816(d[0], d[1], d[2], d[3], ah[0], ah[1], ah[2], ah[3], bhp[0], bhp[1]);
            mma16816(d[0], d[1], d[2], d[3], ah[0], ah[1], ah[2], ah[3], blp[0], blp[1]);
            mma16816(d[0], d[1], d[2], d[3], al[0], al[1], al[2], al[3], bhp[0], bhp[1]);
        }
    }
    // mask (m <= c) and store hi/lo scores to smem
    #pragma unroll
    for (int nt = 0; nt < 4; nt++) {
        const int colb = wn*32 + nt*8 + tq*2;
        const int r0 = wm*16 + g, r1 = r0 + 8;
        float v00 = (colb     <= r0) ? sacc[nt][0] : 0.f;
        float v01 = (colb + 1 <= r0) ? sacc[nt][1] : 0.f;
        float v10 = (colb     <= r1) ? sacc[nt][2] : 0.f;
        float v11 = (colb + 1 <= r1) ? sacc[nt][3] : 0.f;
        __nv_bfloat16 h0, l0, h1, l1;
        bsplit(v00, h0, l0); bsplit(v01, h1, l1);
        *(__nv_bfloat162*)(smem + CO_SCH + r0*144 + colb*2) = __nv_bfloat162(h0, h1);
        *(__nv_bfloat162*)(smem + CO_SCL + r0*144 + colb*2) = __nv_bfloat162(l0, l1);
        bsplit(v10, h0, l0); bsplit(v11, h1, l1);
        *(__nv_bfloat162*)(smem + CO_SCH + r1*144 + colb*2) = __nv_bfloat162(h0, h1);
        *(__nv_bfloat162*)(smem + CO_SCL + r1*144 + colb*2) = __nv_bfloat162(l0, l1);
    }
    __syncthreads();   // scores done; k reads done -> safe to overwrite KH/KL

    // load S_excl^T [d][f] into KH/KL
    {
        const int d = tid >> 2, fg = (tid & 3) * 32;
        const size_t src = (size_t)blk*(F_*HD_) + d*F_ + fg;
        uint4* dh = (uint4*)(smem + CO_KH + d*272 + fg*2);
        uint4* dl = (uint4*)(smem + CO_KL + d*272 + fg*2);
        #pragma unroll
        for (int q = 0; q < 4; q++) {
            dh[q] = *(const uint4*)(STh + src + q*8);
            dl[q] = *(const uint4*)(STl + src + q*8);
        }
    }
    __syncthreads();

    // ---- out = q @ ST^T(=S_excl) + scores @ v ----
    float oacc[4][4];
    #pragma unroll
    for (int i = 0; i < 4; i++)
        #pragma unroll
        for (int j = 0; j < 4; j++) oacc[i][j] = 0.f;

    #pragma unroll
    for (int ks = 0; ks < 8; ks++) {     // inter, k=f=128
        const uint32_t koff = (uint32_t)ks*32;
        uint32_t ah[4], al[4];
        ldm_x4(aQ + koff, ah[0], ah[1], ah[2], ah[3]);
        ldm_x4(aQ + (CO_QL - CO_QH) + koff, al[0], al[1], al[2], al[3]);
        uint32_t bhf[2][4], blf[2][4];
        #pragma unroll
        for (int p = 0; p < 2; p++) {
            const uint32_t ba = bK + (uint32_t)p*16*272 + koff;
            ldm_x4(ba, bhf[p][0], bhf[p][1], bhf[p][2], bhf[p][3]);
            ldm_x4(ba + (CO_KL - CO_KH), blf[p][0], blf[p][1], blf[p][2], blf[p][3]);
        }
        #pragma unroll
        for (int nt = 0; nt < 4; nt++) {
            const uint32_t* bhp = &bhf[nt >> 1][(nt & 1)*2];
            const uint32_t* blp = &blf[nt >> 1][(nt & 1)*2];
            float* d = oacc[nt];
            mma16816(d[0], d[1], d[2], d[3], ah[0], ah[1], ah[2], ah[3], bhp[0], bhp[1]);
            mma16816(d[0], d[1], d[2], d[3], ah[0], ah[1], ah[2], ah[3], blp[0], blp[1]);
            mma16816(d[0], d[1], d[2], d[3], al[0], al[1], al[2], al[3], bhp[0], bhp[1]);
        }
    }
    {   // intra, k=m=64: A = scores (smem), B = vT
        const uint32_t aS = sb + CO_SCH + (uint32_t)(wm*16 + (lane & 15))*144
                          + (uint32_t)(lane >> 4)*16;
        const uint32_t bV = sb + CO_VTH + (uint32_t)(wn*32 + ((lane >> 4) & 1)*8 + (lane & 7))*144
                          + (uint32_t)((lane >> 3) & 1)*16;
        #pragma unroll
        for (int ks = 0; ks < 4; ks++) {
            const uint32_t koff = (uint32_t)ks*32;
            uint32_t ah[4], al[4];
            ldm_x4(aS + koff, ah[0], ah[1], ah[2], ah[3]);
            ldm_x4(aS + (CO_SCL - CO_SCH) + koff, al[0], al[1], al[2], al[3]);
            uint32_t bhf[2][4], blf[2][4];
            #pragma unroll
            for (int p = 0; p < 2; p++) {
                const uint32_t ba = bV + (uint32_t)p*16*144 + koff;
                ldm_x4(ba, bhf[p][0], bhf[p][1], bhf[p][2], bhf[p][3]);
                ldm_x4(ba + (CO_VTL - CO_VTH), blf[p][0], blf[p][1], blf[p][2], blf[p][3]);
            }
            #pragma unroll
            for (int nt = 0; nt < 4; nt++) {
                const uint32_t* bhp = &bhf[nt >> 1][(nt & 1)*2];
                const uint32_t* blp = &blf[nt >> 1][(nt & 1)*2];
                float* d = oacc[nt];
                mma16816(d[0], d[1], d[2], d[3], ah[0], ah[1], ah[2], ah[3], bhp[0], bhp[1]);
                mma16816(d[0], d[1], d[2], d[3], ah[0], ah[1], ah[2], ah[3], blp[0], blp[1]);
                mma16816(d[0], d[1], d[2], d[3], al[0], al[1], al[2], al[3], bhp[0], bhp[1]);
            }
        }
    }

    // write o as bf16 hi/lo in [B,T,H*HD] layout
    #pragma unroll
    for (int nt = 0; nt < 4; nt++) {
        const int dcol = wn*32 + nt*8 + tq*2;
        const int r0 = wm*16 + g;
        #pragma unroll
        for (int half = 0; half < 2; half++) {
            const int r = r0 + half*8;
            const float va = oacc[nt][half*2], vb = oacc[nt][half*2+1];
            __nv_bfloat16 ha, la, hb, lb;
            bsplit(va, ha, la); bsplit(vb, hb, lb);
            const size_t oidx = ((size_t)(b*T_) + n*C_ + r)*D_ + h*HD_ + dcol;
            *(__nv_bfloat162*)(ohi + oidx) = __nv_bfloat162(ha, hb);
            *(__nv_bfloat162*)(olo + oidx) = __nv_bfloat162(la, lb);
        }
    }
}

// ---------------- launcher ----------------------------------------------------
extern "C" void kernel_launch(void* const* d_in, const int* in_sizes, int n_in,
                              void* d_out, int out_size)
{
    const float* hs   = (const float*)d_in[0];
    const float* res  = (const float*)d_in[1];
    const float* nw   = (const float*)d_in[2];
    const float* w_q  = (const float*)d_in[3];
    const float* w_k  = (const float*)d_in[4];
    const float* w_v  = (const float*)d_in[5];
    const float* w_o  = (const float*)d_in[6];
    const float* hqw  = (const float*)d_in[7];
    const float* hqb  = (const float*)d_in[8];
    const float* hkw  = (const float*)d_in[9];
    const float* hkb  = (const float*)d_in[10];
    float* out = (float*)d_out;

    float *pq, *pk, *pv, *pkv;
    __nv_bfloat16 *pxhi, *pxlo, *pohi, *polo, *pwq, *pwk, *pwv, *pwo;
    __nv_bfloat16 *pqfh, *pqfl, *pkfh, *pkfl, *pvh, *pvl, *pSTh, *pSTl;
    cudaGetSymbolAddress((void**)&pq,   g_q);
    cudaGetSymbolAddress((void**)&pk,   g_k);
    cudaGetSymbolAddress((void**)&pv,   g_v);
    cudaGetSymbolAddress((void**)&pkv,  g_kv);
    cudaGetSymbolAddress((void**)&pxhi, g_xhi);
    cudaGetSymbolAddress((void**)&pxlo, g_xlo);
    cudaGetSymbolAddress((void**)&pohi, g_ohi);
    cudaGetSymbolAddress((void**)&polo, g_olo);
    cudaGetSymbolAddress((void**)&pwq,  g_wqT);
    cudaGetSymbolAddress((void**)&pwk,  g_wkT);
    cudaGetSymbolAddress((void**)&pwv,  g_wvT);
    cudaGetSymbolAddress((void**)&pwo,  g_woT);
    cudaGetSymbolAddress((void**)&pqfh, g_qfh);
    cudaGetSymbolAddress((void**)&pqfl, g_qfl);
    cudaGetSymbolAddress((void**)&pkfh, g_kfh);
    cudaGetSymbolAddress((void**)&pkfl, g_kfl);
    cudaGetSymbolAddress((void**)&pvh,  g_vh);
    cudaGetSymbolAddress((void**)&pvl,  g_vl);
    cudaGetSymbolAddress((void**)&pSTh, g_STh);
    cudaGetSymbolAddress((void**)&pSTl, g_STl);

    cudaFuncSetAttribute(gemm_bf16x3,
                         cudaFuncAttributeMaxDynamicSharedMemorySize, GSMEM);
    cudaFuncSetAttribute(chunk_kv_kernel,
                         cudaFuncAttributeMaxDynamicSharedMemorySize, CKV_SMEM);
    cudaFuncSetAttribute(chunk_out_kernel,
                         cudaFuncAttributeMaxDynamicSharedMemorySize, CO_SMEM);

    // 1) fused add + RMSNorm -> resid (2nd half of out) + split x
    addnorm_kernel<<<BT_, 256>>>(hs, res, nw, out + (size_t)BT_*D_, pxhi, pxlo);

    // 2) weight transpose+split
    dim3 wgrid(32, 32);
    wsplit_kernel<<<wgrid, 256>>>(w_q, pwq);
    wsplit_kernel<<<wgrid, 256>>>(w_k, pwk);
    wsplit_kernel<<<wgrid, 256>>>(w_v, pwv);
    wsplit_kernel<<<wgrid, 256>>>(w_o, pwo);

    // 3) QKV projections (HMMA bf16x3)
    dim3 ggrid(D_/128, BT_/128);
    gemm_bf16x3<<<ggrid, 256, GSMEM>>>(pxhi, pxlo, pwq, pq);
    gemm_bf16x3<<<ggrid, 256, GSMEM>>>(pxhi, pxlo, pwk, pk);
    gemm_bf16x3<<<ggrid, 256, GSMEM>>>(pxhi, pxlo, pwv, pv);

    // 4) hedgehog features (bf16 hi/lo) + v split
    hedgehog_kernel<<<BHT_/8, 256>>>(pq, hqw, hqb, pqfh, pqfl, 0.08838834764831845f);
    hedgehog_kernel<<<BHT_/8, 256>>>(pk, hkw, hkb, pkfh, pkfl, 1.0f);
    fsplit_kernel<<<BT_, 256>>>(pv, pvh, pvl);

    // 5) chunked linear attention (tensor cores)
    chunk_kv_kernel<<<NCHUNK_, 256, CKV_SMEM>>>(pkfh, pkfl, pvh, pvl, pkv);
    kv_scan_kernel<<<512, 1024>>>(pkv, pSTh, pSTl);
    chunk_out_kernel<<<NCHUNK_, 256, CO_SMEM>>>(pqfh, pqfl, pkfh, pkfl, pvh, pvl,
                                                pSTh, pSTl, pohi, polo);

    // 6) output projection
    gemm_bf16x3<<<ggrid, 256, GSMEM>>>(pohi, polo, pwo, out);
}

// round 6
// speedup vs baseline: 2.2638x; 1.1971x over previous
#include <cuda_runtime.h>
#include <cuda_bf16.h>
#include <stdint.h>
#include <math.h>

// Problem constants
#define B_  4
#define T_  2048
#define D_  1024
#define H_  16
#define HD_ 64
#define F_  128
#define C_  64
#define N_  32
#define BT_ (B_*T_)        // 8192
#define BHT_ (B_*H_*T_)    // 131072
#define NCHUNK_ (B_*H_*N_) // 2048

// ---------------- scratch (device globals) ----------------------------------
__device__ float g_q [BT_*D_];                  // y_q = x @ (Wq folded)
__device__ float g_k [BT_*D_];                  // y_k
__device__ float g_kv[NCHUNK_*F_*HD_];          // kv^T per chunk: [d][f]
__device__ __nv_bfloat16 g_STh[NCHUNK_*F_*HD_];
__device__ __nv_bfloat16 g_STl[NCHUNK_*F_*HD_];
__device__ __nv_bfloat16 g_qfh[BHT_*F_];
__device__ __nv_bfloat16 g_qfl[BHT_*F_];
__device__ __nv_bfloat16 g_kfh[BHT_*F_];
__device__ __nv_bfloat16 g_kfl[BHT_*F_];
__device__ __nv_bfloat16 g_vh [BT_*D_];
__device__ __nv_bfloat16 g_vl [BT_*D_];
__device__ __nv_bfloat16 g_xhi[BT_*D_];
__device__ __nv_bfloat16 g_xlo[BT_*D_];
__device__ __nv_bfloat16 g_ohi[BT_*D_];
__device__ __nv_bfloat16 g_olo[BT_*D_];
__device__ __nv_bfloat16 g_wT [2*3*D_*D_];      // fused qkv weights: hi [3072,1024], lo at +3*D*D
__device__ __nv_bfloat16 g_woT[2*D_*D_];        // o weights: hi, lo at +D*D

// ---------------- PTX helpers ------------------------------------------------
__device__ __forceinline__ uint32_t smem_u32(const void* p) {
    uint32_t a;
    asm("{ .reg .u64 t; cvta.to.shared.u64 t, %1; cvt.u32.u64 %0, t; }" : "=r"(a) : "l"(p));
    return a;
}
__device__ __forceinline__ void cp_async16(uint32_t saddr, const void* gaddr) {
    asm volatile("cp.async.cg.shared.global [%0], [%1], 16;" :: "r"(saddr), "l"(gaddr));
}
__device__ __forceinline__ void cp_commit() {
    asm volatile("cp.async.commit_group;" ::: "memory");
}
template <int NN>
__device__ __forceinline__ void cp_wait() {
    asm volatile("cp.async.wait_group %0;" :: "n"(NN) : "memory");
}
__device__ __forceinline__ void ldm_x4(uint32_t addr, uint32_t& r0, uint32_t& r1,
                                       uint32_t& r2, uint32_t& r3) {
    asm volatile("ldmatrix.sync.aligned.m8n8.x4.shared.b16 {%0,%1,%2,%3}, [%4];"
                 : "=r"(r0), "=r"(r1), "=r"(r2), "=r"(r3) : "r"(addr));
}
__device__ __forceinline__ void mma16816(float& d0, float& d1, float& d2, float& d3,
                                         uint32_t a0, uint32_t a1, uint32_t a2, uint32_t a3,
                                         uint32_t b0, uint32_t b1) {
    asm volatile("mma.sync.aligned.m16n8k16.row.col.f32.bf16.bf16.f32 "
                 "{%0,%1,%2,%3}, {%4,%5,%6,%7}, {%8,%9}, {%0,%1,%2,%3};"
                 : "+f"(d0), "+f"(d1), "+f"(d2), "+f"(d3)
                 : "r"(a0), "r"(a1), "r"(a2), "r"(a3), "r"(b0), "r"(b1));
}
__device__ __forceinline__ void bsplit(float v, __nv_bfloat16& h, __nv_bfloat16& l) {
    h = __float2bfloat16_rn(v);
    l = __float2bfloat16_rn(v - __bfloat162float(h));
}

// ---------------- fused add + RMSNorm -> resid + bf16 split x ---------------
__global__ __launch_bounds__(256)
void addnorm_kernel(const float* __restrict__ hs, const float* __restrict__ res,
                    const float* __restrict__ w, float* __restrict__ resid_out,
                    __nv_bfloat16* __restrict__ xhi, __nv_bfloat16* __restrict__ xlo)
{
    __shared__ float red[8];
    const int row = blockIdx.x;
    const int t = threadIdx.x;
    const float4* h4 = (const float4*)(hs  + (size_t)row*D_);
    const float4* r4 = (const float4*)(res + (size_t)row*D_);
    float4*      ro4 = (float4*)(resid_out + (size_t)row*D_);

    float4 h = h4[t], r = r4[t];
    float4 s = make_float4(h.x+r.x, h.y+r.y, h.z+r.z, h.w+r.w);
    ro4[t] = s;
    float ss = s.x*s.x + s.y*s.y + s.z*s.z + s.w*s.w;
    #pragma unroll
    for (int o = 16; o; o >>= 1) ss += __shfl_xor_sync(0xffffffffu, ss, o);
    if ((t & 31) == 0) red[t >> 5] = ss;
    __syncthreads();
    float tot = 0.f;
    #pragma unroll
    for (int i = 0; i < 8; i++) tot += red[i];
    float rstd = rsqrtf(tot * (1.0f/1024.0f) + 1e-5f);
    float4 wv = ((const float4*)w)[t];
    float v[4] = { s.x*rstd*wv.x, s.y*rstd*wv.y, s.z*rstd*wv.z, s.w*rstd*wv.w };
    __nv_bfloat16 hi[4], lo[4];
    #pragma unroll
    for (int i = 0; i < 4; i++) bsplit(v[i], hi[i], lo[i]);
    size_t idx = (size_t)row*D_ + t*4;
    *(__nv_bfloat162*)(xhi+idx)   = __nv_bfloat162(hi[0], hi[1]);
    *(__nv_bfloat162*)(xhi+idx+2) = __nv_bfloat162(hi[2], hi[3]);
    *(__nv_bfloat162*)(xlo+idx)   = __nv_bfloat162(lo[0], lo[1]);
    *(__nv_bfloat162*)(xlo+idx+2) = __nv_bfloat162(lo[2], lo[3]);
}

// ---------------- fold hedgehog weight into projection + transpose + split ---
// out[(rowOff + h*64 + e)*D + k] = sum_d W[k, h*64+d] * hhw[e, d]  (hi; lo at +loOff)
__global__ __launch_bounds__(256)
void foldsplit_kernel(const float* __restrict__ W, const float* __restrict__ hhw,
                      __nv_bfloat16* __restrict__ wT, int rowOff, size_t loOff)
{
    extern __shared__ float fsm[];
    float* Wb = fsm;               // [128][65]
    float* hh = fsm + 128*65;      // [64][64]
    const int h = blockIdx.x, kb = blockIdx.y;
    const int tid = threadIdx.x;
    for (int i = tid; i < 8192; i += 256) {
        int r = i >> 6, d = i & 63;
        Wb[r*65 + d] = W[(size_t)(kb*128 + r)*D_ + h*64 + d];
    }
    for (int i = tid; i < 4096; i += 256) hh[i] = hhw[i];
    __syncthreads();

    const int kk = tid & 127;
    const int e0 = (tid >> 7) * 32;
    float acc[32];
    #pragma unroll
    for (int e = 0; e < 32; e++) acc[e] = 0.f;
    for (int d = 0; d < 64; d++) {
        float wv = Wb[kk*65 + d];
        #pragma unroll
        for (int e = 0; e < 32; e++)
            acc[e] = fmaf(wv, hh[(e0+e)*64 + d], acc[e]);
    }
    #pragma unroll
    for (int e = 0; e < 32; e++) {
        __nv_bfloat16 hi, lo;
        bsplit(acc[e], hi, lo);
        size_t idx = (size_t)(rowOff + h*64 + e0 + e)*D_ + kb*128 + kk;
        wT[idx] = hi;
        wT[idx + loOff] = lo;
    }
}

// ---------------- weight transpose + bf16 split ------------------------------
__global__ __launch_bounds__(256)
void wsplit_kernel(const float* __restrict__ W, __nv_bfloat16* __restrict__ wT,
                   int rowOff, size_t loOff)
{
    __shared__ float t[32][33];
    const int bx = blockIdx.x*32, by = blockIdx.y*32;
    const int tx = threadIdx.x & 31, ty = threadIdx.x >> 5;
    #pragma unroll
    for (int i = ty; i < 32; i += 8) t[i][tx] = W[(size_t)(by+i)*D_ + bx + tx];
    __syncthreads();
    #pragma unroll
    for (int i = ty; i < 32; i += 8) {
        float v = t[tx][i];
        __nv_bfloat16 hi, lo;
        bsplit(v, hi, lo);
        size_t idx = (size_t)(rowOff + bx + i)*D_ + by + tx;
        wT[idx] = hi;
        wT[idx + loOff] = lo;
    }
}

// ---------------- bf16x3 fused QKV GEMM (HMMA) -------------------------------
// N=3072: cols [0,1024)=y_q fp32, [1024,2048)=y_k fp32, [2048,3072)=v bf16 split.
#define PITCH 40
#define MAT_BYTES (128*PITCH*2)
#define STAGE_BYTES (4*MAT_BYTES)
#define GSMEM (2*STAGE_BYTES)

__global__ __launch_bounds__(256, 2)
void gemm_qkv(const __nv_bfloat16* __restrict__ Ahi, const __nv_bfloat16* __restrict__ Alo,
              const __nv_bfloat16* __restrict__ BT,
              float* __restrict__ Qout, float* __restrict__ Kout,
              __nv_bfloat16* __restrict__ Vh, __nv_bfloat16* __restrict__ Vl)
{
    extern __shared__ __align__(16) char smem[];
    const uint32_t sbase = smem_u32(smem);
    const int tid = threadIdx.x, wid = tid >> 5, lane = tid & 31;
    const int bx = blockIdx.x, by = blockIdx.y;
    const int wm = wid & 1, wn = wid >> 1;
    const __nv_bfloat16* Bhi = BT;
    const __nv_bfloat16* Blo = BT + (size_t)3*D_*D_;

    const int lrow = tid >> 1;
    const int lc   = (tid & 1) * 2;
    const size_t gA = (size_t)(by*128 + lrow) * D_;
    const size_t gB = (size_t)(bx*128 + lrow) * D_;
    const uint32_t sRow = (uint32_t)lrow * 80;

    float acc[4][4][4];
    #pragma unroll
    for (int i = 0; i < 4; i++)
        #pragma unroll
        for (int j = 0; j < 4; j++)
            #pragma unroll
            for (int l = 0; l < 4; l++) acc[i][j][l] = 0.f;

    #define PREFETCH(kt, buf) do {                                              \
        const int k0 = (kt) * 32;                                               \
        const uint32_t b0 = sbase + (uint32_t)(buf) * STAGE_BYTES;              \
        _Pragma("unroll")                                                       \
        for (int u = 0; u < 2; u++) {                                           \
            const int c = lc + u;                                               \
            const uint32_t so = sRow + (uint32_t)c * 16;                        \
            const size_t go = (size_t)k0 + c * 8;                               \
            cp_async16(b0 + 0*MAT_BYTES + so, Ahi + gA + go);                   \
            cp_async16(b0 + 1*MAT_BYTES + so, Alo + gA + go);                   \
            cp_async16(b0 + 2*MAT_BYTES + so, Bhi + gB + go);                   \
            cp_async16(b0 + 3*MAT_BYTES + so, Blo + gB + go);                   \
        }                                                                       \
        cp_commit();                                                            \
    } while (0)

    PREFETCH(0, 0);
    PREFETCH(1, 1);

    const uint32_t aRow = (uint32_t)(wm*64 + (lane & 15)) * 80 + (uint32_t)(lane >> 4) * 16;
    const uint32_t bRow = (uint32_t)(wn*32 + ((lane >> 4) & 1)*8 + (lane & 7)) * 80
                        + (uint32_t)((lane >> 3) & 1) * 16;

    const int TILES = D_ / 32;
    #pragma unroll 1
    for (int kt = 0; kt < TILES; kt++) {
        const int cur = kt & 1;
        if (kt == TILES - 1) cp_wait<0>(); else cp_wait<1>();
        __syncthreads();
        const uint32_t sb = sbase + (uint32_t)cur * STAGE_BYTES;

        #pragma unroll
        for (int kk = 0; kk < 2; kk++) {
            const uint32_t koff = (uint32_t)kk * 32;
            uint32_t bh[2][4], bl[2][4];
            #pragma unroll
            for (int nt2 = 0; nt2 < 2; nt2++) {
                const uint32_t ba = bRow + (uint32_t)nt2 * 16 * 80 + koff;
                ldm_x4(sb + 2*MAT_BYTES + ba, bh[nt2][0], bh[nt2][1], bh[nt2][2], bh[nt2][3]);
                ldm_x4(sb + 3*MAT_BYTES + ba, bl[nt2][0], bl[nt2][1], bl[nt2][2], bl[nt2][3]);
            }
            #pragma unroll
            for (int mt = 0; mt < 4; mt++) {
                const uint32_t aa = aRow + (uint32_t)mt * 16 * 80 + koff;
                uint32_t ah[4], al[4];
                ldm_x4(sb + 0*MAT_BYTES + aa, ah[0], ah[1], ah[2], ah[3]);
                ldm_x4(sb + 1*MAT_BYTES + aa, al[0], al[1], al[2], al[3]);
                #pragma unroll
                for (int nt = 0; nt < 4; nt++) {
                    const uint32_t* bhp = &bh[nt >> 1][(nt & 1) * 2];
                    const uint32_t* blp = &bl[nt >> 1][(nt & 1) * 2];
                    float* d = acc[mt][nt];
                    mma16816(d[0], d[1], d[2], d[3], ah[0], ah[1], ah[2], ah[3], bhp[0], bhp[1]);
                    mma16816(d[0], d[1], d[2], d[3], ah[0], ah[1], ah[2], ah[3], blp[0], blp[1]);
                    mma16816(d[0], d[1], d[2], d[3], al[0], al[1], al[2], al[3], bhp[0], bhp[1]);
                }
            }
        }
        __syncthreads();
        if (kt + 2 < TILES) PREFETCH(kt + 2, cur);
    }
    #undef PREFETCH

    const int g = lane >> 2, tq = lane & 3;
    if (bx < 16) {
        float* dst = (bx < 8) ? Qout : Kout;
        const int colbase = (bx & 7)*128;
        #pragma unroll
        for (int mt = 0; mt < 4; mt++) {
            const int r0 = by*128 + wm*64 + mt*16 + g;
            #pragma unroll
            for (int nt = 0; nt < 4; nt++) {
                const int col = colbase + wn*32 + nt*8 + tq*2;
                float* d = acc[mt][nt];
                *(float2*)(dst + (size_t)r0*D_ + col)     = make_float2(d[0], d[1]);
                *(float2*)(dst + (size_t)(r0+8)*D_ + col) = make_float2(d[2], d[3]);
            }
        }
    } else {
        const int colbase = (bx - 16)*128;
        #pragma unroll
        for (int mt = 0; mt < 4; mt++) {
            const int r0 = by*128 + wm*64 + mt*16 + g;
            #pragma unroll
            for (int nt = 0; nt < 4; nt++) {
                const int col = colbase + wn*32 + nt*8 + tq*2;
                float* d = acc[mt][nt];
                __nv_bfloat16 h0, l0, h1, l1;
                bsplit(d[0], h0, l0); bsplit(d[1], h1, l1);
                *(__nv_bfloat162*)(Vh + (size_t)r0*D_ + col) = __nv_bfloat162(h0, h1);
                *(__nv_bfloat162*)(Vl + (size_t)r0*D_ + col) = __nv_bfloat162(l0, l1);
                bsplit(d[2], h0, l0); bsplit(d[3], h1, l1);
                *(__nv_bfloat162*)(Vh + (size_t)(r0+8)*D_ + col) = __nv_bfloat162(h0, h1);
                *(__nv_bfloat162*)(Vl + (size_t)(r0+8)*D_ + col) = __nv_bfloat162(l0, l1);
            }
        }
    }
}

// ---------------- bf16x3 GEMM (single fp32 output; o-projection) -------------
__global__ __launch_bounds__(256, 2)
void gemm_bf16x3(const __nv_bfloat16* __restrict__ Ahi, const __nv_bfloat16* __restrict__ Alo,
                 const __nv_bfloat16* __restrict__ BT, float* __restrict__ Cout)
{
    extern __shared__ __align__(16) char smem[];
    const uint32_t sbase = smem_u32(smem);
    const int tid = threadIdx.x, wid = tid >> 5, lane = tid & 31;
    const int bx = blockIdx.x, by = blockIdx.y;
    const int wm = wid & 1, wn = wid >> 1;
    const __nv_bfloat16* Bhi = BT;
    const __nv_bfloat16* Blo = BT + (size_t)D_*D_;

    const int lrow = tid >> 1;
    const int lc   = (tid & 1) * 2;
    const size_t gA = (size_t)(by*128 + lrow) * D_;
    const size_t gB = (size_t)(bx*128 + lrow) * D_;
    const uint32_t sRow = (uint32_t)lrow * 80;

    float acc[4][4][4];
    #pragma unroll
    for (int i = 0; i < 4; i++)
        #pragma unroll
        for (int j = 0; j < 4; j++)
            #pragma unroll
            for (int l = 0; l < 4; l++) acc[i][j][l] = 0.f;

    #define PREFETCH(kt, buf) do {                                              \
        const int k0 = (kt) * 32;                                               \
        const uint32_t b0 = sbase + (uint32_t)(buf) * STAGE_BYTES;              \
        _Pragma("unroll")                                                       \
        for (int u = 0; u < 2; u++) {                                           \
            const int c = lc + u;                                               \
            const uint32_t so = sRow + (uint32_t)c * 16;                        \
            const size_t go = (size_t)k0 + c * 8;                               \
            cp_async16(b0 + 0*MAT_BYTES + so, Ahi + gA + go);                   \
            cp_async16(b0 + 1*MAT_BYTES + so, Alo + gA + go);                   \
            cp_async16(b0 + 2*MAT_BYTES + so, Bhi + gB + go);                   \
            cp_async16(b0 + 3*MAT_BYTES + so, Blo + gB + go);                   \
        }                                                                       \
        cp_commit();                                                            \
    } while (0)

    PREFETCH(0, 0);
    PREFETCH(1, 1);

    const uint32_t aRow = (uint32_t)(wm*64 + (lane & 15)) * 80 + (uint32_t)(lane >> 4) * 16;
    const uint32_t bRow = (uint32_t)(wn*32 + ((lane >> 4) & 1)*8 + (lane & 7)) * 80
                        + (uint32_t)((lane >> 3) & 1) * 16;

    const int TILES = D_ / 32;
    #pragma unroll 1
    for (int kt = 0; kt < TILES; kt++) {
        const int cur = kt & 1;
        if (kt == TILES - 1) cp_wait<0>(); else cp_wait<1>();
        __syncthreads();
        const uint32_t sb = sbase + (uint32_t)cur * STAGE_BYTES;

        #pragma unroll
        for (int kk = 0; kk < 2; kk++) {
            const uint32_t koff = (uint32_t)kk * 32;
            uint32_t bh[2][4], bl[2][4];
            #pragma unroll
            for (int nt2 = 0; nt2 < 2; nt2++) {
                const uint32_t ba = bRow + (uint32_t)nt2 * 16 * 80 + koff;
                ldm_x4(sb + 2*MAT_BYTES + ba, bh[nt2][0], bh[nt2][1], bh[nt2][2], bh[nt2][3]);
                ldm_x4(sb + 3*MAT_BYTES + ba, bl[nt2][0], bl[nt2][1], bl[nt2][2], bl[nt2][3]);
            }
            #pragma unroll
            for (int mt = 0; mt < 4; mt++) {
                const uint32_t aa = aRow + (uint32_t)mt * 16 * 80 + koff;
                uint32_t ah[4], al[4];
                ldm_x4(sb + 0*MAT_BYTES + aa, ah[0], ah[1], ah[2], ah[3]);
                ldm_x4(sb + 1*MAT_BYTES + aa, al[0], al[1], al[2], al[3]);
                #pragma unroll
                for (int nt = 0; nt < 4; nt++) {
                    const uint32_t* bhp = &bh[nt >> 1][(nt & 1) * 2];
                    const uint32_t* blp = &bl[nt >> 1][(nt & 1) * 2];
                    float* d = acc[mt][nt];
                    mma16816(d[0], d[1], d[2], d[3], ah[0], ah[1], ah[2], ah[3], bhp[0], bhp[1]);
                    mma16816(d[0], d[1], d[2], d[3], ah[0], ah[1], ah[2], ah[3], blp[0], blp[1]);
                    mma16816(d[0], d[1], d[2], d[3], al[0], al[1], al[2], al[3], bhp[0], bhp[1]);
                }
            }
        }
        __syncthreads();
        if (kt + 2 < TILES) PREFETCH(kt + 2, cur);
    }
    #undef PREFETCH

    const int g = lane >> 2, tq = lane & 3;
    #pragma unroll
    for (int mt = 0; mt < 4; mt++) {
        const int r0 = by*128 + wm*64 + mt*16 + g;
        #pragma unroll
        for (int nt = 0; nt < 4; nt++) {
            const int col = bx*128 + wn*32 + nt*8 + tq*2;
            float* d = acc[mt][nt];
            *(float2*)(Cout + (size_t)r0*D_ + col)     = make_float2(d[0], d[1]);
            *(float2*)(Cout + (size_t)(r0+8)*D_ + col) = make_float2(d[2], d[3]);
        }
    }
}

// ---------------- hedgehog: bias + softmax([y,-y]) -> bf16 hi/lo -------------
__global__ __launch_bounds__(256)
void hedgehog_kernel(const float* __restrict__ y, const float* __restrict__ bias,
                     __nv_bfloat16* __restrict__ fh, __nv_bfloat16* __restrict__ fl,
                     float scale)
{
    const int tid = threadIdx.x;
    const int warp = tid >> 5, lane = tid & 31;
    const int g = blockIdx.x*8 + warp;
    const int b = g >> 15;
    const int h = (g >> 11) & 15;
    const int t = g & 2047;
    const float* yp = y + ((size_t)(b*T_ + t))*D_ + h*HD_;
    float y0 = yp[lane]      + bias[lane];
    float y1 = yp[lane + 32] + bias[lane + 32];

    float m = fmaxf(fabsf(y0), fabsf(y1));
    #pragma unroll
    for (int o = 16; o; o >>= 1) m = fmaxf(m, __shfl_xor_sync(0xffffffffu, m, o));
    float e0 = __expf(y0 - m), e1 = __expf(y1 - m);
    float e2 = __expf(-y0 - m), e3 = __expf(-y1 - m);
    float z = e0 + e1 + e2 + e3;
    #pragma unroll
    for (int o = 16; o; o >>= 1) z += __shfl_xor_sync(0xffffffffu, z, o);
    float inv = scale / z;
    float vals[4] = { e0*inv, e1*inv, e2*inv, e3*inv };
    __nv_bfloat16* fph = fh + (size_t)g * F_;
    __nv_bfloat16* fpl = fl + (size_t)g * F_;
    #pragma unroll
    for (int i = 0; i < 4; i++) {
        __nv_bfloat16 hv, lv;
        bsplit(vals[i], hv, lv);
        fph[lane + i*32] = hv;
        fpl[lane + i*32] = lv;
    }
}

// ---------------- phase A: kv^T[d][f] = sum_c v[c,d] k[c,f]  (tensor core) ---
#define CKV_KTH 0u
#define CKV_KTL 18432u
#define CKV_VTH 36864u
#define CKV_VTL 46080u
#define CKV_SMEM 55296u

__global__ __launch_bounds__(256, 2)
void chunk_kv_kernel(const __nv_bfloat16* __restrict__ kfh, const __nv_bfloat16* __restrict__ kfl,
                     const __nv_bfloat16* __restrict__ vh, const __nv_bfloat16* __restrict__ vl,
                     float* __restrict__ kvT)
{
    extern __shared__ __align__(16) char smem[];
    const uint32_t sb = smem_u32(smem);
    const int blk = blockIdx.x;
    const int n = blk & 31, bh = blk >> 5;
    const int b = bh >> 4, h = bh & 15;
    const int tid = threadIdx.x, wid = tid >> 5, lane = tid & 31;

    {
        const int c = tid >> 2, fg = (tid & 3) * 32;
        const size_t src = ((size_t)bh*T_ + n*C_ + c)*F_ + fg;
        union { uint4 u; __nv_bfloat16 b[8]; } r;
        #pragma unroll
        for (int q = 0; q < 4; q++) {
            r.u = *(const uint4*)(kfh + src + q*8);
            #pragma unroll
            for (int i = 0; i < 8; i++)
                *(__nv_bfloat16*)(smem + CKV_KTH + (fg+q*8+i)*144 + c*2) = r.b[i];
            r.u = *(const uint4*)(kfl + src + q*8);
            #pragma unroll
            for (int i = 0; i < 8; i++)
                *(__nv_bfloat16*)(smem + CKV_KTL + (fg+q*8+i)*144 + c*2) = r.b[i];
        }
    }
    {
        const int c = tid >> 2, dg = (tid & 3) * 16;
        const size_t src = ((size_t)(b*T_) + n*C_ + c)*D_ + h*HD_ + dg;
        union { uint4 u; __nv_bfloat16 b[8]; } r;
        #pragma unroll
        for (int q = 0; q < 2; q++) {
            r.u = *(const uint4*)(vh + src + q*8);
            #pragma unroll
            for (int i = 0; i < 8; i++)
                *(__nv_bfloat16*)(smem + CKV_VTH + (dg+q*8+i)*144 + c*2) = r.b[i];
            r.u = *(const uint4*)(vl + src + q*8);
            #pragma unroll
            for (int i = 0; i < 8; i++)
                *(__nv_bfloat16*)(smem + CKV_VTL + (dg+q*8+i)*144 + c*2) = r.b[i];
        }
    }
    __syncthreads();

    const int wm = wid & 3, wn = wid >> 2;
    float acc[8][4];
    #pragma unroll
    for (int i = 0; i < 8; i++)
        #pragma unroll
        for (int j = 0; j < 4; j++) acc[i][j] = 0.f;

    const uint32_t aBase = sb + CKV_VTH + (uint32_t)(wm*16 + (lane & 15))*144
                         + (uint32_t)(lane >> 4)*16;
    const uint32_t bBase = sb + CKV_KTH + (uint32_t)(wn*64 + ((lane >> 4) & 1)*8 + (lane & 7))*144
                         + (uint32_t)((lane >> 3) & 1)*16;

    #pragma unroll
    for (int ks = 0; ks < 4; ks++) {
        const uint32_t koff = (uint32_t)ks*32;
        uint32_t ah[4], al[4];
        ldm_x4(aBase + koff, ah[0], ah[1], ah[2], ah[3]);
        ldm_x4(aBase + (CKV_VTL - CKV_VTH) + koff, al[0], al[1], al[2], al[3]);
        uint32_t bhf[4][4], blf[4][4];
        #pragma unroll
        for (int p = 0; p < 4; p++) {
            const uint32_t ba = bBase + (uint32_t)p*16*144 + koff;
            ldm_x4(ba, bhf[p][0], bhf[p][1], bhf[p][2], bhf[p][3]);
            ldm_x4(ba + (CKV_KTL - CKV_KTH), blf[p][0], blf[p][1], blf[p][2], blf[p][3]);
        }
        #pragma unroll
        for (int nt = 0; nt < 8; nt++) {
            const uint32_t* bhp = &bhf[nt >> 1][(nt & 1)*2];
            const uint32_t* blp = &blf[nt >> 1][(nt & 1)*2];
            float* d = acc[nt];
            mma16816(d[0], d[1], d[2], d[3], ah[0], ah[1], ah[2], ah[3], bhp[0], bhp[1]);
            mma16816(d[0], d[1], d[2], d[3], ah[0], ah[1], ah[2], ah[3], blp[0], blp[1]);
            mma16816(d[0], d[1], d[2], d[3], al[0], al[1], al[2], al[3], bhp[0], bhp[1]);
        }
    }
    const int g = lane >> 2, tq = lane & 3;
    float* out = kvT + (size_t)blk * (F_*HD_);
    #pragma unroll
    for (int nt = 0; nt < 8; nt++) {
        const int f = wn*64 + nt*8 + tq*2;
        const int d0 = wm*16 + g;
        *(float2*)(out + (size_t)d0*F_ + f)     = make_float2(acc[nt][0], acc[nt][1]);
        *(float2*)(out + (size_t)(d0+8)*F_ + f) = make_float2(acc[nt][2], acc[nt][3]);
    }
}

// ---------------- phase B: exclusive cumsum -> bf16 hi/lo --------------------
__global__ __launch_bounds__(1024)
void kv_scan_kernel(const float* __restrict__ kvT,
                    __nv_bfloat16* __restrict__ STh, __nv_bfloat16* __restrict__ STl)
{
    const int blk = blockIdx.x;
    const int bh = blk >> 3, seg = blk & 7;
    const int e = seg*1024 + threadIdx.x;
    size_t base = (size_t)bh * N_ * (F_*HD_) + e;
    float acc = 0.f;
    for (int n = 0; n < N_; n++) {
        size_t idx = base + (size_t)n * (F_*HD_);
        __nv_bfloat16 hv, lv;
        bsplit(acc, hv, lv);
        STh[idx] = hv;
        STl[idx] = lv;
        acc += kvT[idx];
    }
}

// ---------------- phase C: out = q@S_excl + tril(q@k^T)@v  (tensor core) -----
#define CO_QH 0u
#define CO_QL 17408u
#define CO_KH 34816u
#define CO_KL 52224u
#define CO_VTH 69632u
#define CO_VTL 78848u
#define CO_SCH 88064u
#define CO_SCL 97280u
#define CO_SMEM 106496u

__global__ __launch_bounds__(256, 1)
void chunk_out_kernel(const __nv_bfloat16* __restrict__ qfh, const __nv_bfloat16* __restrict__ qfl,
                      const __nv_bfloat16* __restrict__ kfh, const __nv_bfloat16* __restrict__ kfl,
                      const __nv_bfloat16* __restrict__ vh,  const __nv_bfloat16* __restrict__ vl,
                      const __nv_bfloat16* __restrict__ STh, const __nv_bfloat16* __restrict__ STl,
                      __nv_bfloat16* __restrict__ ohi, __nv_bfloat16* __restrict__ olo)
{
    extern __shared__ __align__(16) char smem[];
    const uint32_t sb = smem_u32(smem);
    const int blk = blockIdx.x;
    const int n = blk & 31, bh = blk >> 5;
    const int b = bh >> 4, h = bh & 15;
    const int tid = threadIdx.x, wid = tid >> 5, lane = tid & 31;

    {
        const int c = tid >> 2, fg = (tid & 3) * 32;
        const size_t src = ((size_t)bh*T_ + n*C_ + c)*F_ + fg;
        uint4* dq  = (uint4*)(smem + CO_QH + c*272 + fg*2);
        uint4* dql = (uint4*)(smem + CO_QL + c*272 + fg*2);
        uint4* dk  = (uint4*)(smem + CO_KH + c*272 + fg*2);
        uint4* dkl = (uint4*)(smem + CO_KL + c*272 + fg*2);
        #pragma unroll
        for (int q = 0; q < 4; q++) {
            dq [q] = *(const uint4*)(qfh + src + q*8);
            dql[q] = *(const uint4*)(qfl + src + q*8);
            dk [q] = *(const uint4*)(kfh + src + q*8);
            dkl[q] = *(const uint4*)(kfl + src + q*8);
        }
    }
    {
        const int c = tid >> 2, dg = (tid & 3) * 16;
        const size_t src = ((size_t)(b*T_) + n*C_ + c)*D_ + h*HD_ + dg;
        union { uint4 u; __nv_bfloat16 bb[8]; } r;
        #pragma unroll
        for (int q = 0; q < 2; q++) {
            r.u = *(const uint4*)(vh + src + q*8);
            #pragma unroll
            for (int i = 0; i < 8; i++)
                *(__nv_bfloat16*)(smem + CO_VTH + (dg+q*8+i)*144 + c*2) = r.bb[i];
            r.u = *(const uint4*)(vl + src + q*8);
            #pragma unroll
            for (int i = 0; i < 8; i++)
                *(__nv_bfloat16*)(smem + CO_VTL + (dg+q*8+i)*144 + c*2) = r.bb[i];
        }
    }
    __syncthreads();

    const int wm = wid & 3, wn = wid >> 2;
    const int g = lane >> 2, tq = lane & 3;

    const uint32_t aQ = sb + CO_QH + (uint32_t)(wm*16 + (lane & 15))*272 + (uint32_t)(lane >> 4)*16;
    const uint32_t bK = sb + CO_KH + (uint32_t)(wn*32 + ((lane >> 4) & 1)*8 + (lane & 7))*272
                      + (uint32_t)((lane >> 3) & 1)*16;

    float sacc[4][4];
    #pragma unroll
    for (int i = 0; i < 4; i++)
        #pragma unroll
        for (int j = 0; j < 4; j++) sacc[i][j] = 0.f;

    #pragma unroll
    for (int ks = 0; ks < 8; ks++) {
        const uint32_t koff = (uint32_t)ks*32;
        uint32_t ah[4], al[4];
        ldm_x4(aQ + koff, ah[0], ah[1], ah[2], ah[3]);
        ldm_x4(aQ + (CO_QL - CO_QH) + koff, al[0], al[1], al[2], al[3]);
        uint32_t bhf[2][4], blf[2][4];
        #pragma unroll
        for (int p = 0; p < 2; p++) {
            const uint32_t ba = bK + (uint32_t)p*16*272 + koff;
            ldm_x4(ba, bhf[p][0], bhf[p][1], bhf[p][2], bhf[p][3]);
            ldm_x4(ba + (CO_KL - CO_KH), blf[p][0], blf[p][1], blf[p][2], blf[p][3]);
        }
        #pragma unroll
        for (int nt = 0; nt < 4; nt++) {
            const uint32_t* bhp = &bhf[nt >> 1][(nt & 1)*2];
            const uint32_t* blp = &blf[nt >> 1][(nt & 1)*2];
            float* d = sacc[nt];
            mma16816(d[0], d[1], d[2], d[3], ah[0], ah[1], ah[2], ah[3], bhp[0], bhp[1]);
            mma16816(d[0], d[1], d[2], d[3], ah[0], ah[1], ah[2], ah[3], blp[0], blp[1]);
            mma16816(d[0], d[1], d[2], d[3], al[0], al[1], al[2], al[3], bhp[0], bhp[1]);
        }
    }
    #pragma unroll
    for (int nt = 0; nt < 4; nt++) {
        const int colb = wn*32 + nt*8 + tq*2;
        const int r0 = wm*16 + g, r1 = r0 + 8;
        float v00 = (colb     <= r0) ? sacc[nt][0] : 0.f;
        float v01 = (colb + 1 <= r0) ? sacc[nt][1] : 0.f;
        float v10 = (colb     <= r1) ? sacc[nt][2] : 0.f;
        float v11 = (colb + 1 <= r1) ? sacc[nt][3] : 0.f;
        __nv_bfloat16 h0, l0, h1, l1;
        bsplit(v00, h0, l0); bsplit(v01, h1, l1);
        *(__nv_bfloat162*)(smem + CO_SCH + r0*144 + colb*2) = __nv_bfloat162(h0, h1);
        *(__nv_bfloat162*)(smem + CO_SCL + r0*144 + colb*2) = __nv_bfloat162(l0, l1);
        bsplit(v10, h0, l0); bsplit(v11, h1, l1);
        *(__nv_bfloat162*)(smem + CO_SCH + r1*144 + colb*2) = __nv_bfloat162(h0, h1);
        *(__nv_bfloat162*)(smem + CO_SCL + r1*144 + colb*2) = __nv_bfloat162(l0, l1);
    }
    __syncthreads();

    {
        const int d = tid >> 2, fg = (tid & 3) * 32;
        const size_t src = (size_t)blk*(F_*HD_) + d*F_ + fg;
        uint4* dh = (uint4*)(smem + CO_KH + d*272 + fg*2);
        uint4* dl = (uint4*)(smem + CO_KL + d*272 + fg*2);
        #pragma unroll
        for (int q = 0; q < 4; q++) {
            dh[q] = *(const uint4*)(STh + src + q*8);
            dl[q] = *(const uint4*)(STl + src + q*8);
        }
    }
    __syncthreads();

    float oacc[4][4];
    #pragma unroll
    for (int i = 0; i < 4; i++)
        #pragma unroll
        for (int j = 0; j < 4; j++) oacc[i][j] = 0.f;

    #pragma unroll
    for (int ks = 0; ks < 8; ks++) {
        const uint32_t koff = (uint32_t)ks*32;
        uint32_t ah[4], al[4];
        ldm_x4(aQ + koff, ah[0], ah[1], ah[2], ah[3]);
        ldm_x4(aQ + (CO_QL - CO_QH) + koff, al[0], al[1], al[2], al[3]);
        uint32_t bhf[2][4], blf[2][4];
        #pragma unroll
        for (int p = 0; p < 2; p++) {
            const uint32_t ba = bK + (uint32_t)p*16*272 + koff;
            ldm_x4(ba, bhf[p][0], bhf[p][1], bhf[p][2], bhf[p][3]);
            ldm_x4(ba + (CO_KL - CO_KH), blf[p][0], blf[p][1], blf[p][2], blf[p][3]);
        }
        #pragma unroll
        for (int nt = 0; nt < 4; nt++) {
            const uint32_t* bhp = &bhf[nt >> 1][(nt & 1)*2];
            const uint32_t* blp = &blf[nt >> 1][(nt & 1)*2];
            float* d = oacc[nt];
            mma16816(d[0], d[1], d[2], d[3], ah[0], ah[1], ah[2], ah[3], bhp[0], bhp[1]);
            mma16816(d[0], d[1], d[2], d[3], ah[0], ah[1], ah[2], ah[3], blp[0], blp[1]);
            mma16816(d[0], d[1], d[2], d[3], al[0], al[1], al[2], al[3], bhp[0], bhp[1]);
        }
    }
    {
        const uint32_t aS = sb + CO_SCH + (uint32_t)(wm*16 + (lane & 15))*144
                          + (uint32_t)(lane >> 4)*16;
        const uint32_t bV = sb + CO_VTH + (uint32_t)(wn*32 + ((lane >> 4) & 1)*8 + (lane & 7))*144
                          + (uint32_t)((lane >> 3) & 1)*16;
        #pragma unroll
        for (int ks = 0; ks < 4; ks++) {
            const uint32_t koff = (uint32_t)ks*32;
            uint32_t ah[4], al[4];
            ldm_x4(aS + koff, ah[0], ah[1], ah[2], ah[3]);
            ldm_x4(aS + (CO_SCL - CO_SCH) + koff, al[0], al[1], al[2], al[3]);
            uint32_t bhf[2][4], blf[2][4];
            #pragma unroll
            for (int p = 0; p < 2; p++) {
                const uint32_t ba = bV + (uint32_t)p*16*144 + koff;
                ldm_x4(ba, bhf[p][0], bhf[p][1], bhf[p][2], bhf[p][3]);
                ldm_x4(ba + (CO_VTL - CO_VTH), blf[p][0], blf[p][1], blf[p][2], blf[p][3]);
            }
            #pragma unroll
            for (int nt = 0; nt < 4; nt++) {
                const uint32_t* bhp = &bhf[nt >> 1][(nt & 1)*2];
                const uint32_t* blp = &blf[nt >> 1][(nt & 1)*2];
                float* d = oacc[nt];
                mma16816(d[0], d[1], d[2], d[3], ah[0], ah[1], ah[2], ah[3], bhp[0], bhp[1]);
                mma16816(d[0], d[1], d[2], d[3], ah[0], ah[1], ah[2], ah[3], blp[0], blp[1]);
                mma16816(d[0], d[1], d[2], d[3], al[0], al[1], al[2], al[3], bhp[0], bhp[1]);
            }
        }
    }

    #pragma unroll
    for (int nt = 0; nt < 4; nt++) {
        const int dcol = wn*32 + nt*8 + tq*2;
        const int r0 = wm*16 + g;
        #pragma unroll
        for (int half = 0; half < 2; half++) {
            const int r = r0 + half*8;
            const float va = oacc[nt][half*2], vb = oacc[nt][half*2+1];
            __nv_bfloat16 ha, la, hb, lb;
            bsplit(va, ha, la); bsplit(vb, hb, lb);
            const size_t oidx = ((size_t)(b*T_) + n*C_ + r)*D_ + h*HD_ + dcol;
            *(__nv_bfloat162*)(ohi + oidx) = __nv_bfloat162(ha, hb);
            *(__nv_bfloat162*)(olo + oidx) = __nv_bfloat162(la, lb);
        }
    }
}

// ---------------- launcher ----------------------------------------------------
extern "C" void kernel_launch(void* const* d_in, const int* in_sizes, int n_in,
                              void* d_out, int out_size)
{
    const float* hs   = (const float*)d_in[0];
    const float* res  = (const float*)d_in[1];
    const float* nw   = (const float*)d_in[2];
    const float* w_q  = (const float*)d_in[3];
    const float* w_k  = (const float*)d_in[4];
    const float* w_v  = (const float*)d_in[5];
    const float* w_o  = (const float*)d_in[6];
    const float* hqw  = (const float*)d_in[7];
    const float* hqb  = (const float*)d_in[8];
    const float* hkw  = (const float*)d_in[9];
    const float* hkb  = (const float*)d_in[10];
    float* out = (float*)d_out;

    float *pq, *pk, *pkv;
    __nv_bfloat16 *pxhi, *pxlo, *pohi, *polo, *pwT, *pwo;
    __nv_bfloat16 *pqfh, *pqfl, *pkfh, *pkfl, *pvh, *pvl, *pSTh, *pSTl;
    cudaGetSymbolAddress((void**)&pq,   g_q);
    cudaGetSymbolAddress((void**)&pk,   g_k);
    cudaGetSymbolAddress((void**)&pkv,  g_kv);
    cudaGetSymbolAddress((void**)&pxhi, g_xhi);
    cudaGetSymbolAddress((void**)&pxlo, g_xlo);
    cudaGetSymbolAddress((void**)&pohi, g_ohi);
    cudaGetSymbolAddress((void**)&polo, g_olo);
    cudaGetSymbolAddress((void**)&pwT,  g_wT);
    cudaGetSymbolAddress((void**)&pwo,  g_woT);
    cudaGetSymbolAddress((void**)&pqfh, g_qfh);
    cudaGetSymbolAddress((void**)&pqfl, g_qfl);
    cudaGetSymbolAddress((void**)&pkfh, g_kfh);
    cudaGetSymbolAddress((void**)&pkfl, g_kfl);
    cudaGetSymbolAddress((void**)&pvh,  g_vh);
    cudaGetSymbolAddress((void**)&pvl,  g_vl);
    cudaGetSymbolAddress((void**)&pSTh, g_STh);
    cudaGetSymbolAddress((void**)&pSTl, g_STl);

    const size_t fsmem = (128*65 + 64*64) * sizeof(float);   // 49664
    cudaFuncSetAttribute(foldsplit_kernel,
                         cudaFuncAttributeMaxDynamicSharedMemorySize, (int)fsmem);
    cudaFuncSetAttribute(gemm_qkv,
                         cudaFuncAttributeMaxDynamicSharedMemorySize, GSMEM);
    cudaFuncSetAttribute(gemm_bf16x3,
                         cudaFuncAttributeMaxDynamicSharedMemorySize, GSMEM);
    cudaFuncSetAttribute(chunk_kv_kernel,
                         cudaFuncAttributeMaxDynamicSharedMemorySize, CKV_SMEM);
    cudaFuncSetAttribute(chunk_out_kernel,
                         cudaFuncAttributeMaxDynamicSharedMemorySize, CO_SMEM);

    const size_t QKV_LO = (size_t)3*D_*D_;

    // 1) fused add + RMSNorm -> resid (2nd half of out) + split x
    addnorm_kernel<<<BT_, 256>>>(hs, res, nw, out + (size_t)BT_*D_, pxhi, pxlo);

    // 2) fold hedgehog weights into q/k projections; split v weight
    dim3 fgrid(16, 8);
    foldsplit_kernel<<<fgrid, 256, fsmem>>>(w_q, hqw, pwT, 0,    QKV_LO);
    foldsplit_kernel<<<fgrid, 256, fsmem>>>(w_k, hkw, pwT, 1024, QKV_LO);
    dim3 wgrid(32, 32);
    wsplit_kernel<<<wgrid, 256>>>(w_v, pwT, 2048, QKV_LO);

    // 3) fused QKV projection (y_q, y_k fp32; v split bf16)
    dim3 qkvgrid(24, BT_/128);
    gemm_qkv<<<qkvgrid, 256, GSMEM>>>(pxhi, pxlo, pwT, pq, pk, pvh, pvl);

    // 4) hedgehog features (bias + softmax only)
    hedgehog_kernel<<<BHT_/8, 256>>>(pq, hqb, pqfh, pqfl, 0.08838834764831845f);
    hedgehog_kernel<<<BHT_/8, 256>>>(pk, hkb, pkfh, pkfl, 1.0f);

    // 5) chunked linear attention (tensor cores)
    chunk_kv_kernel<<<NCHUNK_, 256, CKV_SMEM>>>(pkfh, pkfl, pvh, pvl, pkv);
    kv_scan_kernel<<<512, 1024>>>(pkv, pSTh, pSTl);
    chunk_out_kernel<<<NCHUNK_, 256, CO_SMEM>>>(pqfh, pqfl, pkfh, pkfl, pvh, pvl,
                                                pSTh, pSTl, pohi, polo);

    // 6) output projection
    wsplit_kernel<<<wgrid, 256>>>(w_o, pwo, 0, (size_t)D_*D_);
    gemm_bf16x3<<<dim3(8, BT_/128), 256, GSMEM>>>(pohi, polo, pwo, out);
}

// round 7
// speedup vs baseline: 2.3301x; 1.0293x over previous
#include <cuda_runtime.h>
#include <cuda_bf16.h>
#include <stdint.h>
#include <math.h>

// Problem constants
#define B_  4
#define T_  2048
#define D_  1024
#define H_  16
#define HD_ 64
#define F_  128
#define C_  64
#define N_  32
#define BT_ (B_*T_)        // 8192
#define BHT_ (B_*H_*T_)    // 131072
#define NCHUNK_ (B_*H_*N_) // 2048

// ---------------- scratch (device globals) ----------------------------------
__device__ float g_kv[NCHUNK_*F_*HD_];          // kv^T per chunk: [d][f]
__device__ __nv_bfloat16 g_STh[NCHUNK_*F_*HD_];
__device__ __nv_bfloat16 g_STl[NCHUNK_*F_*HD_];
__device__ __nv_bfloat16 g_qfh[BHT_*F_];
__device__ __nv_bfloat16 g_qfl[BHT_*F_];
__device__ __nv_bfloat16 g_kfh[BHT_*F_];
__device__ __nv_bfloat16 g_kfl[BHT_*F_];
__device__ __nv_bfloat16 g_vh [BT_*D_];
__device__ __nv_bfloat16 g_vl [BT_*D_];
__device__ __nv_bfloat16 g_xhi[BT_*D_];
__device__ __nv_bfloat16 g_xlo[BT_*D_];
__device__ __nv_bfloat16 g_ohi[BT_*D_];
__device__ __nv_bfloat16 g_olo[BT_*D_];
__device__ __nv_bfloat16 g_wT [2*3*D_*D_];      // fused qkv weights (hi, lo at +3DD)
__device__ __nv_bfloat16 g_woT[2*D_*D_];        // o weights (hi, lo at +DD)

// ---------------- PTX helpers ------------------------------------------------
__device__ __forceinline__ uint32_t smem_u32(const void* p) {
    uint32_t a;
    asm("{ .reg .u64 t; cvta.to.shared.u64 t, %1; cvt.u32.u64 %0, t; }" : "=r"(a) : "l"(p));
    return a;
}
__device__ __forceinline__ void cp_async16(uint32_t saddr, const void* gaddr) {
    asm volatile("cp.async.cg.shared.global [%0], [%1], 16;" :: "r"(saddr), "l"(gaddr));
}
__device__ __forceinline__ void cp_commit() {
    asm volatile("cp.async.commit_group;" ::: "memory");
}
template <int NN>
__device__ __forceinline__ void cp_wait() {
    asm volatile("cp.async.wait_group %0;" :: "n"(NN) : "memory");
}
__device__ __forceinline__ void ldm_x4(uint32_t addr, uint32_t& r0, uint32_t& r1,
                                       uint32_t& r2, uint32_t& r3) {
    asm volatile("ldmatrix.sync.aligned.m8n8.x4.shared.b16 {%0,%1,%2,%3}, [%4];"
                 : "=r"(r0), "=r"(r1), "=r"(r2), "=r"(r3) : "r"(addr));
}
__device__ __forceinline__ void mma16816(float& d0, float& d1, float& d2, float& d3,
                                         uint32_t a0, uint32_t a1, uint32_t a2, uint32_t a3,
                                         uint32_t b0, uint32_t b1) {
    asm volatile("mma.sync.aligned.m16n8k16.row.col.f32.bf16.bf16.f32 "
                 "{%0,%1,%2,%3}, {%4,%5,%6,%7}, {%8,%9}, {%0,%1,%2,%3};"
                 : "+f"(d0), "+f"(d1), "+f"(d2), "+f"(d3)
                 : "r"(a0), "r"(a1), "r"(a2), "r"(a3), "r"(b0), "r"(b1));
}
__device__ __forceinline__ void bsplit(float v, __nv_bfloat16& h, __nv_bfloat16& l) {
    h = __float2bfloat16_rn(v);
    l = __float2bfloat16_rn(v - __bfloat162float(h));
}

// ---------------- weight prep: fold/transpose/split, z-dispatched ------------
// z=0: Wq·hhq^T -> wT rows [0,1024)    z=1: Wk·hhk^T -> wT rows [1024,2048)
// z=2: Wv^T     -> wT rows [2048,3072) z=3: Wo^T     -> woT rows [0,1024)
__global__ __launch_bounds__(256)
void weightprep_kernel(const float* __restrict__ wq, const float* __restrict__ wk,
                       const float* __restrict__ wv, const float* __restrict__ wo,
                       const float* __restrict__ hqw, const float* __restrict__ hkw,
                       __nv_bfloat16* __restrict__ wT, __nv_bfloat16* __restrict__ woT)
{
    extern __shared__ float fsm[];
    float* Wb = fsm;               // [128][65]
    float* hh = fsm + 128*65;      // [64][64]
    const int z = blockIdx.z;
    const float* W   = (z==0) ? wq : (z==1) ? wk : (z==2) ? wv : wo;
    const float* hhw = (z==0) ? hqw : (z==1) ? hkw : nullptr;
    __nv_bfloat16* dst = (z==3) ? woT : wT;
    const int rowOff = (z==0) ? 0 : (z==1) ? 1024 : (z==2) ? 2048 : 0;
    const size_t loOff = (z==3) ? (size_t)D_*D_ : (size_t)3*D_*D_;

    const int h = blockIdx.x, kb = blockIdx.y;
    const int tid = threadIdx.x;
    for (int i = tid; i < 8192; i += 256) {
        int r = i >> 6, d = i & 63;
        Wb[r*65 + d] = W[(size_t)(kb*128 + r)*D_ + h*64 + d];
    }
    if (hhw)
        for (int i = tid; i < 4096; i += 256) hh[i] = hhw[i];
    __syncthreads();

    const int kk = tid & 127;
    const int e0 = (tid >> 7) * 32;
    float acc[32];
    if (hhw) {
        #pragma unroll
        for (int e = 0; e < 32; e++) acc[e] = 0.f;
        for (int d = 0; d < 64; d++) {
            float wv2 = Wb[kk*65 + d];
            #pragma unroll
            for (int e = 0; e < 32; e++)
                acc[e] = fmaf(wv2, hh[(e0+e)*64 + d], acc[e]);
        }
    } else {
        #pragma unroll
        for (int e = 0; e < 32; e++) acc[e] = Wb[kk*65 + e0 + e];
    }
    #pragma unroll
    for (int e = 0; e < 32; e++) {
        __nv_bfloat16 hi, lo;
        bsplit(acc[e], hi, lo);
        size_t idx = (size_t)(rowOff + h*64 + e0 + e)*D_ + kb*128 + kk;
        dst[idx] = hi;
        dst[idx + loOff] = lo;
    }
}

// ---------------- fused add + RMSNorm -> resid + bf16 split x ---------------
__global__ __launch_bounds__(256)
void addnorm_kernel(const float* __restrict__ hs, const float* __restrict__ res,
                    const float* __restrict__ w, float* __restrict__ resid_out,
                    __nv_bfloat16* __restrict__ xhi, __nv_bfloat16* __restrict__ xlo,
                    int rowOff)
{
    __shared__ float red[8];
    const int row = blockIdx.x + rowOff;
    const int t = threadIdx.x;
    const float4* h4 = (const float4*)(hs  + (size_t)row*D_);
    const float4* r4 = (const float4*)(res + (size_t)row*D_);
    float4*      ro4 = (float4*)(resid_out + (size_t)row*D_);

    float4 h = h4[t], r = r4[t];
    float4 s = make_float4(h.x+r.x, h.y+r.y, h.z+r.z, h.w+r.w);
    ro4[t] = s;
    float ss = s.x*s.x + s.y*s.y + s.z*s.z + s.w*s.w;
    #pragma unroll
    for (int o = 16; o; o >>= 1) ss += __shfl_xor_sync(0xffffffffu, ss, o);
    if ((t & 31) == 0) red[t >> 5] = ss;
    __syncthreads();
    float tot = 0.f;
    #pragma unroll
    for (int i = 0; i < 8; i++) tot += red[i];
    float rstd = rsqrtf(tot * (1.0f/1024.0f) + 1e-5f);
    float4 wv = ((const float4*)w)[t];
    float v[4] = { s.x*rstd*wv.x, s.y*rstd*wv.y, s.z*rstd*wv.z, s.w*rstd*wv.w };
    __nv_bfloat16 hi[4], lo[4];
    #pragma unroll
    for (int i = 0; i < 4; i++) bsplit(v[i], hi[i], lo[i]);
    size_t idx = (size_t)row*D_ + t*4;
    *(__nv_bfloat162*)(xhi+idx)   = __nv_bfloat162(hi[0], hi[1]);
    *(__nv_bfloat162*)(xhi+idx+2) = __nv_bfloat162(hi[2], hi[3]);
    *(__nv_bfloat162*)(xlo+idx)   = __nv_bfloat162(lo[0], lo[1]);
    *(__nv_bfloat162*)(xlo+idx+2) = __nv_bfloat162(lo[2], lo[3]);
}

// ---------------- bf16x3 fused QKV GEMM + hedgehog epilogue -------------------
// bx 0..7: q -> hedgehog features; bx 8..15: k -> features; bx 16..23: v split.
#define PITCH 40
#define MAT_BYTES (128*PITCH*2)
#define STAGE_BYTES (4*MAT_BYTES)
#define GSMEM (2*STAGE_BYTES)

__global__ __launch_bounds__(256, 2)
void gemm_qkv(const __nv_bfloat16* __restrict__ Ahi, const __nv_bfloat16* __restrict__ Alo,
              const __nv_bfloat16* __restrict__ BT,
              const float* __restrict__ biasq, const float* __restrict__ biask,
              __nv_bfloat16* __restrict__ Qfh, __nv_bfloat16* __restrict__ Qfl,
              __nv_bfloat16* __restrict__ Kfh, __nv_bfloat16* __restrict__ Kfl,
              __nv_bfloat16* __restrict__ Vh,  __nv_bfloat16* __restrict__ Vl)
{
    extern __shared__ __align__(16) char smem[];
    const uint32_t sbase = smem_u32(smem);
    const int tid = threadIdx.x, wid = tid >> 5, lane = tid & 31;
    const int bx = blockIdx.x, by = blockIdx.y;
    const int wm = wid & 1, wn = wid >> 1;
    const __nv_bfloat16* Bhi = BT;
    const __nv_bfloat16* Blo = BT + (size_t)3*D_*D_;

    const int lrow = tid >> 1;
    const int lc   = (tid & 1) * 2;
    const size_t gA = (size_t)(by*128 + lrow) * D_;
    const size_t gB = (size_t)(bx*128 + lrow) * D_;
    const uint32_t sRow = (uint32_t)lrow * 80;

    float acc[4][4][4];
    #pragma unroll
    for (int i = 0; i < 4; i++)
        #pragma unroll
        for (int j = 0; j < 4; j++)
            #pragma unroll
            for (int l = 0; l < 4; l++) acc[i][j][l] = 0.f;

    #define PREFETCH(kt, buf) do {                                              \
        const int k0 = (kt) * 32;                                               \
        const uint32_t b0 = sbase + (uint32_t)(buf) * STAGE_BYTES;              \
        _Pragma("unroll")                                                       \
        for (int u = 0; u < 2; u++) {                                           \
            const int c = lc + u;                                               \
            const uint32_t so = sRow + (uint32_t)c * 16;                        \
            const size_t go = (size_t)k0 + c * 8;                               \
            cp_async16(b0 + 0*MAT_BYTES + so, Ahi + gA + go);                   \
            cp_async16(b0 + 1*MAT_BYTES + so, Alo + gA + go);                   \
            cp_async16(b0 + 2*MAT_BYTES + so, Bhi + gB + go);                   \
            cp_async16(b0 + 3*MAT_BYTES + so, Blo + gB + go);                   \
        }                                                                       \
        cp_commit();                                                            \
    } while (0)

    PREFETCH(0, 0);
    PREFETCH(1, 1);

    const uint32_t aRow = (uint32_t)(wm*64 + (lane & 15)) * 80 + (uint32_t)(lane >> 4) * 16;
    const uint32_t bRow = (uint32_t)(wn*32 + ((lane >> 4) & 1)*8 + (lane & 7)) * 80
                        + (uint32_t)((lane >> 3) & 1) * 16;

    const int TILES = D_ / 32;
    #pragma unroll 1
    for (int kt = 0; kt < TILES; kt++) {
        const int cur = kt & 1;
        if (kt == TILES - 1) cp_wait<0>(); else cp_wait<1>();
        __syncthreads();
        const uint32_t sb = sbase + (uint32_t)cur * STAGE_BYTES;

        #pragma unroll
        for (int kk = 0; kk < 2; kk++) {
            const uint32_t koff = (uint32_t)kk * 32;
            uint32_t bh[2][4], bl[2][4];
            #pragma unroll
            for (int nt2 = 0; nt2 < 2; nt2++) {
                const uint32_t ba = bRow + (uint32_t)nt2 * 16 * 80 + koff;
                ldm_x4(sb + 2*MAT_BYTES + ba, bh[nt2][0], bh[nt2][1], bh[nt2][2], bh[nt2][3]);
                ldm_x4(sb + 3*MAT_BYTES + ba, bl[nt2][0], bl[nt2][1], bl[nt2][2], bl[nt2][3]);
            }
            #pragma unroll
            for (int mt = 0; mt < 4; mt++) {
                const uint32_t aa = aRow + (uint32_t)mt * 16 * 80 + koff;
                uint32_t ah[4], al[4];
                ldm_x4(sb + 0*MAT_BYTES + aa, ah[0], ah[1], ah[2], ah[3]);
                ldm_x4(sb + 1*MAT_BYTES + aa, al[0], al[1], al[2], al[3]);
                #pragma unroll
                for (int nt = 0; nt < 4; nt++) {
                    const uint32_t* bhp = &bh[nt >> 1][(nt & 1) * 2];
                    const uint32_t* blp = &bl[nt >> 1][(nt & 1) * 2];
                    float* d = acc[mt][nt];
                    mma16816(d[0], d[1], d[2], d[3], ah[0], ah[1], ah[2], ah[3], bhp[0], bhp[1]);
                    mma16816(d[0], d[1], d[2], d[3], ah[0], ah[1], ah[2], ah[3], blp[0], blp[1]);
                    mma16816(d[0], d[1], d[2], d[3], al[0], al[1], al[2], al[3], bhp[0], bhp[1]);
                }
            }
        }
        __syncthreads();
        if (kt + 2 < TILES) PREFETCH(kt + 2, cur);
    }
    #undef PREFETCH

    const int g = lane >> 2, tq = lane & 3;

    if (bx < 16) {
        // -------- hedgehog epilogue: bias + softmax([y,-y]) -> bf16 hi/lo ----
        const int isQ = (bx < 8);
        const float* bias = isQ ? biasq : biask;
        const float scale = isQ ? 0.08838834764831845f : 1.0f;
        __nv_bfloat16* fh = isQ ? Qfh : Kfh;
        __nv_bfloat16* fl = isQ ? Qfl : Kfl;
        float* smax = (float*)smem;          // [4][128]
        float* ssum = smax + 512;            // [4][128]
        // mainloop smem reads are done (sync at loop end); safe to reuse
        // 1) bias add + per-warp row max of |y|
        #pragma unroll
        for (int mt = 0; mt < 4; mt++) {
            float pm0 = 0.f, pm1 = 0.f;
            #pragma unroll
            for (int nt = 0; nt < 4; nt++) {
                const int cb = (wn*32 + nt*8 + tq*2) & 63;
                const float b0 = bias[cb], b1 = bias[cb + 1];
                float* d = acc[mt][nt];
                d[0] += b0; d[1] += b1; d[2] += b0; d[3] += b1;
                pm0 = fmaxf(pm0, fmaxf(fabsf(d[0]), fabsf(d[1])));
                pm1 = fmaxf(pm1, fmaxf(fabsf(d[2]), fabsf(d[3])));
            }
            pm0 = fmaxf(pm0, __shfl_xor_sync(0xffffffffu, pm0, 1));
            pm0 = fmaxf(pm0, __shfl_xor_sync(0xffffffffu, pm0, 2));
            pm1 = fmaxf(pm1, __shfl_xor_sync(0xffffffffu, pm1, 1));
            pm1 = fmaxf(pm1, __shfl_xor_sync(0xffffffffu, pm1, 2));
            if (tq == 0) {
                smax[wn*128 + wm*64 + mt*16 + g]     = pm0;
                smax[wn*128 + wm*64 + mt*16 + g + 8] = pm1;
            }
        }
        __syncthreads();
        // 2) full row max per head (warp pair wn ^ 1), then partial sums
        float mrow[4][2];
        #pragma unroll
        for (int mt = 0; mt < 4; mt++) {
            #pragma unroll
            for (int half = 0; half < 2; half++) {
                const int r = wm*64 + mt*16 + g + half*8;
                mrow[mt][half] = fmaxf(smax[wn*128 + r], smax[(wn^1)*128 + r]);
            }
        }
        #pragma unroll
        for (int mt = 0; mt < 4; mt++) {
            float s0 = 0.f, s1 = 0.f;
            #pragma unroll
            for (int nt = 0; nt < 4; nt++) {
                const float* d = acc[mt][nt];
                s0 += __expf(d[0]-mrow[mt][0]) + __expf(-d[0]-mrow[mt][0])
                    + __expf(d[1]-mrow[mt][0]) + __expf(-d[1]-mrow[mt][0]);
                s1 += __expf(d[2]-mrow[mt][1]) + __expf(-d[2]-mrow[mt][1])
                    + __expf(d[3]-mrow[mt][1]) + __expf(-d[3]-mrow[mt][1]);
            }
            s0 += __shfl_xor_sync(0xffffffffu, s0, 1);
            s0 += __shfl_xor_sync(0xffffffffu, s0, 2);
            s1 += __shfl_xor_sync(0xffffffffu, s1, 1);
            s1 += __shfl_xor_sync(0xffffffffu, s1, 2);
            if (tq == 0) {
                ssum[wn*128 + wm*64 + mt*16 + g]     = s0;
                ssum[wn*128 + wm*64 + mt*16 + g + 8] = s1;
            }
        }
        __syncthreads();
        // 3) write features
        const int hloc = (bx & 7)*2 + (wn >> 1);
        #pragma unroll
        for (int mt = 0; mt < 4; mt++) {
            #pragma unroll
            for (int half = 0; half < 2; half++) {
                const int r = wm*64 + mt*16 + g + half*8;
                const float z = ssum[wn*128 + r] + ssum[(wn^1)*128 + r];
                const float inv = scale / z;
                const float mm = mrow[mt][half];
                const int rowg = by*128 + r;
                const int bb = rowg >> 11, tt = rowg & 2047;
                const size_t base = ((size_t)(bb*H_ + hloc)*T_ + tt)*F_;
                #pragma unroll
                for (int nt = 0; nt < 4; nt++) {
                    const int f = (wn*32 + nt*8 + tq*2) & 63;
                    const float y0 = acc[mt][nt][half*2], y1 = acc[mt][nt][half*2+1];
                    const float p0 = __expf(y0 - mm)*inv,  p1 = __expf(y1 - mm)*inv;
                    const float n0 = __expf(-y0 - mm)*inv, n1 = __expf(-y1 - mm)*inv;
                    __nv_bfloat16 h0, l0, h1, l1;
                    bsplit(p0, h0, l0); bsplit(p1, h1, l1);
                    *(__nv_bfloat162*)(fh + base + f)      = __nv_bfloat162(h0, h1);
                    *(__nv_bfloat162*)(fl + base + f)      = __nv_bfloat162(l0, l1);
                    bsplit(n0, h0, l0); bsplit(n1, h1, l1);
                    *(__nv_bfloat162*)(fh + base + 64 + f) = __nv_bfloat162(h0, h1);
                    *(__nv_bfloat162*)(fl + base + 64 + f) = __nv_bfloat162(l0, l1);
                }
            }
        }
    } else {
        // -------- v epilogue: bf16 hi/lo split ----
        const int colbase = (bx - 16)*128;
        #pragma unroll
        for (int mt = 0; mt < 4; mt++) {
            const int r0 = by*128 + wm*64 + mt*16 + g;
            #pragma unroll
            for (int nt = 0; nt < 4; nt++) {
                const int col = colbase + wn*32 + nt*8 + tq*2;
                float* d = acc[mt][nt];
                __nv_bfloat16 h0, l0, h1, l1;
                bsplit(d[0], h0, l0); bsplit(d[1], h1, l1);
                *(__nv_bfloat162*)(Vh + (size_t)r0*D_ + col) = __nv_bfloat162(h0, h1);
                *(__nv_bfloat162*)(Vl + (size_t)r0*D_ + col) = __nv_bfloat162(l0, l1);
                bsplit(d[2], h0, l0); bsplit(d[3], h1, l1);
                *(__nv_bfloat162*)(Vh + (size_t)(r0+8)*D_ + col) = __nv_bfloat162(h0, h1);
                *(__nv_bfloat162*)(Vl + (size_t)(r0+8)*D_ + col) = __nv_bfloat162(l0, l1);
            }
        }
    }
}

// ---------------- bf16x3 GEMM (fp32 out; o-projection) ------------------------
__global__ __launch_bounds__(256, 2)
void gemm_bf16x3(const __nv_bfloat16* __restrict__ Ahi, const __nv_bfloat16* __restrict__ Alo,
                 const __nv_bfloat16* __restrict__ BT, float* __restrict__ Cout)
{
    extern __shared__ __align__(16) char smem[];
    const uint32_t sbase = smem_u32(smem);
    const int tid = threadIdx.x, wid = tid >> 5, lane = tid & 31;
    const int bx = blockIdx.x, by = blockIdx.y;
    const int wm = wid & 1, wn = wid >> 1;
    const __nv_bfloat16* Bhi = BT;
    const __nv_bfloat16* Blo = BT + (size_t)D_*D_;

    const int lrow = tid >> 1;
    const int lc   = (tid & 1) * 2;
    const size_t gA = (size_t)(by*128 + lrow) * D_;
    const size_t gB = (size_t)(bx*128 + lrow) * D_;
    const uint32_t sRow = (uint32_t)lrow * 80;

    float acc[4][4][4];
    #pragma unroll
    for (int i = 0; i < 4; i++)
        #pragma unroll
        for (int j = 0; j < 4; j++)
            #pragma unroll
            for (int l = 0; l < 4; l++) acc[i][j][l] = 0.f;

    #define PREFETCH(kt, buf) do {                                              \
        const int k0 = (kt) * 32;                                               \
        const uint32_t b0 = sbase + (uint32_t)(buf) * STAGE_BYTES;              \
        _Pragma("unroll")                                                       \
        for (int u = 0; u < 2; u++) {                                           \
            const int c = lc + u;                                               \
            const uint32_t so = sRow + (uint32_t)c * 16;                        \
            const size_t go = (size_t)k0 + c * 8;                               \
            cp_async16(b0 + 0*MAT_BYTES + so, Ahi + gA + go);                   \
            cp_async16(b0 + 1*MAT_BYTES + so, Alo + gA + go);                   \
            cp_async16(b0 + 2*MAT_BYTES + so, Bhi + gB + go);                   \
            cp_async16(b0 + 3*MAT_BYTES + so, Blo + gB + go);                   \
        }                                                                       \
        cp_commit();                                                            \
    } while (0)

    PREFETCH(0, 0);
    PREFETCH(1, 1);

    const uint32_t aRow = (uint32_t)(wm*64 + (lane & 15)) * 80 + (uint32_t)(lane >> 4) * 16;
    const uint32_t bRow = (uint32_t)(wn*32 + ((lane >> 4) & 1)*8 + (lane & 7)) * 80
                        + (uint32_t)((lane >> 3) & 1) * 16;

    const int TILES = D_ / 32;
    #pragma unroll 1
    for (int kt = 0; kt < TILES; kt++) {
        const int cur = kt & 1;
        if (kt == TILES - 1) cp_wait<0>(); else cp_wait<1>();
        __syncthreads();
        const uint32_t sb = sbase + (uint32_t)cur * STAGE_BYTES;

        #pragma unroll
        for (int kk = 0; kk < 2; kk++) {
            const uint32_t koff = (uint32_t)kk * 32;
            uint32_t bh[2][4], bl[2][4];
            #pragma unroll
            for (int nt2 = 0; nt2 < 2; nt2++) {
                const uint32_t ba = bRow + (uint32_t)nt2 * 16 * 80 + koff;
                ldm_x4(sb + 2*MAT_BYTES + ba, bh[nt2][0], bh[nt2][1], bh[nt2][2], bh[nt2][3]);
                ldm_x4(sb + 3*MAT_BYTES + ba, bl[nt2][0], bl[nt2][1], bl[nt2][2], bl[nt2][3]);
            }
            #pragma unroll
            for (int mt = 0; mt < 4; mt++) {
                const uint32_t aa = aRow + (uint32_t)mt * 16 * 80 + koff;
                uint32_t ah[4], al[4];
                ldm_x4(sb + 0*MAT_BYTES + aa, ah[0], ah[1], ah[2], ah[3]);
                ldm_x4(sb + 1*MAT_BYTES + aa, al[0], al[1], al[2], al[3]);
                #pragma unroll
                for (int nt = 0; nt < 4; nt++) {
                    const uint32_t* bhp = &bh[nt >> 1][(nt & 1) * 2];
                    const uint32_t* blp = &bl[nt >> 1][(nt & 1) * 2];
                    float* d = acc[mt][nt];
                    mma16816(d[0], d[1], d[2], d[3], ah[0], ah[1], ah[2], ah[3], bhp[0], bhp[1]);
                    mma16816(d[0], d[1], d[2], d[3], ah[0], ah[1], ah[2], ah[3], blp[0], blp[1]);
                    mma16816(d[0], d[1], d[2], d[3], al[0], al[1], al[2], al[3], bhp[0], bhp[1]);
                }
            }
        }
        __syncthreads();
        if (kt + 2 < TILES) PREFETCH(kt + 2, cur);
    }
    #undef PREFETCH

    const int g = lane >> 2, tq = lane & 3;
    #pragma unroll
    for (int mt = 0; mt < 4; mt++) {
        const int r0 = by*128 + wm*64 + mt*16 + g;
        #pragma unroll
        for (int nt = 0; nt < 4; nt++) {
            const int col = bx*128 + wn*32 + nt*8 + tq*2;
            float* d = acc[mt][nt];
            *(float2*)(Cout + (size_t)r0*D_ + col)     = make_float2(d[0], d[1]);
            *(float2*)(Cout + (size_t)(r0+8)*D_ + col) = make_float2(d[2], d[3]);
        }
    }
}

// ---------------- phase A: kv^T[d][f] = sum_c v[c,d] k[c,f]  (tensor core) ---
#define CKV_KTH 0u
#define CKV_KTL 18432u
#define CKV_VTH 36864u
#define CKV_VTL 46080u
#define CKV_SMEM 55296u

__global__ __launch_bounds__(256, 2)
void chunk_kv_kernel(const __nv_bfloat16* __restrict__ kfh, const __nv_bfloat16* __restrict__ kfl,
                     const __nv_bfloat16* __restrict__ vh, const __nv_bfloat16* __restrict__ vl,
                     float* __restrict__ kvT)
{
    extern __shared__ __align__(16) char smem[];
    const uint32_t sb = smem_u32(smem);
    const int blk = blockIdx.x;
    const int n = blk & 31, bh = blk >> 5;
    const int b = bh >> 4, h = bh & 15;
    const int tid = threadIdx.x, wid = tid >> 5, lane = tid & 31;

    {
        const int c = tid >> 2, fg = (tid & 3) * 32;
        const size_t src = ((size_t)bh*T_ + n*C_ + c)*F_ + fg;
        union { uint4 u; __nv_bfloat16 b[8]; } r;
        #pragma unroll
        for (int q = 0; q < 4; q++) {
            r.u = *(const uint4*)(kfh + src + q*8);
            #pragma unroll
            for (int i = 0; i < 8; i++)
                *(__nv_bfloat16*)(smem + CKV_KTH + (fg+q*8+i)*144 + c*2) = r.b[i];
            r.u = *(const uint4*)(kfl + src + q*8);
            #pragma unroll
            for (int i = 0; i < 8; i++)
                *(__nv_bfloat16*)(smem + CKV_KTL + (fg+q*8+i)*144 + c*2) = r.b[i];
        }
    }
    {
        const int c = tid >> 2, dg = (tid & 3) * 16;
        const size_t src = ((size_t)(b*T_) + n*C_ + c)*D_ + h*HD_ + dg;
        union { uint4 u; __nv_bfloat16 b[8]; } r;
        #pragma unroll
        for (int q = 0; q < 2; q++) {
            r.u = *(const uint4*)(vh + src + q*8);
            #pragma unroll
            for (int i = 0; i < 8; i++)
                *(__nv_bfloat16*)(smem + CKV_VTH + (dg+q*8+i)*144 + c*2) = r.b[i];
            r.u = *(const uint4*)(vl + src + q*8);
            #pragma unroll
            for (int i = 0; i < 8; i++)
                *(__nv_bfloat16*)(smem + CKV_VTL + (dg+q*8+i)*144 + c*2) = r.b[i];
        }
    }
    __syncthreads();

    const int wm = wid & 3, wn = wid >> 2;
    float acc[8][4];
    #pragma unroll
    for (int i = 0; i < 8; i++)
        #pragma unroll
        for (int j = 0; j < 4; j++) acc[i][j] = 0.f;

    const uint32_t aBase = sb + CKV_VTH + (uint32_t)(wm*16 + (lane & 15))*144
                         + (uint32_t)(lane >> 4)*16;
    const uint32_t bBase = sb + CKV_KTH + (uint32_t)(wn*64 + ((lane >> 4) & 1)*8 + (lane & 7))*144
                         + (uint32_t)((lane >> 3) & 1)*16;

    #pragma unroll
    for (int ks = 0; ks < 4; ks++) {
        const uint32_t koff = (uint32_t)ks*32;
        uint32_t ah[4], al[4];
        ldm_x4(aBase + koff, ah[0], ah[1], ah[2], ah[3]);
        ldm_x4(aBase + (CKV_VTL - CKV_VTH) + koff, al[0], al[1], al[2], al[3]);
        uint32_t bhf[4][4], blf[4][4];
        #pragma unroll
        for (int p = 0; p < 4; p++) {
            const uint32_t ba = bBase + (uint32_t)p*16*144 + koff;
            ldm_x4(ba, bhf[p][0], bhf[p][1], bhf[p][2], bhf[p][3]);
            ldm_x4(ba + (CKV_KTL - CKV_KTH), blf[p][0], blf[p][1], blf[p][2], blf[p][3]);
        }
        #pragma unroll
        for (int nt = 0; nt < 8; nt++) {
            const uint32_t* bhp = &bhf[nt >> 1][(nt & 1)*2];
            const uint32_t* blp = &blf[nt >> 1][(nt & 1)*2];
            float* d = acc[nt];
            mma16816(d[0], d[1], d[2], d[3], ah[0], ah[1], ah[2], ah[3], bhp[0], bhp[1]);
            mma16816(d[0], d[1], d[2], d[3], ah[0], ah[1], ah[2], ah[3], blp[0], blp[1]);
            mma16816(d[0], d[1], d[2], d[3], al[0], al[1], al[2], al[3], bhp[0], bhp[1]);
        }
    }
    const int g = lane >> 2, tq = lane & 3;
    float* out = kvT + (size_t)blk * (F_*HD_);
    #pragma unroll
    for (int nt = 0; nt < 8; nt++) {
        const int f = wn*64 + nt*8 + tq*2;
        const int d0 = wm*16 + g;
        *(float2*)(out + (size_t)d0*F_ + f)     = make_float2(acc[nt][0], acc[nt][1]);
        *(float2*)(out + (size_t)(d0+8)*F_ + f) = make_float2(acc[nt][2], acc[nt][3]);
    }
}

// ---------------- phase B: exclusive cumsum -> bf16 hi/lo --------------------
__global__ __launch_bounds__(1024)
void kv_scan_kernel(const float* __restrict__ kvT,
                    __nv_bfloat16* __restrict__ STh, __nv_bfloat16* __restrict__ STl)
{
    const int blk = blockIdx.x;
    const int bh = blk >> 3, seg = blk & 7;
    const int e = seg*1024 + threadIdx.x;
    size_t base = (size_t)bh * N_ * (F_*HD_) + e;
    float acc = 0.f;
    for (int n = 0; n < N_; n++) {
        size_t idx = base + (size_t)n * (F_*HD_);
        __nv_bfloat16 hv, lv;
        bsplit(acc, hv, lv);
        STh[idx] = hv;
        STl[idx] = lv;
        acc += kvT[idx];
    }
}

// ---------------- phase C: out = q@S_excl + tril(q@k^T)@v  (tensor core) -----
#define CO_QH 0u
#define CO_QL 17408u
#define CO_KH 34816u
#define CO_KL 52224u
#define CO_VTH 69632u
#define CO_VTL 78848u
#define CO_SCH 88064u
#define CO_SCL 97280u
#define CO_SMEM 106496u

__global__ __launch_bounds__(256, 1)
void chunk_out_kernel(const __nv_bfloat16* __restrict__ qfh, const __nv_bfloat16* __restrict__ qfl,
                      const __nv_bfloat16* __restrict__ kfh, const __nv_bfloat16* __restrict__ kfl,
                      const __nv_bfloat16* __restrict__ vh,  const __nv_bfloat16* __restrict__ vl,
                      const __nv_bfloat16* __restrict__ STh, const __nv_bfloat16* __restrict__ STl,
                      __nv_bfloat16* __restrict__ ohi, __nv_bfloat16* __restrict__ olo)
{
    extern __shared__ __align__(16) char smem[];
    const uint32_t sb = smem_u32(smem);
    const int blk = blockIdx.x;
    const int n = blk & 31, bh = blk >> 5;
    const int b = bh >> 4, h = bh & 15;
    const int tid = threadIdx.x, wid = tid >> 5, lane = tid & 31;

    {
        const int c = tid >> 2, fg = (tid & 3) * 32;
        const size_t src = ((size_t)bh*T_ + n*C_ + c)*F_ + fg;
        uint4* dq  = (uint4*)(smem + CO_QH + c*272 + fg*2);
        uint4* dql = (uint4*)(smem + CO_QL + c*272 + fg*2);
        uint4* dk  = (uint4*)(smem + CO_KH + c*272 + fg*2);
        uint4* dkl = (uint4*)(smem + CO_KL + c*272 + fg*2);
        #pragma unroll
        for (int q = 0; q < 4; q++) {
            dq [q] = *(const uint4*)(qfh + src + q*8);
            dql[q] = *(const uint4*)(qfl + src + q*8);
            dk [q] = *(const uint4*)(kfh + src + q*8);
            dkl[q] = *(const uint4*)(kfl + src + q*8);
        }
    }
    {
        const int c = tid >> 2, dg = (tid & 3) * 16;
        const size_t src = ((size_t)(b*T_) + n*C_ + c)*D_ + h*HD_ + dg;
        union { uint4 u; __nv_bfloat16 bb[8]; } r;
        #pragma unroll
        for (int q = 0; q < 2; q++) {
            r.u = *(const uint4*)(vh + src + q*8);
            #pragma unroll
            for (int i = 0; i < 8; i++)
                *(__nv_bfloat16*)(smem + CO_VTH + (dg+q*8+i)*144 + c*2) = r.bb[i];
            r.u = *(const uint4*)(vl + src + q*8);
            #pragma unroll
            for (int i = 0; i < 8; i++)
                *(__nv_bfloat16*)(smem + CO_VTL + (dg+q*8+i)*144 + c*2) = r.bb[i];
        }
    }
    __syncthreads();

    const int wm = wid & 3, wn = wid >> 2;
    const int g = lane >> 2, tq = lane & 3;

    const uint32_t aQ = sb + CO_QH + (uint32_t)(wm*16 + (lane & 15))*272 + (uint32_t)(lane >> 4)*16;
    const uint32_t bK = sb + CO_KH + (uint32_t)(wn*32 + ((lane >> 4) & 1)*8 + (lane & 7))*272
                      + (uint32_t)((lane >> 3) & 1)*16;

    float sacc[4][4];
    #pragma unroll
    for (int i = 0; i < 4; i++)
        #pragma unroll
        for (int j = 0; j < 4; j++) sacc[i][j] = 0.f;

    #pragma unroll
    for (int ks = 0; ks < 8; ks++) {
        const uint32_t koff = (uint32_t)ks*32;
        uint32_t ah[4], al[4];
        ldm_x4(aQ + koff, ah[0], ah[1], ah[2], ah[3]);
        ldm_x4(aQ + (CO_QL - CO_QH) + koff, al[0], al[1], al[2], al[3]);
        uint32_t bhf[2][4], blf[2][4];
        #pragma unroll
        for (int p = 0; p < 2; p++) {
            const uint32_t ba = bK + (uint32_t)p*16*272 + koff;
            ldm_x4(ba, bhf[p][0], bhf[p][1], bhf[p][2], bhf[p][3]);
            ldm_x4(ba + (CO_KL - CO_KH), blf[p][0], blf[p][1], blf[p][2], blf[p][3]);
        }
        #pragma unroll
        for (int nt = 0; nt < 4; nt++) {
            const uint32_t* bhp = &bhf[nt >> 1][(nt & 1)*2];
            const uint32_t* blp = &blf[nt >> 1][(nt & 1)*2];
            float* d = sacc[nt];
            mma16816(d[0], d[1], d[2], d[3], ah[0], ah[1], ah[2], ah[3], bhp[0], bhp[1]);
            mma16816(d[0], d[1], d[2], d[3], ah[0], ah[1], ah[2], ah[3], blp[0], blp[1]);
            mma16816(d[0], d[1], d[2], d[3], al[0], al[1], al[2], al[3], bhp[0], bhp[1]);
        }
    }
    #pragma unroll
    for (int nt = 0; nt < 4; nt++) {
        const int colb = wn*32 + nt*8 + tq*2;
        const int r0 = wm*16 + g, r1 = r0 + 8;
        float v00 = (colb     <= r0) ? sacc[nt][0] : 0.f;
        float v01 = (colb + 1 <= r0) ? sacc[nt][1] : 0.f;
        float v10 = (colb     <= r1) ? sacc[nt][2] : 0.f;
        float v11 = (colb + 1 <= r1) ? sacc[nt][3] : 0.f;
        __nv_bfloat16 h0, l0, h1, l1;
        bsplit(v00, h0, l0); bsplit(v01, h1, l1);
        *(__nv_bfloat162*)(smem + CO_SCH + r0*144 + colb*2) = __nv_bfloat162(h0, h1);
        *(__nv_bfloat162*)(smem + CO_SCL + r0*144 + colb*2) = __nv_bfloat162(l0, l1);
        bsplit(v10, h0, l0); bsplit(v11, h1, l1);
        *(__nv_bfloat162*)(smem + CO_SCH + r1*144 + colb*2) = __nv_bfloat162(h0, h1);
        *(__nv_bfloat162*)(smem + CO_SCL + r1*144 + colb*2) = __nv_bfloat162(l0, l1);
    }
    __syncthreads();

    {
        const int d = tid >> 2, fg = (tid & 3) * 32;
        const size_t src = (size_t)blk*(F_*HD_) + d*F_ + fg;
        uint4* dh = (uint4*)(smem + CO_KH + d*272 + fg*2);
        uint4* dl = (uint4*)(smem + CO_KL + d*272 + fg*2);
        #pragma unroll
        for (int q = 0; q < 4; q++) {
            dh[q] = *(const uint4*)(STh + src + q*8);
            dl[q] = *(const uint4*)(STl + src + q*8);
        }
    }
    __syncthreads();

    float oacc[4][4];
    #pragma unroll
    for (int i = 0; i < 4; i++)
        #pragma unroll
        for (int j = 0; j < 4; j++) oacc[i][j] = 0.f;

    #pragma unroll
    for (int ks = 0; ks < 8; ks++) {
        const uint32_t koff = (uint32_t)ks*32;
        uint32_t ah[4], al[4];
        ldm_x4(aQ + koff, ah[0], ah[1], ah[2], ah[3]);
        ldm_x4(aQ + (CO_QL - CO_QH) + koff, al[0], al[1], al[2], al[3]);
        uint32_t bhf[2][4], blf[2][4];
        #pragma unroll
        for (int p = 0; p < 2; p++) {
            const uint32_t ba = bK + (uint32_t)p*16*272 + koff;
            ldm_x4(ba, bhf[p][0], bhf[p][1], bhf[p][2], bhf[p][3]);
            ldm_x4(ba + (CO_KL - CO_KH), blf[p][0], blf[p][1], blf[p][2], blf[p][3]);
        }
        #pragma unroll
        for (int nt = 0; nt < 4; nt++) {
            const uint32_t* bhp = &bhf[nt >> 1][(nt & 1)*2];
            const uint32_t* blp = &blf[nt >> 1][(nt & 1)*2];
            float* d = oacc[nt];
            mma16816(d[0], d[1], d[2], d[3], ah[0], ah[1], ah[2], ah[3], bhp[0], bhp[1]);
            mma16816(d[0], d[1], d[2], d[3], ah[0], ah[1], ah[2], ah[3], blp[0], blp[1]);
            mma16816(d[0], d[1], d[2], d[3], al[0], al[1], al[2], al[3], bhp[0], bhp[1]);
        }
    }
    {
        const uint32_t aS = sb + CO_SCH + (uint32_t)(wm*16 + (lane & 15))*144
                          + (uint32_t)(lane >> 4)*16;
        const uint32_t bV = sb + CO_VTH + (uint32_t)(wn*32 + ((lane >> 4) & 1)*8 + (lane & 7))*144
                          + (uint32_t)((lane >> 3) & 1)*16;
        #pragma unroll
        for (int ks = 0; ks < 4; ks++) {
            const uint32_t koff = (uint32_t)ks*32;
            uint32_t ah[4], al[4];
            ldm_x4(aS + koff, ah[0], ah[1], ah[2], ah[3]);
            ldm_x4(aS + (CO_SCL - CO_SCH) + koff, al[0], al[1], al[2], al[3]);
            uint32_t bhf[2][4], blf[2][4];
            #pragma unroll
            for (int p = 0; p < 2; p++) {
                const uint32_t ba = bV + (uint32_t)p*16*144 + koff;
                ldm_x4(ba, bhf[p][0], bhf[p][1], bhf[p][2], bhf[p][3]);
                ldm_x4(ba + (CO_VTL - CO_VTH), blf[p][0], blf[p][1], blf[p][2], blf[p][3]);
            }
            #pragma unroll
            for (int nt = 0; nt < 4; nt++) {
                const uint32_t* bhp = &bhf[nt >> 1][(nt & 1)*2];
                const uint32_t* blp = &blf[nt >> 1][(nt & 1)*2];
                float* d = oacc[nt];
                mma16816(d[0], d[1], d[2], d[3], ah[0], ah[1], ah[2], ah[3], bhp[0], bhp[1]);
                mma16816(d[0], d[1], d[2], d[3], ah[0], ah[1], ah[2], ah[3], blp[0], blp[1]);
                mma16816(d[0], d[1], d[2], d[3], al[0], al[1], al[2], al[3], bhp[0], bhp[1]);
            }
        }
    }

    #pragma unroll
    for (int nt = 0; nt < 4; nt++) {
        const int dcol = wn*32 + nt*8 + tq*2;
        const int r0 = wm*16 + g;
        #pragma unroll
        for (int half = 0; half < 2; half++) {
            const int r = r0 + half*8;
            const float va = oacc[nt][half*2], vb = oacc[nt][half*2+1];
            __nv_bfloat16 ha, la, hb, lb;
            bsplit(va, ha, la); bsplit(vb, hb, lb);
            const size_t oidx = ((size_t)(b*T_) + n*C_ + r)*D_ + h*HD_ + dcol;
            *(__nv_bfloat162*)(ohi + oidx) = __nv_bfloat162(ha, hb);
            *(__nv_bfloat162*)(olo + oidx) = __nv_bfloat162(la, lb);
        }
    }
}

// ---------------- launcher ----------------------------------------------------
extern "C" void kernel_launch(void* const* d_in, const int* in_sizes, int n_in,
                              void* d_out, int out_size)
{
    const float* hs   = (const float*)d_in[0];
    const float* res  = (const float*)d_in[1];
    const float* nw   = (const float*)d_in[2];
    const float* w_q  = (const float*)d_in[3];
    const float* w_k  = (const float*)d_in[4];
    const float* w_v  = (const float*)d_in[5];
    const float* w_o  = (const float*)d_in[6];
    const float* hqw  = (const float*)d_in[7];
    const float* hqb  = (const float*)d_in[8];
    const float* hkw  = (const float*)d_in[9];
    const float* hkb  = (const float*)d_in[10];
    float* out = (float*)d_out;

    float *pkv;
    __nv_bfloat16 *pxhi, *pxlo, *pohi, *polo, *pwT, *pwo;
    __nv_bfloat16 *pqfh, *pqfl, *pkfh, *pkfl, *pvh, *pvl, *pSTh, *pSTl;
    cudaGetSymbolAddress((void**)&pkv,  g_kv);
    cudaGetSymbolAddress((void**)&pxhi, g_xhi);
    cudaGetSymbolAddress((void**)&pxlo, g_xlo);
    cudaGetSymbolAddress((void**)&pohi, g_ohi);
    cudaGetSymbolAddress((void**)&polo, g_olo);
    cudaGetSymbolAddress((void**)&pwT,  g_wT);
    cudaGetSymbolAddress((void**)&pwo,  g_woT);
    cudaGetSymbolAddress((void**)&pqfh, g_qfh);
    cudaGetSymbolAddress((void**)&pqfl, g_qfl);
    cudaGetSymbolAddress((void**)&pkfh, g_kfh);
    cudaGetSymbolAddress((void**)&pkfl, g_kfl);
    cudaGetSymbolAddress((void**)&pvh,  g_vh);
    cudaGetSymbolAddress((void**)&pvl,  g_vl);
    cudaGetSymbolAddress((void**)&pSTh, g_STh);
    cudaGetSymbolAddress((void**)&pSTl, g_STl);

    const int fsmem = (128*65 + 64*64) * sizeof(float);   // 49664
    cudaFuncSetAttribute(weightprep_kernel,
                         cudaFuncAttributeMaxDynamicSharedMemorySize, fsmem);
    cudaFuncSetAttribute(gemm_qkv,
                         cudaFuncAttributeMaxDynamicSharedMemorySize, GSMEM);
    cudaFuncSetAttribute(gemm_bf16x3,
                         cudaFuncAttributeMaxDynamicSharedMemorySize, GSMEM);
    cudaFuncSetAttribute(chunk_kv_kernel,
                         cudaFuncAttributeMaxDynamicSharedMemorySize, CKV_SMEM);
    cudaFuncSetAttribute(chunk_out_kernel,
                         cudaFuncAttributeMaxDynamicSharedMemorySize, CO_SMEM);

    // 1) weight prep (fold hedgehog into q/k, transpose+split v and o)
    weightprep_kernel<<<dim3(16, 8, 4), 256, fsmem>>>(w_q, w_k, w_v, w_o, hqw, hkw, pwT, pwo);

    // 2+3) fused add + RMSNorm (two halves -> positions gemm_qkv as launch #4)
    addnorm_kernel<<<BT_/2, 256>>>(hs, res, nw, out + (size_t)BT_*D_, pxhi, pxlo, 0);
    addnorm_kernel<<<BT_/2, 256>>>(hs, res, nw, out + (size_t)BT_*D_, pxhi, pxlo, BT_/2);

    // 4) fused QKV projection + hedgehog epilogue (features + split v)
    dim3 qkvgrid(24, BT_/128);
    gemm_qkv<<<qkvgrid, 256, GSMEM>>>(pxhi, pxlo, pwT, hqb, hkb,
                                      pqfh, pqfl, pkfh, pkfl, pvh, pvl);

    // 5) chunked linear attention (tensor cores)
    chunk_kv_kernel<<<NCHUNK_, 256, CKV_SMEM>>>(pkfh, pkfl, pvh, pvl, pkv);
    kv_scan_kernel<<<512, 1024>>>(pkv, pSTh, pSTl);
    chunk_out_kernel<<<NCHUNK_, 256, CO_SMEM>>>(pqfh, pqfl, pkfh, pkfl, pvh, pvl,
                                                pSTh, pSTl, pohi, polo);

    // 6) output projection
    gemm_bf16x3<<<dim3(8, BT_/128), 256, GSMEM>>>(pohi, polo, pwo, out);
}

// round 8
// speedup vs baseline: 3.0999x; 1.3304x over previous
#include <cuda_runtime.h>
#include <cuda_bf16.h>
#include <cuda_fp16.h>
#include <stdint.h>
#include <math.h>

// Problem constants
#define B_  4
#define T_  2048
#define D_  1024
#define H_  16
#define HD_ 64
#define F_  128
#define C_  64
#define N_  32
#define BT_ (B_*T_)        // 8192
#define BHT_ (B_*H_*T_)    // 131072
#define NCHUNK_ (B_*H_*N_) // 2048

// ---------------- scratch (device globals) ----------------------------------
__device__ float g_kv[NCHUNK_*F_*HD_];          // kv^T per chunk: [d][f]
__device__ __nv_bfloat16 g_STh[NCHUNK_*F_*HD_];
__device__ __nv_bfloat16 g_STl[NCHUNK_*F_*HD_];
__device__ __nv_bfloat16 g_qfh[BHT_*F_];
__device__ __nv_bfloat16 g_qfl[BHT_*F_];
__device__ __nv_bfloat16 g_kfh[BHT_*F_];
__device__ __nv_bfloat16 g_kfl[BHT_*F_];
__device__ __nv_bfloat16 g_vh [BT_*D_];
__device__ __nv_bfloat16 g_vl [BT_*D_];
__device__ __half g_xh[BT_*D_];                 // x split (fp16)
__device__ __half g_xl[BT_*D_];
__device__ __half g_oh[BT_*D_];                 // attention out split (fp16)
__device__ __half g_ol[BT_*D_];
__device__ __half g_wT [3*D_*D_];               // fused qkv weights, fp16 single
__device__ __half g_woT[D_*D_];                 // o weights, fp16 single

// ---------------- PTX helpers ------------------------------------------------
__device__ __forceinline__ uint32_t smem_u32(const void* p) {
    uint32_t a;
    asm("{ .reg .u64 t; cvta.to.shared.u64 t, %1; cvt.u32.u64 %0, t; }" : "=r"(a) : "l"(p));
    return a;
}
__device__ __forceinline__ void cp_async16(uint32_t saddr, const void* gaddr) {
    asm volatile("cp.async.cg.shared.global [%0], [%1], 16;" :: "r"(saddr), "l"(gaddr));
}
__device__ __forceinline__ void cp_commit() {
    asm volatile("cp.async.commit_group;" ::: "memory");
}
template <int NN>
__device__ __forceinline__ void cp_wait() {
    asm volatile("cp.async.wait_group %0;" :: "n"(NN) : "memory");
}
__device__ __forceinline__ void ldm_x4(uint32_t addr, uint32_t& r0, uint32_t& r1,
                                       uint32_t& r2, uint32_t& r3) {
    asm volatile("ldmatrix.sync.aligned.m8n8.x4.shared.b16 {%0,%1,%2,%3}, [%4];"
                 : "=r"(r0), "=r"(r1), "=r"(r2), "=r"(r3) : "r"(addr));
}
__device__ __forceinline__ void mma16816(float& d0, float& d1, float& d2, float& d3,
                                         uint32_t a0, uint32_t a1, uint32_t a2, uint32_t a3,
                                         uint32_t b0, uint32_t b1) {
    asm volatile("mma.sync.aligned.m16n8k16.row.col.f32.bf16.bf16.f32 "
                 "{%0,%1,%2,%3}, {%4,%5,%6,%7}, {%8,%9}, {%0,%1,%2,%3};"
                 : "+f"(d0), "+f"(d1), "+f"(d2), "+f"(d3)
                 : "r"(a0), "r"(a1), "r"(a2), "r"(a3), "r"(b0), "r"(b1));
}
__device__ __forceinline__ void mma16816h(float& d0, float& d1, float& d2, float& d3,
                                          uint32_t a0, uint32_t a1, uint32_t a2, uint32_t a3,
                                          uint32_t b0, uint32_t b1) {
    asm volatile("mma.sync.aligned.m16n8k16.row.col.f32.f16.f16.f32 "
                 "{%0,%1,%2,%3}, {%4,%5,%6,%7}, {%8,%9}, {%0,%1,%2,%3};"
                 : "+f"(d0), "+f"(d1), "+f"(d2), "+f"(d3)
                 : "r"(a0), "r"(a1), "r"(a2), "r"(a3), "r"(b0), "r"(b1));
}
__device__ __forceinline__ void bsplit(float v, __nv_bfloat16& h, __nv_bfloat16& l) {
    h = __float2bfloat16_rn(v);
    l = __float2bfloat16_rn(v - __bfloat162float(h));
}
__device__ __forceinline__ void hsplit(float v, __half& h, __half& l) {
    h = __float2half_rn(v);
    l = __float2half_rn(v - __half2float(h));
}

// ---------------- weight prep: fold/transpose -> fp16, z-dispatched ----------
__global__ __launch_bounds__(256)
void weightprep_kernel(const float* __restrict__ wq, const float* __restrict__ wk,
                       const float* __restrict__ wv, const float* __restrict__ wo,
                       const float* __restrict__ hqw, const float* __restrict__ hkw,
                       __half* __restrict__ wT, __half* __restrict__ woT)
{
    extern __shared__ float fsm[];
    float* Wb = fsm;               // [128][65]
    float* hh = fsm + 128*65;      // [64][64]
    const int z = blockIdx.z;
    const float* W   = (z==0) ? wq : (z==1) ? wk : (z==2) ? wv : wo;
    const float* hhw = (z==0) ? hqw : (z==1) ? hkw : nullptr;
    __half* dst = (z==3) ? woT : wT;
    const int rowOff = (z==0) ? 0 : (z==1) ? 1024 : (z==2) ? 2048 : 0;

    const int h = blockIdx.x, kb = blockIdx.y;
    const int tid = threadIdx.x;
    for (int i = tid; i < 8192; i += 256) {
        int r = i >> 6, d = i & 63;
        Wb[r*65 + d] = W[(size_t)(kb*128 + r)*D_ + h*64 + d];
    }
    if (hhw)
        for (int i = tid; i < 4096; i += 256) hh[i] = hhw[i];
    __syncthreads();

    const int kk = tid & 127;
    const int e0 = (tid >> 7) * 32;
    float acc[32];
    if (hhw) {
        #pragma unroll
        for (int e = 0; e < 32; e++) acc[e] = 0.f;
        for (int d = 0; d < 64; d++) {
            float wv2 = Wb[kk*65 + d];
            #pragma unroll
            for (int e = 0; e < 32; e++)
                acc[e] = fmaf(wv2, hh[(e0+e)*64 + d], acc[e]);
        }
    } else {
        #pragma unroll
        for (int e = 0; e < 32; e++) acc[e] = Wb[kk*65 + e0 + e];
    }
    #pragma unroll
    for (int e = 0; e < 32; e++) {
        size_t idx = (size_t)(rowOff + h*64 + e0 + e)*D_ + kb*128 + kk;
        dst[idx] = __float2half_rn(acc[e]);
    }
}

// ---------------- fused add + RMSNorm -> resid + fp16 split x ----------------
__global__ __launch_bounds__(256)
void addnorm_kernel(const float* __restrict__ hs, const float* __restrict__ res,
                    const float* __restrict__ w, float* __restrict__ resid_out,
                    __half* __restrict__ xh, __half* __restrict__ xl, int rowOff)
{
    __shared__ float red[8];
    const int row = blockIdx.x + rowOff;
    const int t = threadIdx.x;
    const float4* h4 = (const float4*)(hs  + (size_t)row*D_);
    const float4* r4 = (const float4*)(res + (size_t)row*D_);
    float4*      ro4 = (float4*)(resid_out + (size_t)row*D_);

    float4 h = h4[t], r = r4[t];
    float4 s = make_float4(h.x+r.x, h.y+r.y, h.z+r.z, h.w+r.w);
    ro4[t] = s;
    float ss = s.x*s.x + s.y*s.y + s.z*s.z + s.w*s.w;
    #pragma unroll
    for (int o = 16; o; o >>= 1) ss += __shfl_xor_sync(0xffffffffu, ss, o);
    if ((t & 31) == 0) red[t >> 5] = ss;
    __syncthreads();
    float tot = 0.f;
    #pragma unroll
    for (int i = 0; i < 8; i++) tot += red[i];
    float rstd = rsqrtf(tot * (1.0f/1024.0f) + 1e-5f);
    float4 wv = ((const float4*)w)[t];
    float v[4] = { s.x*rstd*wv.x, s.y*rstd*wv.y, s.z*rstd*wv.z, s.w*rstd*wv.w };
    __half hi[4], lo[4];
    #pragma unroll
    for (int i = 0; i < 4; i++) hsplit(v[i], hi[i], lo[i]);
    size_t idx = (size_t)row*D_ + t*4;
    *(__half2*)(xh+idx)   = __half2(hi[0], hi[1]);
    *(__half2*)(xh+idx+2) = __half2(hi[2], hi[3]);
    *(__half2*)(xl+idx)   = __half2(lo[0], lo[1]);
    *(__half2*)(xl+idx+2) = __half2(lo[2], lo[3]);
}

// ---------------- fp16x2 fused QKV GEMM + hedgehog epilogue -------------------
// A = xh + xl (fp16), B = W fp16 single. 2 mma products. 3-stage, 1 barrier/tile.
// bx 0..7: q features; 8..15: k features; 16..23: v bf16 split.
#define PITCH 40
#define MAT_BYTES (128*PITCH*2)          // 10240
#define STAGE3 (3*MAT_BYTES)             // 30720
#define GSMEM3 (3*STAGE3)                // 92160

__global__ __launch_bounds__(256, 2)
void gemm_qkv(const __half* __restrict__ Ah, const __half* __restrict__ Al,
              const __half* __restrict__ W,
              const float* __restrict__ biasq, const float* __restrict__ biask,
              __nv_bfloat16* __restrict__ Qfh, __nv_bfloat16* __restrict__ Qfl,
              __nv_bfloat16* __restrict__ Kfh, __nv_bfloat16* __restrict__ Kfl,
              __nv_bfloat16* __restrict__ Vh,  __nv_bfloat16* __restrict__ Vl)
{
    extern __shared__ __align__(16) char smem[];
    const uint32_t sbase = smem_u32(smem);
    const int tid = threadIdx.x, wid = tid >> 5, lane = tid & 31;
    const int bx = blockIdx.x, by = blockIdx.y;
    const int wm = wid & 1, wn = wid >> 1;

    const int lrow = tid >> 1;
    const int lc   = (tid & 1) * 2;
    const size_t gA = (size_t)(by*128 + lrow) * D_;
    const size_t gB = (size_t)(bx*128 + lrow) * D_;
    const uint32_t sRow = (uint32_t)lrow * 80;

    float acc[4][4][4];
    #pragma unroll
    for (int i = 0; i < 4; i++)
        #pragma unroll
        for (int j = 0; j < 4; j++)
            #pragma unroll
            for (int l = 0; l < 4; l++) acc[i][j][l] = 0.f;

    #define PREFETCH(kt, buf) do {                                              \
        const int k0 = (kt) * 32;                                               \
        const uint32_t b0 = sbase + (uint32_t)(buf) * STAGE3;                   \
        _Pragma("unroll")                                                       \
        for (int u = 0; u < 2; u++) {                                           \
            const int c = lc + u;                                               \
            const uint32_t so = sRow + (uint32_t)c * 16;                        \
            const size_t go = (size_t)k0 + c * 8;                               \
            cp_async16(b0 + 0*MAT_BYTES + so, Ah + gA + go);                    \
            cp_async16(b0 + 1*MAT_BYTES + so, Al + gA + go);                    \
            cp_async16(b0 + 2*MAT_BYTES + so, W  + gB + go);                    \
        }                                                                       \
        cp_commit();                                                            \
    } while (0)

    PREFETCH(0, 0);
    PREFETCH(1, 1);

    const uint32_t aRow = (uint32_t)(wm*64 + (lane & 15)) * 80 + (uint32_t)(lane >> 4) * 16;
    const uint32_t bRow = (uint32_t)(wn*32 + ((lane >> 4) & 1)*8 + (lane & 7)) * 80
                        + (uint32_t)((lane >> 3) & 1) * 16;

    const int TILES = D_ / 32;   // 32
    int buf = 0;                 // kt % 3
    #pragma unroll 1
    for (int kt = 0; kt < TILES; kt++) {
        if (kt == TILES - 1) cp_wait<0>(); else cp_wait<1>();
        __syncthreads();
        if (kt + 2 < TILES) {
            int b2 = buf + 2; if (b2 >= 3) b2 -= 3;
            PREFETCH(kt + 2, b2);
        }
        const uint32_t sb = sbase + (uint32_t)buf * STAGE3;

        #pragma unroll
        for (int kk = 0; kk < 2; kk++) {
            const uint32_t koff = (uint32_t)kk * 32;
            uint32_t bw[2][4];
            #pragma unroll
            for (int nt2 = 0; nt2 < 2; nt2++) {
                const uint32_t ba = bRow + (uint32_t)nt2 * 16 * 80 + koff;
                ldm_x4(sb + 2*MAT_BYTES + ba, bw[nt2][0], bw[nt2][1], bw[nt2][2], bw[nt2][3]);
            }
            #pragma unroll
            for (int mt = 0; mt < 4; mt++) {
                const uint32_t aa = aRow + (uint32_t)mt * 16 * 80 + koff;
                uint32_t ah[4], al[4];
                ldm_x4(sb + 0*MAT_BYTES + aa, ah[0], ah[1], ah[2], ah[3]);
                ldm_x4(sb + 1*MAT_BYTES + aa, al[0], al[1], al[2], al[3]);
                #pragma unroll
                for (int nt = 0; nt < 4; nt++) {
                    const uint32_t* bp = &bw[nt >> 1][(nt & 1) * 2];
                    float* d = acc[mt][nt];
                    mma16816h(d[0], d[1], d[2], d[3], ah[0], ah[1], ah[2], ah[3], bp[0], bp[1]);
                    mma16816h(d[0], d[1], d[2], d[3], al[0], al[1], al[2], al[3], bp[0], bp[1]);
                }
            }
        }
        buf++; if (buf == 3) buf = 0;
    }
    #undef PREFETCH
    __syncthreads();    // smem reuse below

    const int g = lane >> 2, tq = lane & 3;

    if (bx < 16) {
        // -------- hedgehog epilogue: bias + softmax([y,-y]) -> bf16 hi/lo ----
        const int isQ = (bx < 8);
        const float* bias = isQ ? biasq : biask;
        const float scale = isQ ? 0.08838834764831845f : 1.0f;
        __nv_bfloat16* fh = isQ ? Qfh : Kfh;
        __nv_bfloat16* fl = isQ ? Qfl : Kfl;
        float* smax = (float*)smem;          // [4][128]
        float* ssum = smax + 512;            // [4][128]
        #pragma unroll
        for (int mt = 0; mt < 4; mt++) {
            float pm0 = 0.f, pm1 = 0.f;
            #pragma unroll
            for (int nt = 0; nt < 4; nt++) {
                const int cb = (wn*32 + nt*8 + tq*2) & 63;
                const float b0 = bias[cb], b1 = bias[cb + 1];
                float* d = acc[mt][nt];
                d[0] += b0; d[1] += b1; d[2] += b0; d[3] += b1;
                pm0 = fmaxf(pm0, fmaxf(fabsf(d[0]), fabsf(d[1])));
                pm1 = fmaxf(pm1, fmaxf(fabsf(d[2]), fabsf(d[3])));
            }
            pm0 = fmaxf(pm0, __shfl_xor_sync(0xffffffffu, pm0, 1));
            pm0 = fmaxf(pm0, __shfl_xor_sync(0xffffffffu, pm0, 2));
            pm1 = fmaxf(pm1, __shfl_xor_sync(0xffffffffu, pm1, 1));
            pm1 = fmaxf(pm1, __shfl_xor_sync(0xffffffffu, pm1, 2));
            if (tq == 0) {
                smax[wn*128 + wm*64 + mt*16 + g]     = pm0;
                smax[wn*128 + wm*64 + mt*16 + g + 8] = pm1;
            }
        }
        __syncthreads();
        float mrow[4][2];
        #pragma unroll
        for (int mt = 0; mt < 4; mt++) {
            #pragma unroll
            for (int half = 0; half < 2; half++) {
                const int r = wm*64 + mt*16 + g + half*8;
                mrow[mt][half] = fmaxf(smax[wn*128 + r], smax[(wn^1)*128 + r]);
            }
        }
        #pragma unroll
        for (int mt = 0; mt < 4; mt++) {
            float s0 = 0.f, s1 = 0.f;
            #pragma unroll
            for (int nt = 0; nt < 4; nt++) {
                const float* d = acc[mt][nt];
                s0 += __expf(d[0]-mrow[mt][0]) + __expf(-d[0]-mrow[mt][0])
                    + __expf(d[1]-mrow[mt][0]) + __expf(-d[1]-mrow[mt][0]);
                s1 += __expf(d[2]-mrow[mt][1]) + __expf(-d[2]-mrow[mt][1])
                    + __expf(d[3]-mrow[mt][1]) + __expf(-d[3]-mrow[mt][1]);
            }
            s0 += __shfl_xor_sync(0xffffffffu, s0, 1);
            s0 += __shfl_xor_sync(0xffffffffu, s0, 2);
            s1 += __shfl_xor_sync(0xffffffffu, s1, 1);
            s1 += __shfl_xor_sync(0xffffffffu, s1, 2);
            if (tq == 0) {
                ssum[wn*128 + wm*64 + mt*16 + g]     = s0;
                ssum[wn*128 + wm*64 + mt*16 + g + 8] = s1;
            }
        }
        __syncthreads();
        const int hloc = (bx & 7)*2 + (wn >> 1);
        #pragma unroll
        for (int mt = 0; mt < 4; mt++) {
            #pragma unroll
            for (int half = 0; half < 2; half++) {
                const int r = wm*64 + mt*16 + g + half*8;
                const float z = ssum[wn*128 + r] + ssum[(wn^1)*128 + r];
                const float inv = scale / z;
                const float mm = mrow[mt][half];
                const int rowg = by*128 + r;
                const int bb = rowg >> 11, tt = rowg & 2047;
                const size_t base = ((size_t)(bb*H_ + hloc)*T_ + tt)*F_;
                #pragma unroll
                for (int nt = 0; nt < 4; nt++) {
                    const int f = (wn*32 + nt*8 + tq*2) & 63;
                    const float y0 = acc[mt][nt][half*2], y1 = acc[mt][nt][half*2+1];
                    const float p0 = __expf(y0 - mm)*inv,  p1 = __expf(y1 - mm)*inv;
                    const float n0 = __expf(-y0 - mm)*inv, n1 = __expf(-y1 - mm)*inv;
                    __nv_bfloat16 h0, l0, h1, l1;
                    bsplit(p0, h0, l0); bsplit(p1, h1, l1);
                    *(__nv_bfloat162*)(fh + base + f)      = __nv_bfloat162(h0, h1);
                    *(__nv_bfloat162*)(fl + base + f)      = __nv_bfloat162(l0, l1);
                    bsplit(n0, h0, l0); bsplit(n1, h1, l1);
                    *(__nv_bfloat162*)(fh + base + 64 + f) = __nv_bfloat162(h0, h1);
                    *(__nv_bfloat162*)(fl + base + 64 + f) = __nv_bfloat162(l0, l1);
                }
            }
        }
    } else {
        // -------- v epilogue: bf16 hi/lo split ----
        const int colbase = (bx - 16)*128;
        #pragma unroll
        for (int mt = 0; mt < 4; mt++) {
            const int r0 = by*128 + wm*64 + mt*16 + g;
            #pragma unroll
            for (int nt = 0; nt < 4; nt++) {
                const int col = colbase + wn*32 + nt*8 + tq*2;
                float* d = acc[mt][nt];
                __nv_bfloat16 h0, l0, h1, l1;
                bsplit(d[0], h0, l0); bsplit(d[1], h1, l1);
                *(__nv_bfloat162*)(Vh + (size_t)r0*D_ + col) = __nv_bfloat162(h0, h1);
                *(__nv_bfloat162*)(Vl + (size_t)r0*D_ + col) = __nv_bfloat162(l0, l1);
                bsplit(d[2], h0, l0); bsplit(d[3], h1, l1);
                *(__nv_bfloat162*)(Vh + (size_t)(r0+8)*D_ + col) = __nv_bfloat162(h0, h1);
                *(__nv_bfloat162*)(Vl + (size_t)(r0+8)*D_ + col) = __nv_bfloat162(l0, l1);
            }
        }
    }
}

// ---------------- fp16x2 GEMM (fp32 out; o-projection) ------------------------
__global__ __launch_bounds__(256, 2)
void gemm_o(const __half* __restrict__ Ah, const __half* __restrict__ Al,
            const __half* __restrict__ W, float* __restrict__ Cout)
{
    extern __shared__ __align__(16) char smem[];
    const uint32_t sbase = smem_u32(smem);
    const int tid = threadIdx.x, wid = tid >> 5, lane = tid & 31;
    const int bx = blockIdx.x, by = blockIdx.y;
    const int wm = wid & 1, wn = wid >> 1;

    const int lrow = tid >> 1;
    const int lc   = (tid & 1) * 2;
    const size_t gA = (size_t)(by*128 + lrow) * D_;
    const size_t gB = (size_t)(bx*128 + lrow) * D_;
    const uint32_t sRow = (uint32_t)lrow * 80;

    float acc[4][4][4];
    #pragma unroll
    for (int i = 0; i < 4; i++)
        #pragma unroll
        for (int j = 0; j < 4; j++)
            #pragma unroll
            for (int l = 0; l < 4; l++) acc[i][j][l] = 0.f;

    #define PREFETCH(kt, buf) do {                                              \
        const int k0 = (kt) * 32;                                               \
        const uint32_t b0 = sbase + (uint32_t)(buf) * STAGE3;                   \
        _Pragma("unroll")                                                       \
        for (int u = 0; u < 2; u++) {                                           \
            const int c = lc + u;                                               \
            const uint32_t so = sRow + (uint32_t)c * 16;                        \
            const size_t go = (size_t)k0 + c * 8;                               \
            cp_async16(b0 + 0*MAT_BYTES + so, Ah + gA + go);                    \
            cp_async16(b0 + 1*MAT_BYTES + so, Al + gA + go);                    \
            cp_async16(b0 + 2*MAT_BYTES + so, W  + gB + go);                    \
        }                                                                       \
        cp_commit();                                                            \
    } while (0)

    PREFETCH(0, 0);
    PREFETCH(1, 1);

    const uint32_t aRow = (uint32_t)(wm*64 + (lane & 15)) * 80 + (uint32_t)(lane >> 4) * 16;
    const uint32_t bRow = (uint32_t)(wn*32 + ((lane >> 4) & 1)*8 + (lane & 7)) * 80
                        + (uint32_t)((lane >> 3) & 1) * 16;

    const int TILES = D_ / 32;
    int buf = 0;
    #pragma unroll 1
    for (int kt = 0; kt < TILES; kt++) {
        if (kt == TILES - 1) cp_wait<0>(); else cp_wait<1>();
        __syncthreads();
        if (kt + 2 < TILES) {
            int b2 = buf + 2; if (b2 >= 3) b2 -= 3;
            PREFETCH(kt + 2, b2);
        }
        const uint32_t sb = sbase + (uint32_t)buf * STAGE3;

        #pragma unroll
        for (int kk = 0; kk < 2; kk++) {
            const uint32_t koff = (uint32_t)kk * 32;
            uint32_t bw[2][4];
            #pragma unroll
            for (int nt2 = 0; nt2 < 2; nt2++) {
                const uint32_t ba = bRow + (uint32_t)nt2 * 16 * 80 + koff;
                ldm_x4(sb + 2*MAT_BYTES + ba, bw[nt2][0], bw[nt2][1], bw[nt2][2], bw[nt2][3]);
            }
            #pragma unroll
            for (int mt = 0; mt < 4; mt++) {
                const uint32_t aa = aRow + (uint32_t)mt * 16 * 80 + koff;
                uint32_t ah[4], al[4];
                ldm_x4(sb + 0*MAT_BYTES + aa, ah[0], ah[1], ah[2], ah[3]);
                ldm_x4(sb + 1*MAT_BYTES + aa, al[0], al[1], al[2], al[3]);
                #pragma unroll
                for (int nt = 0; nt < 4; nt++) {
                    const uint32_t* bp = &bw[nt >> 1][(nt & 1) * 2];
                    float* d = acc[mt][nt];
                    mma16816h(d[0], d[1], d[2], d[3], ah[0], ah[1], ah[2], ah[3], bp[0], bp[1]);
                    mma16816h(d[0], d[1], d[2], d[3], al[0], al[1], al[2], al[3], bp[0], bp[1]);
                }
            }
        }
        buf++; if (buf == 3) buf = 0;
    }
    #undef PREFETCH

    const int g = lane >> 2, tq = lane & 3;
    #pragma unroll
    for (int mt = 0; mt < 4; mt++) {
        const int r0 = by*128 + wm*64 + mt*16 + g;
        #pragma unroll
        for (int nt = 0; nt < 4; nt++) {
            const int col = bx*128 + wn*32 + nt*8 + tq*2;
            float* d = acc[mt][nt];
            *(float2*)(Cout + (size_t)r0*D_ + col)     = make_float2(d[0], d[1]);
            *(float2*)(Cout + (size_t)(r0+8)*D_ + col) = make_float2(d[2], d[3]);
        }
    }
}

// ---------------- phase A: kv^T[d][f] = sum_c v[c,d] k[c,f]  (bf16x3) --------
#define CKV_KTH 0u
#define CKV_KTL 18432u
#define CKV_VTH 36864u
#define CKV_VTL 46080u
#define CKV_SMEM 55296u

__global__ __launch_bounds__(256, 2)
void chunk_kv_kernel(const __nv_bfloat16* __restrict__ kfh, const __nv_bfloat16* __restrict__ kfl,
                     const __nv_bfloat16* __restrict__ vh, const __nv_bfloat16* __restrict__ vl,
                     float* __restrict__ kvT)
{
    extern __shared__ __align__(16) char smem[];
    const uint32_t sb = smem_u32(smem);
    const int blk = blockIdx.x;
    const int n = blk & 31, bh = blk >> 5;
    const int b = bh >> 4, h = bh & 15;
    const int tid = threadIdx.x, wid = tid >> 5, lane = tid & 31;

    {
        const int c = tid >> 2, fg = (tid & 3) * 32;
        const size_t src = ((size_t)bh*T_ + n*C_ + c)*F_ + fg;
        union { uint4 u; __nv_bfloat16 b[8]; } r;
        #pragma unroll
        for (int q = 0; q < 4; q++) {
            r.u = *(const uint4*)(kfh + src + q*8);
            #pragma unroll
            for (int i = 0; i < 8; i++)
                *(__nv_bfloat16*)(smem + CKV_KTH + (fg+q*8+i)*144 + c*2) = r.b[i];
            r.u = *(const uint4*)(kfl + src + q*8);
            #pragma unroll
            for (int i = 0; i < 8; i++)
                *(__nv_bfloat16*)(smem + CKV_KTL + (fg+q*8+i)*144 + c*2) = r.b[i];
        }
    }
    {
        const int c = tid >> 2, dg = (tid & 3) * 16;
        const size_t src = ((size_t)(b*T_) + n*C_ + c)*D_ + h*HD_ + dg;
        union { uint4 u; __nv_bfloat16 b[8]; } r;
        #pragma unroll
        for (int q = 0; q < 2; q++) {
            r.u = *(const uint4*)(vh + src + q*8);
            #pragma unroll
            for (int i = 0; i < 8; i++)
                *(__nv_bfloat16*)(smem + CKV_VTH + (dg+q*8+i)*144 + c*2) = r.b[i];
            r.u = *(const uint4*)(vl + src + q*8);
            #pragma unroll
            for (int i = 0; i < 8; i++)
                *(__nv_bfloat16*)(smem + CKV_VTL + (dg+q*8+i)*144 + c*2) = r.b[i];
        }
    }
    __syncthreads();

    const int wm = wid & 3, wn = wid >> 2;
    float acc[8][4];
    #pragma unroll
    for (int i = 0; i < 8; i++)
        #pragma unroll
        for (int j = 0; j < 4; j++) acc[i][j] = 0.f;

    const uint32_t aBase = sb + CKV_VTH + (uint32_t)(wm*16 + (lane & 15))*144
                         + (uint32_t)(lane >> 4)*16;
    const uint32_t bBase = sb + CKV_KTH + (uint32_t)(wn*64 + ((lane >> 4) & 1)*8 + (lane & 7))*144
                         + (uint32_t)((lane >> 3) & 1)*16;

    #pragma unroll
    for (int ks = 0; ks < 4; ks++) {
        const uint32_t koff = (uint32_t)ks*32;
        uint32_t ah[4], al[4];
        ldm_x4(aBase + koff, ah[0], ah[1], ah[2], ah[3]);
        ldm_x4(aBase + (CKV_VTL - CKV_VTH) + koff, al[0], al[1], al[2], al[3]);
        uint32_t bhf[4][4], blf[4][4];
        #pragma unroll
        for (int p = 0; p < 4; p++) {
            const uint32_t ba = bBase + (uint32_t)p*16*144 + koff;
            ldm_x4(ba, bhf[p][0], bhf[p][1], bhf[p][2], bhf[p][3]);
            ldm_x4(ba + (CKV_KTL - CKV_KTH), blf[p][0], blf[p][1], blf[p][2], blf[p][3]);
        }
        #pragma unroll
        for (int nt = 0; nt < 8; nt++) {
            const uint32_t* bhp = &bhf[nt >> 1][(nt & 1)*2];
            const uint32_t* blp = &blf[nt >> 1][(nt & 1)*2];
            float* d = acc[nt];
            mma16816(d[0], d[1], d[2], d[3], ah[0], ah[1], ah[2], ah[3], bhp[0], bhp[1]);
            mma16816(d[0], d[1], d[2], d[3], ah[0], ah[1], ah[2], ah[3], blp[0], blp[1]);
            mma16816(d[0], d[1], d[2], d[3], al[0], al[1], al[2], al[3], bhp[0], bhp[1]);
        }
    }
    const int g = lane >> 2, tq = lane & 3;
    float* out = kvT + (size_t)blk * (F_*HD_);
    #pragma unroll
    for (int nt = 0; nt < 8; nt++) {
        const int f = wn*64 + nt*8 + tq*2;
        const int d0 = wm*16 + g;
        *(float2*)(out + (size_t)d0*F_ + f)     = make_float2(acc[nt][0], acc[nt][1]);
        *(float2*)(out + (size_t)(d0+8)*F_ + f) = make_float2(acc[nt][2], acc[nt][3]);
    }
}

// ---------------- phase B: exclusive cumsum -> bf16 hi/lo --------------------
__global__ __launch_bounds__(1024)
void kv_scan_kernel(const float* __restrict__ kvT,
                    __nv_bfloat16* __restrict__ STh, __nv_bfloat16* __restrict__ STl)
{
    const int blk = blockIdx.x;
    const int bh = blk >> 3, seg = blk & 7;
    const int e = seg*1024 + threadIdx.x;
    size_t base = (size_t)bh * N_ * (F_*HD_) + e;
    float acc = 0.f;
    for (int n = 0; n < N_; n++) {
        size_t idx = base + (size_t)n * (F_*HD_);
        __nv_bfloat16 hv, lv;
        bsplit(acc, hv, lv);
        STh[idx] = hv;
        STl[idx] = lv;
        acc += kvT[idx];
    }
}

// ---------------- phase C: out = q@S_excl + tril(q@k^T)@v  (bf16x3) ----------
#define CO_QH 0u
#define CO_QL 17408u
#define CO_KH 34816u
#define CO_KL 52224u
#define CO_VTH 69632u
#define CO_VTL 78848u
#define CO_SCH 88064u
#define CO_SCL 97280u
#define CO_SMEM 106496u

__global__ __launch_bounds__(256, 1)
void chunk_out_kernel(const __nv_bfloat16* __restrict__ qfh, const __nv_bfloat16* __restrict__ qfl,
                      const __nv_bfloat16* __restrict__ kfh, const __nv_bfloat16* __restrict__ kfl,
                      const __nv_bfloat16* __restrict__ vh,  const __nv_bfloat16* __restrict__ vl,
                      const __nv_bfloat16* __restrict__ STh, const __nv_bfloat16* __restrict__ STl,
                      __half* __restrict__ oh, __half* __restrict__ ol)
{
    extern __shared__ __align__(16) char smem[];
    const uint32_t sb = smem_u32(smem);
    const int blk = blockIdx.x;
    const int n = blk & 31, bh = blk >> 5;
    const int b = bh >> 4, h = bh & 15;
    const int tid = threadIdx.x, wid = tid >> 5, lane = tid & 31;

    {
        const int c = tid >> 2, fg = (tid & 3) * 32;
        const size_t src = ((size_t)bh*T_ + n*C_ + c)*F_ + fg;
        uint4* dq  = (uint4*)(smem + CO_QH + c*272 + fg*2);
        uint4* dql = (uint4*)(smem + CO_QL + c*272 + fg*2);
        uint4* dk  = (uint4*)(smem + CO_KH + c*272 + fg*2);
        uint4* dkl = (uint4*)(smem + CO_KL + c*272 + fg*2);
        #pragma unroll
        for (int q = 0; q < 4; q++) {
            dq [q] = *(const uint4*)(qfh + src + q*8);
            dql[q] = *(const uint4*)(qfl + src + q*8);
            dk [q] = *(const uint4*)(kfh + src + q*8);
            dkl[q] = *(const uint4*)(kfl + src + q*8);
        }
    }
    {
        const int c = tid >> 2, dg = (tid & 3) * 16;
        const size_t src = ((size_t)(b*T_) + n*C_ + c)*D_ + h*HD_ + dg;
        union { uint4 u; __nv_bfloat16 bb[8]; } r;
        #pragma unroll
        for (int q = 0; q < 2; q++) {
            r.u = *(const uint4*)(vh + src + q*8);
            #pragma unroll
            for (int i = 0; i < 8; i++)
                *(__nv_bfloat16*)(smem + CO_VTH + (dg+q*8+i)*144 + c*2) = r.bb[i];
            r.u = *(const uint4*)(vl + src + q*8);
            #pragma unroll
            for (int i = 0; i < 8; i++)
                *(__nv_bfloat16*)(smem + CO_VTL + (dg+q*8+i)*144 + c*2) = r.bb[i];
        }
    }
    __syncthreads();

    const int wm = wid & 3, wn = wid >> 2;
    const int g = lane >> 2, tq = lane & 3;

    const uint32_t aQ = sb + CO_QH + (uint32_t)(wm*16 + (lane & 15))*272 + (uint32_t)(lane >> 4)*16;
    const uint32_t bK = sb + CO_KH + (uint32_t)(wn*32 + ((lane >> 4) & 1)*8 + (lane & 7))*272
                      + (uint32_t)((lane >> 3) & 1)*16;

    float sacc[4][4];
    #pragma unroll
    for (int i = 0; i < 4; i++)
        #pragma unroll
        for (int j = 0; j < 4; j++) sacc[i][j] = 0.f;

    #pragma unroll
    for (int ks = 0; ks < 8; ks++) {
        const uint32_t koff = (uint32_t)ks*32;
        uint32_t ah[4], al[4];
        ldm_x4(aQ + koff, ah[0], ah[1], ah[2], ah[3]);
        ldm_x4(aQ + (CO_QL - CO_QH) + koff, al[0], al[1], al[2], al[3]);
        uint32_t bhf[2][4], blf[2][4];
        #pragma unroll
        for (int p = 0; p < 2; p++) {
            const uint32_t ba = bK + (uint32_t)p*16*272 + koff;
            ldm_x4(ba, bhf[p][0], bhf[p][1], bhf[p][2], bhf[p][3]);
            ldm_x4(ba + (CO_KL - CO_KH), blf[p][0], blf[p][1], blf[p][2], blf[p][3]);
        }
        #pragma unroll
        for (int nt = 0; nt < 4; nt++) {
            const uint32_t* bhp = &bhf[nt >> 1][(nt & 1)*2];
            const uint32_t* blp = &blf[nt >> 1][(nt & 1)*2];
            float* d = sacc[nt];
            mma16816(d[0], d[1], d[2], d[3], ah[0], ah[1], ah[2], ah[3], bhp[0], bhp[1]);
            mma16816(d[0], d[1], d[2], d[3], ah[0], ah[1], ah[2], ah[3], blp[0], blp[1]);
            mma16816(d[0], d[1], d[2], d[3], al[0], al[1], al[2], al[3], bhp[0], bhp[1]);
        }
    }
    #pragma unroll
    for (int nt = 0; nt < 4; nt++) {
        const int colb = wn*32 + nt*8 + tq*2;
        const int r0 = wm*16 + g, r1 = r0 + 8;
        float v00 = (colb     <= r0) ? sacc[nt][0] : 0.f;
        float v01 = (colb + 1 <= r0) ? sacc[nt][1] : 0.f;
        float v10 = (colb     <= r1) ? sacc[nt][2] : 0.f;
        float v11 = (colb + 1 <= r1) ? sacc[nt][3] : 0.f;
        __nv_bfloat16 h0, l0, h1, l1;
        bsplit(v00, h0, l0); bsplit(v01, h1, l1);
        *(__nv_bfloat162*)(smem + CO_SCH + r0*144 + colb*2) = __nv_bfloat162(h0, h1);
        *(__nv_bfloat162*)(smem + CO_SCL + r0*144 + colb*2) = __nv_bfloat162(l0, l1);
        bsplit(v10, h0, l0); bsplit(v11, h1, l1);
        *(__nv_bfloat162*)(smem + CO_SCH + r1*144 + colb*2) = __nv_bfloat162(h0, h1);
        *(__nv_bfloat162*)(smem + CO_SCL + r1*144 + colb*2) = __nv_bfloat162(l0, l1);
    }
    __syncthreads();

    {
        const int d = tid >> 2, fg = (tid & 3) * 32;
        const size_t src = (size_t)blk*(F_*HD_) + d*F_ + fg;
        uint4* dh = (uint4*)(smem + CO_KH + d*272 + fg*2);
        uint4* dl = (uint4*)(smem + CO_KL + d*272 + fg*2);
        #pragma unroll
        for (int q = 0; q < 4; q++) {
            dh[q] = *(const uint4*)(STh + src + q*8);
            dl[q] = *(const uint4*)(STl + src + q*8);
        }
    }
    __syncthreads();

    float oacc[4][4];
    #pragma unroll
    for (int i = 0; i < 4; i++)
        #pragma unroll
        for (int j = 0; j < 4; j++) oacc[i][j] = 0.f;

    #pragma unroll
    for (int ks = 0; ks < 8; ks++) {
        const uint32_t koff = (uint32_t)ks*32;
        uint32_t ah[4], al[4];
        ldm_x4(aQ + koff, ah[0], ah[1], ah[2], ah[3]);
        ldm_x4(aQ + (CO_QL - CO_QH) + koff, al[0], al[1], al[2], al[3]);
        uint32_t bhf[2][4], blf[2][4];
        #pragma unroll
        for (int p = 0; p < 2; p++) {
            const uint32_t ba = bK + (uint32_t)p*16*272 + koff;
            ldm_x4(ba, bhf[p][0], bhf[p][1], bhf[p][2], bhf[p][3]);
            ldm_x4(ba + (CO_KL - CO_KH), blf[p][0], blf[p][1], blf[p][2], blf[p][3]);
        }
        #pragma unroll
        for (int nt = 0; nt < 4; nt++) {
            const uint32_t* bhp = &bhf[nt >> 1][(nt & 1)*2];
            const uint32_t* blp = &blf[nt >> 1][(nt & 1)*2];
            float* d = oacc[nt];
            mma16816(d[0], d[1], d[2], d[3], ah[0], ah[1], ah[2], ah[3], bhp[0], bhp[1]);
            mma16816(d[0], d[1], d[2], d[3], ah[0], ah[1], ah[2], ah[3], blp[0], blp[1]);
            mma16816(d[0], d[1], d[2], d[3], al[0], al[1], al[2], al[3], bhp[0], bhp[1]);
        }
    }
    {
        const uint32_t aS = sb + CO_SCH + (uint32_t)(wm*16 + (lane & 15))*144
                          + (uint32_t)(lane >> 4)*16;
        const uint32_t bV = sb + CO_VTH + (uint32_t)(wn*32 + ((lane >> 4) & 1)*8 + (lane & 7))*144
                          + (uint32_t)((lane >> 3) & 1)*16;
        #pragma unroll
        for (int ks = 0; ks < 4; ks++) {
            const uint32_t koff = (uint32_t)ks*32;
            uint32_t ah[4], al[4];
            ldm_x4(aS + koff, ah[0], ah[1], ah[2], ah[3]);
            ldm_x4(aS + (CO_SCL - CO_SCH) + koff, al[0], al[1], al[2], al[3]);
            uint32_t bhf[2][4], blf[2][4];
            #pragma unroll
            for (int p = 0; p < 2; p++) {
                const uint32_t ba = bV + (uint32_t)p*16*144 + koff;
                ldm_x4(ba, bhf[p][0], bhf[p][1], bhf[p][2], bhf[p][3]);
                ldm_x4(ba + (CO_VTL - CO_VTH), blf[p][0], blf[p][1], blf[p][2], blf[p][3]);
            }
            #pragma unroll
            for (int nt = 0; nt < 4; nt++) {
                const uint32_t* bhp = &bhf[nt >> 1][(nt & 1)*2];
                const uint32_t* blp = &blf[nt >> 1][(nt & 1)*2];
                float* d = oacc[nt];
                mma16816(d[0], d[1], d[2], d[3], ah[0], ah[1], ah[2], ah[3], bhp[0], bhp[1]);
                mma16816(d[0], d[1], d[2], d[3], ah[0], ah[1], ah[2], ah[3], blp[0], blp[1]);
                mma16816(d[0], d[1], d[2], d[3], al[0], al[1], al[2], al[3], bhp[0], bhp[1]);
            }
        }
    }

    #pragma unroll
    for (int nt = 0; nt < 4; nt++) {
        const int dcol = wn*32 + nt*8 + tq*2;
        const int r0 = wm*16 + g;
        #pragma unroll
        for (int half = 0; half < 2; half++) {
            const int r = r0 + half*8;
            const float va = oacc[nt][half*2], vb = oacc[nt][half*2+1];
            __half ha, la, hb, lb;
            hsplit(va, ha, la); hsplit(vb, hb, lb);
            const size_t oidx = ((size_t)(b*T_) + n*C_ + r)*D_ + h*HD_ + dcol;
            *(__half2*)(oh + oidx) = __half2(ha, hb);
            *(__half2*)(ol + oidx) = __half2(la, lb);
        }
    }
}

// ---------------- launcher ----------------------------------------------------
extern "C" void kernel_launch(void* const* d_in, const int* in_sizes, int n_in,
                              void* d_out, int out_size)
{
    const float* hs   = (const float*)d_in[0];
    const float* res  = (const float*)d_in[1];
    const float* nw   = (const float*)d_in[2];
    const float* w_q  = (const float*)d_in[3];
    const float* w_k  = (const float*)d_in[4];
    const float* w_v  = (const float*)d_in[5];
    const float* w_o  = (const float*)d_in[6];
    const float* hqw  = (const float*)d_in[7];
    const float* hqb  = (const float*)d_in[8];
    const float* hkw  = (const float*)d_in[9];
    const float* hkb  = (const float*)d_in[10];
    float* out = (float*)d_out;

    float *pkv;
    __half *pxh, *pxl, *poh, *pol, *pwT, *pwo;
    __nv_bfloat16 *pqfh, *pqfl, *pkfh, *pkfl, *pvh, *pvl, *pSTh, *pSTl;
    cudaGetSymbolAddress((void**)&pkv,  g_kv);
    cudaGetSymbolAddress((void**)&pxh,  g_xh);
    cudaGetSymbolAddress((void**)&pxl,  g_xl);
    cudaGetSymbolAddress((void**)&poh,  g_oh);
    cudaGetSymbolAddress((void**)&pol,  g_ol);
    cudaGetSymbolAddress((void**)&pwT,  g_wT);
    cudaGetSymbolAddress((void**)&pwo,  g_woT);
    cudaGetSymbolAddress((void**)&pqfh, g_qfh);
    cudaGetSymbolAddress((void**)&pqfl, g_qfl);
    cudaGetSymbolAddress((void**)&pkfh, g_kfh);
    cudaGetSymbolAddress((void**)&pkfl, g_kfl);
    cudaGetSymbolAddress((void**)&pvh,  g_vh);
    cudaGetSymbolAddress((void**)&pvl,  g_vl);
    cudaGetSymbolAddress((void**)&pSTh, g_STh);
    cudaGetSymbolAddress((void**)&pSTl, g_STl);

    const int fsmem = (128*65 + 64*64) * sizeof(float);   // 49664
    cudaFuncSetAttribute(weightprep_kernel,
                         cudaFuncAttributeMaxDynamicSharedMemorySize, fsmem);
    cudaFuncSetAttribute(gemm_qkv,
                         cudaFuncAttributeMaxDynamicSharedMemorySize, GSMEM3);
    cudaFuncSetAttribute(gemm_o,
                         cudaFuncAttributeMaxDynamicSharedMemorySize, GSMEM3);
    cudaFuncSetAttribute(chunk_kv_kernel,
                         cudaFuncAttributeMaxDynamicSharedMemorySize, CKV_SMEM);
    cudaFuncSetAttribute(chunk_out_kernel,
                         cudaFuncAttributeMaxDynamicSharedMemorySize, CO_SMEM);

    // 1) weight prep (fold hedgehog into q/k; transpose v, o) -> fp16
    weightprep_kernel<<<dim3(16, 8, 4), 256, fsmem>>>(w_q, w_k, w_v, w_o, hqw, hkw, pwT, pwo);

    // 2+3) fused add + RMSNorm (two halves -> keeps gemm_qkv as launch #4)
    addnorm_kernel<<<BT_/2, 256>>>(hs, res, nw, out + (size_t)BT_*D_, pxh, pxl, 0);
    addnorm_kernel<<<BT_/2, 256>>>(hs, res, nw, out + (size_t)BT_*D_, pxh, pxl, BT_/2);

    // 4) fused QKV projection (fp16x2) + hedgehog epilogue
    dim3 qkvgrid(24, BT_/128);
    gemm_qkv<<<qkvgrid, 256, GSMEM3>>>(pxh, pxl, pwT, hqb, hkb,
                                       pqfh, pqfl, pkfh, pkfl, pvh, pvl);

    // 5) chunked linear attention (bf16x3 tensor cores)
    chunk_kv_kernel<<<NCHUNK_, 256, CKV_SMEM>>>(pkfh, pkfl, pvh, pvl, pkv);
    kv_scan_kernel<<<512, 1024>>>(pkv, pSTh, pSTl);
    chunk_out_kernel<<<NCHUNK_, 256, CO_SMEM>>>(pqfh, pqfl, pkfh, pkfl, pvh, pvl,
                                                pSTh, pSTl, poh, pol);

    // 6) output projection (fp16x2)
    gemm_o<<<dim3(8, BT_/128), 256, GSMEM3>>>(poh, pol, pwo, out);
}

// round 9
// speedup vs baseline: 3.3879x; 1.0929x over previous
#include <cuda_runtime.h>
#include <cuda_bf16.h>
#include <cuda_fp16.h>
#include <stdint.h>
#include <math.h>

// Problem constants
#define B_  4
#define T_  2048
#define D_  1024
#define H_  16
#define HD_ 64
#define F_  128
#define C_  64
#define N_  32
#define BT_ (B_*T_)        // 8192
#define BHT_ (B_*H_*T_)    // 131072
#define NCHUNK_ (B_*H_*N_) // 2048

// ---------------- scratch (device globals) ----------------------------------
__device__ float g_kv[NCHUNK_*F_*HD_];          // kv^T per chunk: [d][f]
__device__ __half g_ST [NCHUNK_*F_*HD_];        // S_excl^T single fp16 (B-only)
__device__ __half g_qfh[BHT_*F_];               // q features split (A operand)
__device__ __half g_qfl[BHT_*F_];
__device__ __half g_kfh[BHT_*F_];               // k features hi-only (B operand)
__device__ __half g_vh [BT_*D_];                // v split (A in chunk_kv, B hi-only)
__device__ __half g_vl [BT_*D_];
__device__ __half g_xh[BT_*D_];                 // x split (fp16)
__device__ __half g_xl[BT_*D_];
__device__ __half g_oh[BT_*D_];                 // attention out split (fp16)
__device__ __half g_ol[BT_*D_];
__device__ __half g_wT [3*D_*D_];               // fused qkv weights, fp16 single
__device__ __half g_woT[D_*D_];                 // o weights, fp16 single

// ---------------- PTX helpers ------------------------------------------------
__device__ __forceinline__ uint32_t smem_u32(const void* p) {
    uint32_t a;
    asm("{ .reg .u64 t; cvta.to.shared.u64 t, %1; cvt.u32.u64 %0, t; }" : "=r"(a) : "l"(p));
    return a;
}
__device__ __forceinline__ void cp_async16(uint32_t saddr, const void* gaddr) {
    asm volatile("cp.async.cg.shared.global [%0], [%1], 16;" :: "r"(saddr), "l"(gaddr));
}
__device__ __forceinline__ void cp_commit() {
    asm volatile("cp.async.commit_group;" ::: "memory");
}
template <int NN>
__device__ __forceinline__ void cp_wait() {
    asm volatile("cp.async.wait_group %0;" :: "n"(NN) : "memory");
}
__device__ __forceinline__ void ldm_x4(uint32_t addr, uint32_t& r0, uint32_t& r1,
                                       uint32_t& r2, uint32_t& r3) {
    asm volatile("ldmatrix.sync.aligned.m8n8.x4.shared.b16 {%0,%1,%2,%3}, [%4];"
                 : "=r"(r0), "=r"(r1), "=r"(r2), "=r"(r3) : "r"(addr));
}
__device__ __forceinline__ void mma16816h(float& d0, float& d1, float& d2, float& d3,
                                          uint32_t a0, uint32_t a1, uint32_t a2, uint32_t a3,
                                          uint32_t b0, uint32_t b1) {
    asm volatile("mma.sync.aligned.m16n8k16.row.col.f32.f16.f16.f32 "
                 "{%0,%1,%2,%3}, {%4,%5,%6,%7}, {%8,%9}, {%0,%1,%2,%3};"
                 : "+f"(d0), "+f"(d1), "+f"(d2), "+f"(d3)
                 : "r"(a0), "r"(a1), "r"(a2), "r"(a3), "r"(b0), "r"(b1));
}
__device__ __forceinline__ void hsplit(float v, __half& h, __half& l) {
    h = __float2half_rn(v);
    l = __float2half_rn(v - __half2float(h));
}

// ---------------- weight prep: fold/transpose -> fp16, z-dispatched ----------
__global__ __launch_bounds__(256)
void weightprep_kernel(const float* __restrict__ wq, const float* __restrict__ wk,
                       const float* __restrict__ wv, const float* __restrict__ wo,
                       const float* __restrict__ hqw, const float* __restrict__ hkw,
                       __half* __restrict__ wT, __half* __restrict__ woT)
{
    extern __shared__ float fsm[];
    float* Wb = fsm;               // [128][65]
    float* hh = fsm + 128*65;      // [64][64]
    const int z = blockIdx.z;
    const float* W   = (z==0) ? wq : (z==1) ? wk : (z==2) ? wv : wo;
    const float* hhw = (z==0) ? hqw : (z==1) ? hkw : nullptr;
    __half* dst = (z==3) ? woT : wT;
    const int rowOff = (z==0) ? 0 : (z==1) ? 1024 : (z==2) ? 2048 : 0;

    const int h = blockIdx.x, kb = blockIdx.y;
    const int tid = threadIdx.x;
    for (int i = tid; i < 8192; i += 256) {
        int r = i >> 6, d = i & 63;
        Wb[r*65 + d] = W[(size_t)(kb*128 + r)*D_ + h*64 + d];
    }
    if (hhw)
        for (int i = tid; i < 4096; i += 256) hh[i] = hhw[i];
    __syncthreads();

    const int kk = tid & 127;
    const int e0 = (tid >> 7) * 32;
    float acc[32];
    if (hhw) {
        #pragma unroll
        for (int e = 0; e < 32; e++) acc[e] = 0.f;
        for (int d = 0; d < 64; d++) {
            float wv2 = Wb[kk*65 + d];
            #pragma unroll
            for (int e = 0; e < 32; e++)
                acc[e] = fmaf(wv2, hh[(e0+e)*64 + d], acc[e]);
        }
    } else {
        #pragma unroll
        for (int e = 0; e < 32; e++) acc[e] = Wb[kk*65 + e0 + e];
    }
    #pragma unroll
    for (int e = 0; e < 32; e++) {
        size_t idx = (size_t)(rowOff + h*64 + e0 + e)*D_ + kb*128 + kk;
        dst[idx] = __float2half_rn(acc[e]);
    }
}

// ---------------- fused add + RMSNorm -> resid + fp16 split x ----------------
__global__ __launch_bounds__(256)
void addnorm_kernel(const float* __restrict__ hs, const float* __restrict__ res,
                    const float* __restrict__ w, float* __restrict__ resid_out,
                    __half* __restrict__ xh, __half* __restrict__ xl, int rowOff)
{
    __shared__ float red[8];
    const int row = blockIdx.x + rowOff;
    const int t = threadIdx.x;
    const float4* h4 = (const float4*)(hs  + (size_t)row*D_);
    const float4* r4 = (const float4*)(res + (size_t)row*D_);
    float4*      ro4 = (float4*)(resid_out + (size_t)row*D_);

    float4 h = h4[t], r = r4[t];
    float4 s = make_float4(h.x+r.x, h.y+r.y, h.z+r.z, h.w+r.w);
    ro4[t] = s;
    float ss = s.x*s.x + s.y*s.y + s.z*s.z + s.w*s.w;
    #pragma unroll
    for (int o = 16; o; o >>= 1) ss += __shfl_xor_sync(0xffffffffu, ss, o);
    if ((t & 31) == 0) red[t >> 5] = ss;
    __syncthreads();
    float tot = 0.f;
    #pragma unroll
    for (int i = 0; i < 8; i++) tot += red[i];
    float rstd = rsqrtf(tot * (1.0f/1024.0f) + 1e-5f);
    float4 wv = ((const float4*)w)[t];
    float v[4] = { s.x*rstd*wv.x, s.y*rstd*wv.y, s.z*rstd*wv.z, s.w*rstd*wv.w };
    __half hi[4], lo[4];
    #pragma unroll
    for (int i = 0; i < 4; i++) hsplit(v[i], hi[i], lo[i]);
    size_t idx = (size_t)row*D_ + t*4;
    *(__half2*)(xh+idx)   = __halves2half2(hi[0], hi[1]);
    *(__half2*)(xh+idx+2) = __halves2half2(hi[2], hi[3]);
    *(__half2*)(xl+idx)   = __halves2half2(lo[0], lo[1]);
    *(__half2*)(xl+idx+2) = __halves2half2(lo[2], lo[3]);
}

// ---------------- fp16x2 fused QKV GEMM + hedgehog epilogue -------------------
#define PITCH 40
#define MAT_BYTES (128*PITCH*2)          // 10240
#define STAGE3 (3*MAT_BYTES)             // 30720
#define GSMEM3 (3*STAGE3)                // 92160

__global__ __launch_bounds__(256, 2)
void gemm_qkv(const __half* __restrict__ Ah, const __half* __restrict__ Al,
              const __half* __restrict__ W,
              const float* __restrict__ biasq, const float* __restrict__ biask,
              __half* __restrict__ Qfh, __half* __restrict__ Qfl,
              __half* __restrict__ Kfh,
              __half* __restrict__ Vh,  __half* __restrict__ Vl)
{
    extern __shared__ __align__(16) char smem[];
    const uint32_t sbase = smem_u32(smem);
    const int tid = threadIdx.x, wid = tid >> 5, lane = tid & 31;
    const int bx = blockIdx.x, by = blockIdx.y;
    const int wm = wid & 1, wn = wid >> 1;

    const int lrow = tid >> 1;
    const int lc   = (tid & 1) * 2;
    const size_t gA = (size_t)(by*128 + lrow) * D_;
    const size_t gB = (size_t)(bx*128 + lrow) * D_;
    const uint32_t sRow = (uint32_t)lrow * 80;

    float acc[4][4][4];
    #pragma unroll
    for (int i = 0; i < 4; i++)
        #pragma unroll
        for (int j = 0; j < 4; j++)
            #pragma unroll
            for (int l = 0; l < 4; l++) acc[i][j][l] = 0.f;

    #define PREFETCH(kt, buf) do {                                              \
        const int k0 = (kt) * 32;                                               \
        const uint32_t b0 = sbase + (uint32_t)(buf) * STAGE3;                   \
        _Pragma("unroll")                                                       \
        for (int u = 0; u < 2; u++) {                                           \
            const int c = lc + u;                                               \
            const uint32_t so = sRow + (uint32_t)c * 16;                        \
            const size_t go = (size_t)k0 + c * 8;                               \
            cp_async16(b0 + 0*MAT_BYTES + so, Ah + gA + go);                    \
            cp_async16(b0 + 1*MAT_BYTES + so, Al + gA + go);                    \
            cp_async16(b0 + 2*MAT_BYTES + so, W  + gB + go);                    \
        }                                                                       \
        cp_commit();                                                            \
    } while (0)

    PREFETCH(0, 0);
    PREFETCH(1, 1);

    const uint32_t aRow = (uint32_t)(wm*64 + (lane & 15)) * 80 + (uint32_t)(lane >> 4) * 16;
    const uint32_t bRow = (uint32_t)(wn*32 + ((lane >> 4) & 1)*8 + (lane & 7)) * 80
                        + (uint32_t)((lane >> 3) & 1) * 16;

    const int TILES = D_ / 32;   // 32
    int buf = 0;
    #pragma unroll 1
    for (int kt = 0; kt < TILES; kt++) {
        if (kt == TILES - 1) cp_wait<0>(); else cp_wait<1>();
        __syncthreads();
        if (kt + 2 < TILES) {
            int b2 = buf + 2; if (b2 >= 3) b2 -= 3;
            PREFETCH(kt + 2, b2);
        }
        const uint32_t sb = sbase + (uint32_t)buf * STAGE3;

        #pragma unroll
        for (int kk = 0; kk < 2; kk++) {
            const uint32_t koff = (uint32_t)kk * 32;
            uint32_t bw[2][4];
            #pragma unroll
            for (int nt2 = 0; nt2 < 2; nt2++) {
                const uint32_t ba = bRow + (uint32_t)nt2 * 16 * 80 + koff;
                ldm_x4(sb + 2*MAT_BYTES + ba, bw[nt2][0], bw[nt2][1], bw[nt2][2], bw[nt2][3]);
            }
            #pragma unroll
            for (int mt = 0; mt < 4; mt++) {
                const uint32_t aa = aRow + (uint32_t)mt * 16 * 80 + koff;
                uint32_t ah[4], al[4];
                ldm_x4(sb + 0*MAT_BYTES + aa, ah[0], ah[1], ah[2], ah[3]);
                ldm_x4(sb + 1*MAT_BYTES + aa, al[0], al[1], al[2], al[3]);
                #pragma unroll
                for (int nt = 0; nt < 4; nt++) {
                    const uint32_t* bp = &bw[nt >> 1][(nt & 1) * 2];
                    float* d = acc[mt][nt];
                    mma16816h(d[0], d[1], d[2], d[3], ah[0], ah[1], ah[2], ah[3], bp[0], bp[1]);
                    mma16816h(d[0], d[1], d[2], d[3], al[0], al[1], al[2], al[3], bp[0], bp[1]);
                }
            }
        }
        buf++; if (buf == 3) buf = 0;
    }
    #undef PREFETCH
    __syncthreads();    // smem reuse below

    const int g = lane >> 2, tq = lane & 3;

    if (bx < 16) {
        // -------- hedgehog epilogue: bias + softmax([y,-y]) -> fp16 ----------
        const int isQ = (bx < 8);
        const float* bias = isQ ? biasq : biask;
        const float scale = isQ ? 0.08838834764831845f : 1.0f;
        __half* fh = isQ ? Qfh : Kfh;
        __half* fl = isQ ? Qfl : nullptr;   // k features: hi-only (B operand)
        float* smax = (float*)smem;          // [4][128]
        float* ssum = smax + 512;            // [4][128]
        #pragma unroll
        for (int mt = 0; mt < 4; mt++) {
            float pm0 = 0.f, pm1 = 0.f;
            #pragma unroll
            for (int nt = 0; nt < 4; nt++) {
                const int cb = (wn*32 + nt*8 + tq*2) & 63;
                const float b0 = bias[cb], b1 = bias[cb + 1];
                float* d = acc[mt][nt];
                d[0] += b0; d[1] += b1; d[2] += b0; d[3] += b1;
                pm0 = fmaxf(pm0, fmaxf(fabsf(d[0]), fabsf(d[1])));
                pm1 = fmaxf(pm1, fmaxf(fabsf(d[2]), fabsf(d[3])));
            }
            pm0 = fmaxf(pm0, __shfl_xor_sync(0xffffffffu, pm0, 1));
            pm0 = fmaxf(pm0, __shfl_xor_sync(0xffffffffu, pm0, 2));
            pm1 = fmaxf(pm1, __shfl_xor_sync(0xffffffffu, pm1, 1));
            pm1 = fmaxf(pm1, __shfl_xor_sync(0xffffffffu, pm1, 2));
            if (tq == 0) {
                smax[wn*128 + wm*64 + mt*16 + g]     = pm0;
                smax[wn*128 + wm*64 + mt*16 + g + 8] = pm1;
            }
        }
        __syncthreads();
        float mrow[4][2];
        #pragma unroll
        for (int mt = 0; mt < 4; mt++) {
            #pragma unroll
            for (int half = 0; half < 2; half++) {
                const int r = wm*64 + mt*16 + g + half*8;
                mrow[mt][half] = fmaxf(smax[wn*128 + r], smax[(wn^1)*128 + r]);
            }
        }
        #pragma unroll
        for (int mt = 0; mt < 4; mt++) {
            float s0 = 0.f, s1 = 0.f;
            #pragma unroll
            for (int nt = 0; nt < 4; nt++) {
                const float* d = acc[mt][nt];
                s0 += __expf(d[0]-mrow[mt][0]) + __expf(-d[0]-mrow[mt][0])
                    + __expf(d[1]-mrow[mt][0]) + __expf(-d[1]-mrow[mt][0]);
                s1 += __expf(d[2]-mrow[mt][1]) + __expf(-d[2]-mrow[mt][1])
                    + __expf(d[3]-mrow[mt][1]) + __expf(-d[3]-mrow[mt][1]);
            }
            s0 += __shfl_xor_sync(0xffffffffu, s0, 1);
            s0 += __shfl_xor_sync(0xffffffffu, s0, 2);
            s1 += __shfl_xor_sync(0xffffffffu, s1, 1);
            s1 += __shfl_xor_sync(0xffffffffu, s1, 2);
            if (tq == 0) {
                ssum[wn*128 + wm*64 + mt*16 + g]     = s0;
                ssum[wn*128 + wm*64 + mt*16 + g + 8] = s1;
            }
        }
        __syncthreads();
        const int hloc = (bx & 7)*2 + (wn >> 1);
        #pragma unroll
        for (int mt = 0; mt < 4; mt++) {
            #pragma unroll
            for (int half = 0; half < 2; half++) {
                const int r = wm*64 + mt*16 + g + half*8;
                const float z = ssum[wn*128 + r] + ssum[(wn^1)*128 + r];
                const float inv = scale / z;
                const float mm = mrow[mt][half];
                const int rowg = by*128 + r;
                const int bb = rowg >> 11, tt = rowg & 2047;
                const size_t base = ((size_t)(bb*H_ + hloc)*T_ + tt)*F_;
                #pragma unroll
                for (int nt = 0; nt < 4; nt++) {
                    const int f = (wn*32 + nt*8 + tq*2) & 63;
                    const float y0 = acc[mt][nt][half*2], y1 = acc[mt][nt][half*2+1];
                    const float p0 = __expf(y0 - mm)*inv,  p1 = __expf(y1 - mm)*inv;
                    const float n0 = __expf(-y0 - mm)*inv, n1 = __expf(-y1 - mm)*inv;
                    __half h0, l0, h1, l1;
                    hsplit(p0, h0, l0); hsplit(p1, h1, l1);
                    *(__half2*)(fh + base + f) = __halves2half2(h0, h1);
                    if (fl) *(__half2*)(fl + base + f) = __halves2half2(l0, l1);
                    hsplit(n0, h0, l0); hsplit(n1, h1, l1);
                    *(__half2*)(fh + base + 64 + f) = __halves2half2(h0, h1);
                    if (fl) *(__half2*)(fl + base + 64 + f) = __halves2half2(l0, l1);
                }
            }
        }
    } else {
        // -------- v epilogue: fp16 hi/lo split ----
        const int colbase = (bx - 16)*128;
        #pragma unroll
        for (int mt = 0; mt < 4; mt++) {
            const int r0 = by*128 + wm*64 + mt*16 + g;
            #pragma unroll
            for (int nt = 0; nt < 4; nt++) {
                const int col = colbase + wn*32 + nt*8 + tq*2;
                float* d = acc[mt][nt];
                __half h0, l0, h1, l1;
                hsplit(d[0], h0, l0); hsplit(d[1], h1, l1);
                *(__half2*)(Vh + (size_t)r0*D_ + col) = __halves2half2(h0, h1);
                *(__half2*)(Vl + (size_t)r0*D_ + col) = __halves2half2(l0, l1);
                hsplit(d[2], h0, l0); hsplit(d[3], h1, l1);
                *(__half2*)(Vh + (size_t)(r0+8)*D_ + col) = __halves2half2(h0, h1);
                *(__half2*)(Vl + (size_t)(r0+8)*D_ + col) = __halves2half2(l0, l1);
            }
        }
    }
}

// ---------------- fp16x2 GEMM (fp32 out; o-projection) ------------------------
__global__ __launch_bounds__(256, 2)
void gemm_o(const __half* __restrict__ Ah, const __half* __restrict__ Al,
            const __half* __restrict__ W, float* __restrict__ Cout)
{
    extern __shared__ __align__(16) char smem[];
    const uint32_t sbase = smem_u32(smem);
    const int tid = threadIdx.x, wid = tid >> 5, lane = tid & 31;
    const int bx = blockIdx.x, by = blockIdx.y;
    const int wm = wid & 1, wn = wid >> 1;

    const int lrow = tid >> 1;
    const int lc   = (tid & 1) * 2;
    const size_t gA = (size_t)(by*128 + lrow) * D_;
    const size_t gB = (size_t)(bx*128 + lrow) * D_;
    const uint32_t sRow = (uint32_t)lrow * 80;

    float acc[4][4][4];
    #pragma unroll
    for (int i = 0; i < 4; i++)
        #pragma unroll
        for (int j = 0; j < 4; j++)
            #pragma unroll
            for (int l = 0; l < 4; l++) acc[i][j][l] = 0.f;

    #define PREFETCH(kt, buf) do {                                              \
        const int k0 = (kt) * 32;                                               \
        const uint32_t b0 = sbase + (uint32_t)(buf) * STAGE3;                   \
        _Pragma("unroll")                                                       \
        for (int u = 0; u < 2; u++) {                                           \
            const int c = lc + u;                                               \
            const uint32_t so = sRow + (uint32_t)c * 16;                        \
            const size_t go = (size_t)k0 + c * 8;                               \
            cp_async16(b0 + 0*MAT_BYTES + so, Ah + gA + go);                    \
            cp_async16(b0 + 1*MAT_BYTES + so, Al + gA + go);                    \
            cp_async16(b0 + 2*MAT_BYTES + so, W  + gB + go);                    \
        }                                                                       \
        cp_commit();                                                            \
    } while (0)

    PREFETCH(0, 0);
    PREFETCH(1, 1);

    const uint32_t aRow = (uint32_t)(wm*64 + (lane & 15)) * 80 + (uint32_t)(lane >> 4) * 16;
    const uint32_t bRow = (uint32_t)(wn*32 + ((lane >> 4) & 1)*8 + (lane & 7)) * 80
                        + (uint32_t)((lane >> 3) & 1) * 16;

    const int TILES = D_ / 32;
    int buf = 0;
    #pragma unroll 1
    for (int kt = 0; kt < TILES; kt++) {
        if (kt == TILES - 1) cp_wait<0>(); else cp_wait<1>();
        __syncthreads();
        if (kt + 2 < TILES) {
            int b2 = buf + 2; if (b2 >= 3) b2 -= 3;
            PREFETCH(kt + 2, b2);
        }
        const uint32_t sb = sbase + (uint32_t)buf * STAGE3;

        #pragma unroll
        for (int kk = 0; kk < 2; kk++) {
            const uint32_t koff = (uint32_t)kk * 32;
            uint32_t bw[2][4];
            #pragma unroll
            for (int nt2 = 0; nt2 < 2; nt2++) {
                const uint32_t ba = bRow + (uint32_t)nt2 * 16 * 80 + koff;
                ldm_x4(sb + 2*MAT_BYTES + ba, bw[nt2][0], bw[nt2][1], bw[nt2][2], bw[nt2][3]);
            }
            #pragma unroll
            for (int mt = 0; mt < 4; mt++) {
                const uint32_t aa = aRow + (uint32_t)mt * 16 * 80 + koff;
                uint32_t ah[4], al[4];
                ldm_x4(sb + 0*MAT_BYTES + aa, ah[0], ah[1], ah[2], ah[3]);
                ldm_x4(sb + 1*MAT_BYTES + aa, al[0], al[1], al[2], al[3]);
                #pragma unroll
                for (int nt = 0; nt < 4; nt++) {
                    const uint32_t* bp = &bw[nt >> 1][(nt & 1) * 2];
                    float* d = acc[mt][nt];
                    mma16816h(d[0], d[1], d[2], d[3], ah[0], ah[1], ah[2], ah[3], bp[0], bp[1]);
                    mma16816h(d[0], d[1], d[2], d[3], al[0], al[1], al[2], al[3], bp[0], bp[1]);
                }
            }
        }
        buf++; if (buf == 3) buf = 0;
    }
    #undef PREFETCH

    const int g = lane >> 2, tq = lane & 3;
    #pragma unroll
    for (int mt = 0; mt < 4; mt++) {
        const int r0 = by*128 + wm*64 + mt*16 + g;
        #pragma unroll
        for (int nt = 0; nt < 4; nt++) {
            const int col = bx*128 + wn*32 + nt*8 + tq*2;
            float* d = acc[mt][nt];
            *(float2*)(Cout + (size_t)r0*D_ + col)     = make_float2(d[0], d[1]);
            *(float2*)(Cout + (size_t)(r0+8)*D_ + col) = make_float2(d[2], d[3]);
        }
    }
}

// ---------------- phase A: kv^T[d][f] = sum_c v[c,d] k[c,f]  (fp16x2) --------
// A = vT split (VTH+VTL), B = kT single. 2 products.
#define CKV_KT  0u                         // [128 f][64 c] pitch 144 = 18432
#define CKV_VTH 18432u                     // [64 d][64 c] pitch 144 = 9216
#define CKV_VTL 27648u
#define CKV_SMEM 36864u

__global__ __launch_bounds__(256, 2)
void chunk_kv_kernel(const __half* __restrict__ kfh,
                     const __half* __restrict__ vh, const __half* __restrict__ vl,
                     float* __restrict__ kvT)
{
    extern __shared__ __align__(16) char smem[];
    const uint32_t sb = smem_u32(smem);
    const int blk = blockIdx.x;
    const int n = blk & 31, bh = blk >> 5;
    const int b = bh >> 4, h = bh & 15;
    const int tid = threadIdx.x, wid = tid >> 5, lane = tid & 31;

    // k features [c][f] -> kT[f][c] single
    {
        const int c = tid >> 2, fg = (tid & 3) * 32;
        const size_t src = ((size_t)bh*T_ + n*C_ + c)*F_ + fg;
        union { uint4 u; __half b[8]; } r;
        #pragma unroll
        for (int q = 0; q < 4; q++) {
            r.u = *(const uint4*)(kfh + src + q*8);
            #pragma unroll
            for (int i = 0; i < 8; i++)
                *(__half*)(smem + CKV_KT + (fg+q*8+i)*144 + c*2) = r.b[i];
        }
    }
    // v [c][d] -> vT[d][c] split
    {
        const int c = tid >> 2, dg = (tid & 3) * 16;
        const size_t src = ((size_t)(b*T_) + n*C_ + c)*D_ + h*HD_ + dg;
        union { uint4 u; __half b[8]; } r;
        #pragma unroll
        for (int q = 0; q < 2; q++) {
            r.u = *(const uint4*)(vh + src + q*8);
            #pragma unroll
            for (int i = 0; i < 8; i++)
                *(__half*)(smem + CKV_VTH + (dg+q*8+i)*144 + c*2) = r.b[i];
            r.u = *(const uint4*)(vl + src + q*8);
            #pragma unroll
            for (int i = 0; i < 8; i++)
                *(__half*)(smem + CKV_VTL + (dg+q*8+i)*144 + c*2) = r.b[i];
        }
    }
    __syncthreads();

    const int wm = wid & 3, wn = wid >> 2;
    float acc[8][4];
    #pragma unroll
    for (int i = 0; i < 8; i++)
        #pragma unroll
        for (int j = 0; j < 4; j++) acc[i][j] = 0.f;

    const uint32_t aBase = sb + CKV_VTH + (uint32_t)(wm*16 + (lane & 15))*144
                         + (uint32_t)(lane >> 4)*16;
    const uint32_t bBase = sb + CKV_KT + (uint32_t)(wn*64 + ((lane >> 4) & 1)*8 + (lane & 7))*144
                         + (uint32_t)((lane >> 3) & 1)*16;

    #pragma unroll
    for (int ks = 0; ks < 4; ks++) {
        const uint32_t koff = (uint32_t)ks*32;
        uint32_t ah[4], al[4];
        ldm_x4(aBase + koff, ah[0], ah[1], ah[2], ah[3]);
        ldm_x4(aBase + (CKV_VTL - CKV_VTH) + koff, al[0], al[1], al[2], al[3]);
        uint32_t bw[4][4];
        #pragma unroll
        for (int p = 0; p < 4; p++) {
            const uint32_t ba = bBase + (uint32_t)p*16*144 + koff;
            ldm_x4(ba, bw[p][0], bw[p][1], bw[p][2], bw[p][3]);
        }
        #pragma unroll
        for (int nt = 0; nt < 8; nt++) {
            const uint32_t* bp = &bw[nt >> 1][(nt & 1)*2];
            float* d = acc[nt];
            mma16816h(d[0], d[1], d[2], d[3], ah[0], ah[1], ah[2], ah[3], bp[0], bp[1]);
            mma16816h(d[0], d[1], d[2], d[3], al[0], al[1], al[2], al[3], bp[0], bp[1]);
        }
    }
    const int g = lane >> 2, tq = lane & 3;
    float* out = kvT + (size_t)blk * (F_*HD_);
    #pragma unroll
    for (int nt = 0; nt < 8; nt++) {
        const int f = wn*64 + nt*8 + tq*2;
        const int d0 = wm*16 + g;
        *(float2*)(out + (size_t)d0*F_ + f)     = make_float2(acc[nt][0], acc[nt][1]);
        *(float2*)(out + (size_t)(d0+8)*F_ + f) = make_float2(acc[nt][2], acc[nt][3]);
    }
}

// ---------------- phase B: exclusive cumsum -> single fp16 -------------------
__global__ __launch_bounds__(1024)
void kv_scan_kernel(const float* __restrict__ kvT, __half* __restrict__ ST)
{
    const int blk = blockIdx.x;
    const int bh = blk >> 3, seg = blk & 7;
    const int e = seg*1024 + threadIdx.x;
    size_t base = (size_t)bh * N_ * (F_*HD_) + e;
    float acc = 0.f;
    for (int n = 0; n < N_; n++) {
        size_t idx = base + (size_t)n * (F_*HD_);
        ST[idx] = __float2half_rn(acc);
        acc += kvT[idx];
    }
}

// ---------------- phase C: out = q@S_excl + tril(q@k^T)@v  (fp16x2) ----------
// A operands split (q, scores); B operands single (k, ST, v).
#define CO_QH  0u          // [64 c][128 f] pitch 272 = 17408
#define CO_QL  17408u
#define CO_KH  34816u      // k [c][f]; later ST [d][f]
#define CO_VT  52224u      // vT [64 d][64 c] pitch 144 = 9216
#define CO_SCH 61440u      // scores hi [64 c][64 m] pitch 144
#define CO_SCL 70656u
#define CO_SMEM 79872u

__global__ __launch_bounds__(256, 2)
void chunk_out_kernel(const __half* __restrict__ qfh, const __half* __restrict__ qfl,
                      const __half* __restrict__ kfh,
                      const __half* __restrict__ vh,
                      const __half* __restrict__ ST,
                      __half* __restrict__ oh, __half* __restrict__ ol)
{
    extern __shared__ __align__(16) char smem[];
    const uint32_t sb = smem_u32(smem);
    const int blk = blockIdx.x;
    const int n = blk & 31, bh = blk >> 5;
    const int b = bh >> 4, h = bh & 15;
    const int tid = threadIdx.x, wid = tid >> 5, lane = tid & 31;

    // q split + k single (row-major [c][f], pitch 272)
    {
        const int c = tid >> 2, fg = (tid & 3) * 32;
        const size_t src = ((size_t)bh*T_ + n*C_ + c)*F_ + fg;
        uint4* dq  = (uint4*)(smem + CO_QH + c*272 + fg*2);
        uint4* dql = (uint4*)(smem + CO_QL + c*272 + fg*2);
        uint4* dk  = (uint4*)(smem + CO_KH + c*272 + fg*2);
        #pragma unroll
        for (int q = 0; q < 4; q++) {
            dq [q] = *(const uint4*)(qfh + src + q*8);
            dql[q] = *(const uint4*)(qfl + src + q*8);
            dk [q] = *(const uint4*)(kfh + src + q*8);
        }
    }
    // v -> vT single
    {
        const int c = tid >> 2, dg = (tid & 3) * 16;
        const size_t src = ((size_t)(b*T_) + n*C_ + c)*D_ + h*HD_ + dg;
        union { uint4 u; __half bb[8]; } r;
        #pragma unroll
        for (int q = 0; q < 2; q++) {
            r.u = *(const uint4*)(vh + src + q*8);
            #pragma unroll
            for (int i = 0; i < 8; i++)
                *(__half*)(smem + CO_VT + (dg+q*8+i)*144 + c*2) = r.bb[i];
        }
    }
    __syncthreads();

    const int wm = wid & 3, wn = wid >> 2;
    const int g = lane >> 2, tq = lane & 3;

    const uint32_t aQ = sb + CO_QH + (uint32_t)(wm*16 + (lane & 15))*272 + (uint32_t)(lane >> 4)*16;
    const uint32_t bK = sb + CO_KH + (uint32_t)(wn*32 + ((lane >> 4) & 1)*8 + (lane & 7))*272
                      + (uint32_t)((lane >> 3) & 1)*16;

    // ---- scores = q @ k^T ----
    float sacc[4][4];
    #pragma unroll
    for (int i = 0; i < 4; i++)
        #pragma unroll
        for (int j = 0; j < 4; j++) sacc[i][j] = 0.f;

    #pragma unroll
    for (int ks = 0; ks < 8; ks++) {
        const uint32_t koff = (uint32_t)ks*32;
        uint32_t ah[4], al[4];
        ldm_x4(aQ + koff, ah[0], ah[1], ah[2], ah[3]);
        ldm_x4(aQ + (CO_QL - CO_QH) + koff, al[0], al[1], al[2], al[3]);
        uint32_t bw[2][4];
        #pragma unroll
        for (int p = 0; p < 2; p++) {
            const uint32_t ba = bK + (uint32_t)p*16*272 + koff;
            ldm_x4(ba, bw[p][0], bw[p][1], bw[p][2], bw[p][3]);
        }
        #pragma unroll
        for (int nt = 0; nt < 4; nt++) {
            const uint32_t* bp = &bw[nt >> 1][(nt & 1)*2];
            float* d = sacc[nt];
            mma16816h(d[0], d[1], d[2], d[3], ah[0], ah[1], ah[2], ah[3], bp[0], bp[1]);
            mma16816h(d[0], d[1], d[2], d[3], al[0], al[1], al[2], al[3], bp[0], bp[1]);
        }
    }
    // mask (m <= c), split-store scores
    #pragma unroll
    for (int nt = 0; nt < 4; nt++) {
        const int colb = wn*32 + nt*8 + tq*2;
        const int r0 = wm*16 + g, r1 = r0 + 8;
        float v00 = (colb     <= r0) ? sacc[nt][0] : 0.f;
        float v01 = (colb + 1 <= r0) ? sacc[nt][1] : 0.f;
        float v10 = (colb     <= r1) ? sacc[nt][2] : 0.f;
        float v11 = (colb + 1 <= r1) ? sacc[nt][3] : 0.f;
        __half h0, l0, h1, l1;
        hsplit(v00, h0, l0); hsplit(v01, h1, l1);
        *(__half2*)(smem + CO_SCH + r0*144 + colb*2) = __halves2half2(h0, h1);
        *(__half2*)(smem + CO_SCL + r0*144 + colb*2) = __halves2half2(l0, l1);
        hsplit(v10, h0, l0); hsplit(v11, h1, l1);
        *(__half2*)(smem + CO_SCH + r1*144 + colb*2) = __halves2half2(h0, h1);
        *(__half2*)(smem + CO_SCL + r1*144 + colb*2) = __halves2half2(l0, l1);
    }
    __syncthreads();

    // load S_excl^T [d][f] single into KH
    {
        const int d = tid >> 2, fg = (tid & 3) * 32;
        const size_t src = (size_t)blk*(F_*HD_) + d*F_ + fg;
        uint4* dh = (uint4*)(smem + CO_KH + d*272 + fg*2);
        #pragma unroll
        for (int q = 0; q < 4; q++)
            dh[q] = *(const uint4*)(ST + src + q*8);
    }
    __syncthreads();

    // ---- out = q @ S_excl + scores @ v ----
    float oacc[4][4];
    #pragma unroll
    for (int i = 0; i < 4; i++)
        #pragma unroll
        for (int j = 0; j < 4; j++) oacc[i][j] = 0.f;

    #pragma unroll
    for (int ks = 0; ks < 8; ks++) {     // inter
        const uint32_t koff = (uint32_t)ks*32;
        uint32_t ah[4], al[4];
        ldm_x4(aQ + koff, ah[0], ah[1], ah[2], ah[3]);
        ldm_x4(aQ + (CO_QL - CO_QH) + koff, al[0], al[1], al[2], al[3]);
        uint32_t bw[2][4];
        #pragma unroll
        for (int p = 0; p < 2; p++) {
            const uint32_t ba = bK + (uint32_t)p*16*272 + koff;
            ldm_x4(ba, bw[p][0], bw[p][1], bw[p][2], bw[p][3]);
        }
        #pragma unroll
        for (int nt = 0; nt < 4; nt++) {
            const uint32_t* bp = &bw[nt >> 1][(nt & 1)*2];
            float* d = oacc[nt];
            mma16816h(d[0], d[1], d[2], d[3], ah[0], ah[1], ah[2], ah[3], bp[0], bp[1]);
            mma16816h(d[0], d[1], d[2], d[3], al[0], al[1], al[2], al[3], bp[0], bp[1]);
        }
    }
    {   // intra: A = scores split, B = vT single
        const uint32_t aS = sb + CO_SCH + (uint32_t)(wm*16 + (lane & 15))*144
                          + (uint32_t)(lane >> 4)*16;
        const uint32_t bV = sb + CO_VT + (uint32_t)(wn*32 + ((lane >> 4) & 1)*8 + (lane & 7))*144
                          + (uint32_t)((lane >> 3) & 1)*16;
        #pragma unroll
        for (int ks = 0; ks < 4; ks++) {
            const uint32_t koff = (uint32_t)ks*32;
            uint32_t ah[4], al[4];
            ldm_x4(aS + koff, ah[0], ah[1], ah[2], ah[3]);
            ldm_x4(aS + (CO_SCL - CO_SCH) + koff, al[0], al[1], al[2], al[3]);
            uint32_t bw[2][4];
            #pragma unroll
            for (int p = 0; p < 2; p++) {
                const uint32_t ba = bV + (uint32_t)p*16*144 + koff;
                ldm_x4(ba, bw[p][0], bw[p][1], bw[p][2], bw[p][3]);
            }
            #pragma unroll
            for (int nt = 0; nt < 4; nt++) {
                const uint32_t* bp = &bw[nt >> 1][(nt & 1)*2];
                float* d = oacc[nt];
                mma16816h(d[0], d[1], d[2], d[3], ah[0], ah[1], ah[2], ah[3], bp[0], bp[1]);
                mma16816h(d[0], d[1], d[2], d[3], al[0], al[1], al[2], al[3], bp[0], bp[1]);
            }
        }
    }

    // write o as fp16 hi/lo in [B,T,H*HD] layout
    #pragma unroll
    for (int nt = 0; nt < 4; nt++) {
        const int dcol = wn*32 + nt*8 + tq*2;
        const int r0 = wm*16 + g;
        #pragma unroll
        for (int half = 0; half < 2; half++) {
            const int r = r0 + half*8;
            const float va = oacc[nt][half*2], vb = oacc[nt][half*2+1];
            __half ha, la, hb, lb;
            hsplit(va, ha, la); hsplit(vb, hb, lb);
            const size_t oidx = ((size_t)(b*T_) + n*C_ + r)*D_ + h*HD_ + dcol;
            *(__half2*)(oh + oidx) = __halves2half2(ha, hb);
            *(__half2*)(ol + oidx) = __halves2half2(la, lb);
        }
    }
}

// ---------------- launcher ----------------------------------------------------
extern "C" void kernel_launch(void* const* d_in, const int* in_sizes, int n_in,
                              void* d_out, int out_size)
{
    const float* hs   = (const float*)d_in[0];
    const float* res  = (const float*)d_in[1];
    const float* nw   = (const float*)d_in[2];
    const float* w_q  = (const float*)d_in[3];
    const float* w_k  = (const float*)d_in[4];
    const float* w_v  = (const float*)d_in[5];
    const float* w_o  = (const float*)d_in[6];
    const float* hqw  = (const float*)d_in[7];
    const float* hqb  = (const float*)d_in[8];
    const float* hkw  = (const float*)d_in[9];
    const float* hkb  = (const float*)d_in[10];
    float* out = (float*)d_out;

    float *pkv;
    __half *pxh, *pxl, *poh, *pol, *pwT, *pwo;
    __half *pqfh, *pqfl, *pkfh, *pvh, *pvl, *pST;
    cudaGetSymbolAddress((void**)&pkv,  g_kv);
    cudaGetSymbolAddress((void**)&pxh,  g_xh);
    cudaGetSymbolAddress((void**)&pxl,  g_xl);
    cudaGetSymbolAddress((void**)&poh,  g_oh);
    cudaGetSymbolAddress((void**)&pol,  g_ol);
    cudaGetSymbolAddress((void**)&pwT,  g_wT);
    cudaGetSymbolAddress((void**)&pwo,  g_woT);
    cudaGetSymbolAddress((void**)&pqfh, g_qfh);
    cudaGetSymbolAddress((void**)&pqfl, g_qfl);
    cudaGetSymbolAddress((void**)&pkfh, g_kfh);
    cudaGetSymbolAddress((void**)&pvh,  g_vh);
    cudaGetSymbolAddress((void**)&pvl,  g_vl);
    cudaGetSymbolAddress((void**)&pST,  g_ST);

    const int fsmem = (128*65 + 64*64) * sizeof(float);   // 49664
    cudaFuncSetAttribute(weightprep_kernel,
                         cudaFuncAttributeMaxDynamicSharedMemorySize, fsmem);
    cudaFuncSetAttribute(gemm_qkv,
                         cudaFuncAttributeMaxDynamicSharedMemorySize, GSMEM3);
    cudaFuncSetAttribute(gemm_o,
                         cudaFuncAttributeMaxDynamicSharedMemorySize, GSMEM3);
    cudaFuncSetAttribute(chunk_kv_kernel,
                         cudaFuncAttributeMaxDynamicSharedMemorySize, CKV_SMEM);
    cudaFuncSetAttribute(chunk_out_kernel,
                         cudaFuncAttributeMaxDynamicSharedMemorySize, CO_SMEM);

    // 1) weight prep (fold hedgehog into q/k; transpose v, o) -> fp16
    weightprep_kernel<<<dim3(16, 8, 4), 256, fsmem>>>(w_q, w_k, w_v, w_o, hqw, hkw, pwT, pwo);

    // 2+3) fused add + RMSNorm (two halves -> keeps gemm_qkv as launch #4)
    addnorm_kernel<<<BT_/2, 256>>>(hs, res, nw, out + (size_t)BT_*D_, pxh, pxl, 0);
    addnorm_kernel<<<BT_/2, 256>>>(hs, res, nw, out + (size_t)BT_*D_, pxh, pxl, BT_/2);

    // 4) fused QKV projection (fp16x2) + hedgehog epilogue
    dim3 qkvgrid(24, BT_/128);
    gemm_qkv<<<qkvgrid, 256, GSMEM3>>>(pxh, pxl, pwT, hqb, hkb,
                                       pqfh, pqfl, pkfh, pvh, pvl);

    // 5) chunked linear attention (fp16x2 tensor cores)
    chunk_kv_kernel<<<NCHUNK_, 256, CKV_SMEM>>>(pkfh, pvh, pvl, pkv);
    kv_scan_kernel<<<512, 1024>>>(pkv, pST);
    chunk_out_kernel<<<NCHUNK_, 256, CO_SMEM>>>(pqfh, pqfl, pkfh, pvh, pST, poh, pol);

    // 6) output projection (fp16x2)
    gemm_o<<<dim3(8, BT_/128), 256, GSMEM3>>>(poh, pol, pwo, out);
}

// round 10
// speedup vs baseline: 3.6489x; 1.0770x over previous
#include <cuda_runtime.h>
#include <cuda_bf16.h>
#include <cuda_fp16.h>
#include <stdint.h>
#include <math.h>

// Problem constants
#define B_  4
#define T_  2048
#define D_  1024
#define H_  16
#define HD_ 64
#define F_  128
#define C_  64
#define N_  32
#define BT_ (B_*T_)        // 8192
#define BHT_ (B_*H_*T_)    // 131072
#define NCHUNK_ (B_*H_*N_) // 2048

// ---------------- scratch (device globals) ----------------------------------
__device__ float g_kv[NCHUNK_*F_*HD_];          // kv^T per chunk: [d][f]
__device__ __half g_ST [NCHUNK_*F_*HD_];        // S_excl^T single fp16
__device__ __half g_qfh[BHT_*F_];               // q features single fp16
__device__ __half g_kfh[BHT_*F_];               // k features single fp16
__device__ __half g_vh [BT_*D_];                // v split
__device__ __half g_vl [BT_*D_];
__device__ __half g_xh[BT_*D_];                 // x split (fp16)
__device__ __half g_xl[BT_*D_];
__device__ __half g_oh[BT_*D_];                 // attention out split (fp16)
__device__ __half g_ol[BT_*D_];
__device__ __half g_wT [3*D_*D_];               // fused qkv weights, fp16 single
__device__ __half g_woT[D_*D_];                 // o weights, fp16 single

// ---------------- PTX helpers ------------------------------------------------
__device__ __forceinline__ uint32_t smem_u32(const void* p) {
    uint32_t a;
    asm("{ .reg .u64 t; cvta.to.shared.u64 t, %1; cvt.u32.u64 %0, t; }" : "=r"(a) : "l"(p));
    return a;
}
__device__ __forceinline__ void cp_async16(uint32_t saddr, const void* gaddr) {
    asm volatile("cp.async.cg.shared.global [%0], [%1], 16;" :: "r"(saddr), "l"(gaddr));
}
__device__ __forceinline__ void cp_commit() {
    asm volatile("cp.async.commit_group;" ::: "memory");
}
template <int NN>
__device__ __forceinline__ void cp_wait() {
    asm volatile("cp.async.wait_group %0;" :: "n"(NN) : "memory");
}
__device__ __forceinline__ void ldm_x4(uint32_t addr, uint32_t& r0, uint32_t& r1,
                                       uint32_t& r2, uint32_t& r3) {
    asm volatile("ldmatrix.sync.aligned.m8n8.x4.shared.b16 {%0,%1,%2,%3}, [%4];"
                 : "=r"(r0), "=r"(r1), "=r"(r2), "=r"(r3) : "r"(addr));
}
__device__ __forceinline__ void mma16816h(float& d0, float& d1, float& d2, float& d3,
                                          uint32_t a0, uint32_t a1, uint32_t a2, uint32_t a3,
                                          uint32_t b0, uint32_t b1) {
    asm volatile("mma.sync.aligned.m16n8k16.row.col.f32.f16.f16.f32 "
                 "{%0,%1,%2,%3}, {%4,%5,%6,%7}, {%8,%9}, {%0,%1,%2,%3};"
                 : "+f"(d0), "+f"(d1), "+f"(d2), "+f"(d3)
                 : "r"(a0), "r"(a1), "r"(a2), "r"(a3), "r"(b0), "r"(b1));
}
__device__ __forceinline__ void hsplit(float v, __half& h, __half& l) {
    h = __float2half_rn(v);
    l = __float2half_rn(v - __half2float(h));
}

// ---------------- weight prep: fold/transpose -> fp16, z-dispatched ----------
__global__ __launch_bounds__(256)
void weightprep_kernel(const float* __restrict__ wq, const float* __restrict__ wk,
                       const float* __restrict__ wv, const float* __restrict__ wo,
                       const float* __restrict__ hqw, const float* __restrict__ hkw,
                       __half* __restrict__ wT, __half* __restrict__ woT)
{
    extern __shared__ float fsm[];
    float* Wb = fsm;               // [128][65]
    float* hh = fsm + 128*65;      // [64][64]
    const int z = blockIdx.z;
    const float* W   = (z==0) ? wq : (z==1) ? wk : (z==2) ? wv : wo;
    const float* hhw = (z==0) ? hqw : (z==1) ? hkw : nullptr;
    __half* dst = (z==3) ? woT : wT;
    const int rowOff = (z==0) ? 0 : (z==1) ? 1024 : (z==2) ? 2048 : 0;

    const int h = blockIdx.x, kb = blockIdx.y;
    const int tid = threadIdx.x;
    for (int i = tid; i < 8192; i += 256) {
        int r = i >> 6, d = i & 63;
        Wb[r*65 + d] = W[(size_t)(kb*128 + r)*D_ + h*64 + d];
    }
    if (hhw)
        for (int i = tid; i < 4096; i += 256) hh[i] = hhw[i];
    __syncthreads();

    const int kk = tid & 127;
    const int e0 = (tid >> 7) * 32;
    float acc[32];
    if (hhw) {
        #pragma unroll
        for (int e = 0; e < 32; e++) acc[e] = 0.f;
        for (int d = 0; d < 64; d++) {
            float wv2 = Wb[kk*65 + d];
            #pragma unroll
            for (int e = 0; e < 32; e++)
                acc[e] = fmaf(wv2, hh[(e0+e)*64 + d], acc[e]);
        }
    } else {
        #pragma unroll
        for (int e = 0; e < 32; e++) acc[e] = Wb[kk*65 + e0 + e];
    }
    #pragma unroll
    for (int e = 0; e < 32; e++) {
        size_t idx = (size_t)(rowOff + h*64 + e0 + e)*D_ + kb*128 + kk;
        dst[idx] = __float2half_rn(acc[e]);
    }
}

// ---------------- fused add + RMSNorm -> resid + fp16 split x ----------------
__global__ __launch_bounds__(256)
void addnorm_kernel(const float* __restrict__ hs, const float* __restrict__ res,
                    const float* __restrict__ w, float* __restrict__ resid_out,
                    __half* __restrict__ xh, __half* __restrict__ xl, int rowOff)
{
    __shared__ float red[8];
    const int row = blockIdx.x + rowOff;
    const int t = threadIdx.x;
    const float4* h4 = (const float4*)(hs  + (size_t)row*D_);
    const float4* r4 = (const float4*)(res + (size_t)row*D_);
    float4*      ro4 = (float4*)(resid_out + (size_t)row*D_);

    float4 h = h4[t], r = r4[t];
    float4 s = make_float4(h.x+r.x, h.y+r.y, h.z+r.z, h.w+r.w);
    ro4[t] = s;
    float ss = s.x*s.x + s.y*s.y + s.z*s.z + s.w*s.w;
    #pragma unroll
    for (int o = 16; o; o >>= 1) ss += __shfl_xor_sync(0xffffffffu, ss, o);
    if ((t & 31) == 0) red[t >> 5] = ss;
    __syncthreads();
    float tot = 0.f;
    #pragma unroll
    for (int i = 0; i < 8; i++) tot += red[i];
    float rstd = rsqrtf(tot * (1.0f/1024.0f) + 1e-5f);
    float4 wv = ((const float4*)w)[t];
    float v[4] = { s.x*rstd*wv.x, s.y*rstd*wv.y, s.z*rstd*wv.z, s.w*rstd*wv.w };
    __half hi[4], lo[4];
    #pragma unroll
    for (int i = 0; i < 4; i++) hsplit(v[i], hi[i], lo[i]);
    size_t idx = (size_t)row*D_ + t*4;
    *(__half2*)(xh+idx)   = __halves2half2(hi[0], hi[1]);
    *(__half2*)(xh+idx+2) = __halves2half2(hi[2], hi[3]);
    *(__half2*)(xl+idx)   = __halves2half2(lo[0], lo[1]);
    *(__half2*)(xl+idx+2) = __halves2half2(lo[2], lo[3]);
}

// ---------------- fp16 fused QKV GEMM + hedgehog epilogue ---------------------
// q/k CTAs (bx<16): single-fp16 x (1 product). v CTAs (bx>=16): split x (2 products).
#define PITCH 40
#define MAT_BYTES (128*PITCH*2)          // 10240
#define STAGE3 (3*MAT_BYTES)             // 30720
#define GSMEM3 (3*STAGE3)                // 92160

__global__ __launch_bounds__(256, 2)
void gemm_qkv(const __half* __restrict__ Ah, const __half* __restrict__ Al,
              const __half* __restrict__ W,
              const float* __restrict__ biasq, const float* __restrict__ biask,
              __half* __restrict__ Qfh, __half* __restrict__ Kfh,
              __half* __restrict__ Vh,  __half* __restrict__ Vl)
{
    extern __shared__ __align__(16) char smem[];
    const uint32_t sbase = smem_u32(smem);
    const int tid = threadIdx.x, wid = tid >> 5, lane = tid & 31;
    const int bx = blockIdx.x, by = blockIdx.y;
    const int wm = wid & 1, wn = wid >> 1;
    const bool useLo = (bx >= 16);

    const int lrow = tid >> 1;
    const int lc   = (tid & 1) * 2;
    const size_t gA = (size_t)(by*128 + lrow) * D_;
    const size_t gB = (size_t)(bx*128 + lrow) * D_;
    const uint32_t sRow = (uint32_t)lrow * 80;

    float acc[4][4][4];
    #pragma unroll
    for (int i = 0; i < 4; i++)
        #pragma unroll
        for (int j = 0; j < 4; j++)
            #pragma unroll
            for (int l = 0; l < 4; l++) acc[i][j][l] = 0.f;

    #define PREFETCH(kt, buf) do {                                              \
        const int k0 = (kt) * 32;                                               \
        const uint32_t b0 = sbase + (uint32_t)(buf) * STAGE3;                   \
        _Pragma("unroll")                                                       \
        for (int u = 0; u < 2; u++) {                                           \
            const int c = lc + u;                                               \
            const uint32_t so = sRow + (uint32_t)c * 16;                        \
            const size_t go = (size_t)k0 + c * 8;                               \
            cp_async16(b0 + 0*MAT_BYTES + so, Ah + gA + go);                    \
            if (useLo) cp_async16(b0 + 1*MAT_BYTES + so, Al + gA + go);         \
            cp_async16(b0 + 2*MAT_BYTES + so, W  + gB + go);                    \
        }                                                                       \
        cp_commit();                                                            \
    } while (0)

    PREFETCH(0, 0);
    PREFETCH(1, 1);

    const uint32_t aRow = (uint32_t)(wm*64 + (lane & 15)) * 80 + (uint32_t)(lane >> 4) * 16;
    const uint32_t bRow = (uint32_t)(wn*32 + ((lane >> 4) & 1)*8 + (lane & 7)) * 80
                        + (uint32_t)((lane >> 3) & 1) * 16;

    const int TILES = D_ / 32;   // 32
    int buf = 0;
    #pragma unroll 1
    for (int kt = 0; kt < TILES; kt++) {
        if (kt == TILES - 1) cp_wait<0>(); else cp_wait<1>();
        __syncthreads();
        if (kt + 2 < TILES) {
            int b2 = buf + 2; if (b2 >= 3) b2 -= 3;
            PREFETCH(kt + 2, b2);
        }
        const uint32_t sb = sbase + (uint32_t)buf * STAGE3;

        #pragma unroll
        for (int kk = 0; kk < 2; kk++) {
            const uint32_t koff = (uint32_t)kk * 32;
            uint32_t bw[2][4];
            #pragma unroll
            for (int nt2 = 0; nt2 < 2; nt2++) {
                const uint32_t ba = bRow + (uint32_t)nt2 * 16 * 80 + koff;
                ldm_x4(sb + 2*MAT_BYTES + ba, bw[nt2][0], bw[nt2][1], bw[nt2][2], bw[nt2][3]);
            }
            #pragma unroll
            for (int mt = 0; mt < 4; mt++) {
                const uint32_t aa = aRow + (uint32_t)mt * 16 * 80 + koff;
                uint32_t ah[4];
                ldm_x4(sb + 0*MAT_BYTES + aa, ah[0], ah[1], ah[2], ah[3]);
                #pragma unroll
                for (int nt = 0; nt < 4; nt++) {
                    const uint32_t* bp = &bw[nt >> 1][(nt & 1) * 2];
                    float* d = acc[mt][nt];
                    mma16816h(d[0], d[1], d[2], d[3], ah[0], ah[1], ah[2], ah[3], bp[0], bp[1]);
                }
                if (useLo) {
                    uint32_t al[4];
                    ldm_x4(sb + 1*MAT_BYTES + aa, al[0], al[1], al[2], al[3]);
                    #pragma unroll
                    for (int nt = 0; nt < 4; nt++) {
                        const uint32_t* bp = &bw[nt >> 1][(nt & 1) * 2];
                        float* d = acc[mt][nt];
                        mma16816h(d[0], d[1], d[2], d[3], al[0], al[1], al[2], al[3], bp[0], bp[1]);
                    }
                }
            }
        }
        buf++; if (buf == 3) buf = 0;
    }
    #undef PREFETCH
    __syncthreads();    // smem reuse below

    const int g = lane >> 2, tq = lane & 3;

    if (bx < 16) {
        // -------- hedgehog epilogue: bias + softmax([y,-y]) -> fp16 ----------
        const int isQ = (bx < 8);
        const float* bias = isQ ? biasq : biask;
        const float scale = isQ ? 0.08838834764831845f : 1.0f;
        __half* fh = isQ ? Qfh : Kfh;
        float* smax = (float*)smem;          // [4][128]
        float* ssum = smax + 512;            // [4][128]
        #pragma unroll
        for (int mt = 0; mt < 4; mt++) {
            float pm0 = 0.f, pm1 = 0.f;
            #pragma unroll
            for (int nt = 0; nt < 4; nt++) {
                const int cb = (wn*32 + nt*8 + tq*2) & 63;
                const float b0 = bias[cb], b1 = bias[cb + 1];
                float* d = acc[mt][nt];
                d[0] += b0; d[1] += b1; d[2] += b0; d[3] += b1;
                pm0 = fmaxf(pm0, fmaxf(fabsf(d[0]), fabsf(d[1])));
                pm1 = fmaxf(pm1, fmaxf(fabsf(d[2]), fabsf(d[3])));
            }
            pm0 = fmaxf(pm0, __shfl_xor_sync(0xffffffffu, pm0, 1));
            pm0 = fmaxf(pm0, __shfl_xor_sync(0xffffffffu, pm0, 2));
            pm1 = fmaxf(pm1, __shfl_xor_sync(0xffffffffu, pm1, 1));
            pm1 = fmaxf(pm1, __shfl_xor_sync(0xffffffffu, pm1, 2));
            if (tq == 0) {
                smax[wn*128 + wm*64 + mt*16 + g]     = pm0;
                smax[wn*128 + wm*64 + mt*16 + g + 8] = pm1;
            }
        }
        __syncthreads();
        float mrow[4][2];
        #pragma unroll
        for (int mt = 0; mt < 4; mt++) {
            #pragma unroll
            for (int half = 0; half < 2; half++) {
                const int r = wm*64 + mt*16 + g + half*8;
                mrow[mt][half] = fmaxf(smax[wn*128 + r], smax[(wn^1)*128 + r]);
            }
        }
        #pragma unroll
        for (int mt = 0; mt < 4; mt++) {
            float s0 = 0.f, s1 = 0.f;
            #pragma unroll
            for (int nt = 0; nt < 4; nt++) {
                const float* d = acc[mt][nt];
                s0 += __expf(d[0]-mrow[mt][0]) + __expf(-d[0]-mrow[mt][0])
                    + __expf(d[1]-mrow[mt][0]) + __expf(-d[1]-mrow[mt][0]);
                s1 += __expf(d[2]-mrow[mt][1]) + __expf(-d[2]-mrow[mt][1])
                    + __expf(d[3]-mrow[mt][1]) + __expf(-d[3]-mrow[mt][1]);
            }
            s0 += __shfl_xor_sync(0xffffffffu, s0, 1);
            s0 += __shfl_xor_sync(0xffffffffu, s0, 2);
            s1 += __shfl_xor_sync(0xffffffffu, s1, 1);
            s1 += __shfl_xor_sync(0xffffffffu, s1, 2);
            if (tq == 0) {
                ssum[wn*128 + wm*64 + mt*16 + g]     = s0;
                ssum[wn*128 + wm*64 + mt*16 + g + 8] = s1;
            }
        }
        __syncthreads();
        const int hloc = (bx & 7)*2 + (wn >> 1);
        #pragma unroll
        for (int mt = 0; mt < 4; mt++) {
            #pragma unroll
            for (int half = 0; half < 2; half++) {
                const int r = wm*64 + mt*16 + g + half*8;
                const float z = ssum[wn*128 + r] + ssum[(wn^1)*128 + r];
                const float inv = scale / z;
                const float mm = mrow[mt][half];
                const int rowg = by*128 + r;
                const int bb = rowg >> 11, tt = rowg & 2047;
                const size_t base = ((size_t)(bb*H_ + hloc)*T_ + tt)*F_;
                #pragma unroll
                for (int nt = 0; nt < 4; nt++) {
                    const int f = (wn*32 + nt*8 + tq*2) & 63;
                    const float y0 = acc[mt][nt][half*2], y1 = acc[mt][nt][half*2+1];
                    const float p0 = __expf(y0 - mm)*inv,  p1 = __expf(y1 - mm)*inv;
                    const float n0 = __expf(-y0 - mm)*inv, n1 = __expf(-y1 - mm)*inv;
                    *(__half2*)(fh + base + f) =
                        __halves2half2(__float2half_rn(p0), __float2half_rn(p1));
                    *(__half2*)(fh + base + 64 + f) =
                        __halves2half2(__float2half_rn(n0), __float2half_rn(n1));
                }
            }
        }
    } else {
        // -------- v epilogue: fp16 hi/lo split ----
        const int colbase = (bx - 16)*128;
        #pragma unroll
        for (int mt = 0; mt < 4; mt++) {
            const int r0 = by*128 + wm*64 + mt*16 + g;
            #pragma unroll
            for (int nt = 0; nt < 4; nt++) {
                const int col = colbase + wn*32 + nt*8 + tq*2;
                float* d = acc[mt][nt];
                __half h0, l0, h1, l1;
                hsplit(d[0], h0, l0); hsplit(d[1], h1, l1);
                *(__half2*)(Vh + (size_t)r0*D_ + col) = __halves2half2(h0, h1);
                *(__half2*)(Vl + (size_t)r0*D_ + col) = __halves2half2(l0, l1);
                hsplit(d[2], h0, l0); hsplit(d[3], h1, l1);
                *(__half2*)(Vh + (size_t)(r0+8)*D_ + col) = __halves2half2(h0, h1);
                *(__half2*)(Vl + (size_t)(r0+8)*D_ + col) = __halves2half2(l0, l1);
            }
        }
    }
}

// ---------------- fp16x2 GEMM (fp32 out; o-projection) ------------------------
__global__ __launch_bounds__(256, 2)
void gemm_o(const __half* __restrict__ Ah, const __half* __restrict__ Al,
            const __half* __restrict__ W, float* __restrict__ Cout)
{
    extern __shared__ __align__(16) char smem[];
    const uint32_t sbase = smem_u32(smem);
    const int tid = threadIdx.x, wid = tid >> 5, lane = tid & 31;
    const int bx = blockIdx.x, by = blockIdx.y;
    const int wm = wid & 1, wn = wid >> 1;

    const int lrow = tid >> 1;
    const int lc   = (tid & 1) * 2;
    const size_t gA = (size_t)(by*128 + lrow) * D_;
    const size_t gB = (size_t)(bx*128 + lrow) * D_;
    const uint32_t sRow = (uint32_t)lrow * 80;

    float acc[4][4][4];
    #pragma unroll
    for (int i = 0; i < 4; i++)
        #pragma unroll
        for (int j = 0; j < 4; j++)
            #pragma unroll
            for (int l = 0; l < 4; l++) acc[i][j][l] = 0.f;

    #define PREFETCH(kt, buf) do {                                              \
        const int k0 = (kt) * 32;                                               \
        const uint32_t b0 = sbase + (uint32_t)(buf) * STAGE3;                   \
        _Pragma("unroll")                                                       \
        for (int u = 0; u < 2; u++) {                                           \
            const int c = lc + u;                                               \
            const uint32_t so = sRow + (uint32_t)c * 16;                        \
            const size_t go = (size_t)k0 + c * 8;                               \
            cp_async16(b0 + 0*MAT_BYTES + so, Ah + gA + go);                    \
            cp_async16(b0 + 1*MAT_BYTES + so, Al + gA + go);                    \
            cp_async16(b0 + 2*MAT_BYTES + so, W  + gB + go);                    \
        }                                                                       \
        cp_commit();                                                            \
    } while (0)

    PREFETCH(0, 0);
    PREFETCH(1, 1);

    const uint32_t aRow = (uint32_t)(wm*64 + (lane & 15)) * 80 + (uint32_t)(lane >> 4) * 16;
    const uint32_t bRow = (uint32_t)(wn*32 + ((lane >> 4) & 1)*8 + (lane & 7)) * 80
                        + (uint32_t)((lane >> 3) & 1) * 16;

    const int TILES = D_ / 32;
    int buf = 0;
    #pragma unroll 1
    for (int kt = 0; kt < TILES; kt++) {
        if (kt == TILES - 1) cp_wait<0>(); else cp_wait<1>();
        __syncthreads();
        if (kt + 2 < TILES) {
            int b2 = buf + 2; if (b2 >= 3) b2 -= 3;
            PREFETCH(kt + 2, b2);
        }
        const uint32_t sb = sbase + (uint32_t)buf * STAGE3;

        #pragma unroll
        for (int kk = 0; kk < 2; kk++) {
            const uint32_t koff = (uint32_t)kk * 32;
            uint32_t bw[2][4];
            #pragma unroll
            for (int nt2 = 0; nt2 < 2; nt2++) {
                const uint32_t ba = bRow + (uint32_t)nt2 * 16 * 80 + koff;
                ldm_x4(sb + 2*MAT_BYTES + ba, bw[nt2][0], bw[nt2][1], bw[nt2][2], bw[nt2][3]);
            }
            #pragma unroll
            for (int mt = 0; mt < 4; mt++) {
                const uint32_t aa = aRow + (uint32_t)mt * 16 * 80 + koff;
                uint32_t ah[4], al[4];
                ldm_x4(sb + 0*MAT_BYTES + aa, ah[0], ah[1], ah[2], ah[3]);
                ldm_x4(sb + 1*MAT_BYTES + aa, al[0], al[1], al[2], al[3]);
                #pragma unroll
                for (int nt = 0; nt < 4; nt++) {
                    const uint32_t* bp = &bw[nt >> 1][(nt & 1) * 2];
                    float* d = acc[mt][nt];
                    mma16816h(d[0], d[1], d[2], d[3], ah[0], ah[1], ah[2], ah[3], bp[0], bp[1]);
                    mma16816h(d[0], d[1], d[2], d[3], al[0], al[1], al[2], al[3], bp[0], bp[1]);
                }
            }
        }
        buf++; if (buf == 3) buf = 0;
    }
    #undef PREFETCH

    const int g = lane >> 2, tq = lane & 3;
    #pragma unroll
    for (int mt = 0; mt < 4; mt++) {
        const int r0 = by*128 + wm*64 + mt*16 + g;
        #pragma unroll
        for (int nt = 0; nt < 4; nt++) {
            const int col = bx*128 + wn*32 + nt*8 + tq*2;
            float* d = acc[mt][nt];
            *(float2*)(Cout + (size_t)r0*D_ + col)     = make_float2(d[0], d[1]);
            *(float2*)(Cout + (size_t)(r0+8)*D_ + col) = make_float2(d[2], d[3]);
        }
    }
}

// ---------------- phase A: kv^T[d][f] = sum_c v[c,d] k[c,f]  (fp16x2) --------
#define CKV_KT  0u                         // [128 f][64 c] pitch 144 = 18432
#define CKV_VTH 18432u                     // [64 d][64 c] pitch 144 = 9216
#define CKV_VTL 27648u
#define CKV_SMEM 36864u

__global__ __launch_bounds__(256, 2)
void chunk_kv_kernel(const __half* __restrict__ kfh,
                     const __half* __restrict__ vh, const __half* __restrict__ vl,
                     float* __restrict__ kvT)
{
    extern __shared__ __align__(16) char smem[];
    const uint32_t sb = smem_u32(smem);
    const int blk = blockIdx.x;
    const int n = blk & 31, bh = blk >> 5;
    const int b = bh >> 4, h = bh & 15;
    const int tid = threadIdx.x, wid = tid >> 5, lane = tid & 31;

    {
        const int c = tid >> 2, fg = (tid & 3) * 32;
        const size_t src = ((size_t)bh*T_ + n*C_ + c)*F_ + fg;
        union { uint4 u; __half b[8]; } r;
        #pragma unroll
        for (int q = 0; q < 4; q++) {
            r.u = *(const uint4*)(kfh + src + q*8);
            #pragma unroll
            for (int i = 0; i < 8; i++)
                *(__half*)(smem + CKV_KT + (fg+q*8+i)*144 + c*2) = r.b[i];
        }
    }
    {
        const int c = tid >> 2, dg = (tid & 3) * 16;
        const size_t src = ((size_t)(b*T_) + n*C_ + c)*D_ + h*HD_ + dg;
        union { uint4 u; __half b[8]; } r;
        #pragma unroll
        for (int q = 0; q < 2; q++) {
            r.u = *(const uint4*)(vh + src + q*8);
            #pragma unroll
            for (int i = 0; i < 8; i++)
                *(__half*)(smem + CKV_VTH + (dg+q*8+i)*144 + c*2) = r.b[i];
            r.u = *(const uint4*)(vl + src + q*8);
            #pragma unroll
            for (int i = 0; i < 8; i++)
                *(__half*)(smem + CKV_VTL + (dg+q*8+i)*144 + c*2) = r.b[i];
        }
    }
    __syncthreads();

    const int wm = wid & 3, wn = wid >> 2;
    float acc[8][4];
    #pragma unroll
    for (int i = 0; i < 8; i++)
        #pragma unroll
        for (int j = 0; j < 4; j++) acc[i][j] = 0.f;

    const uint32_t aBase = sb + CKV_VTH + (uint32_t)(wm*16 + (lane & 15))*144
                         + (uint32_t)(lane >> 4)*16;
    const uint32_t bBase = sb + CKV_KT + (uint32_t)(wn*64 + ((lane >> 4) & 1)*8 + (lane & 7))*144
                         + (uint32_t)((lane >> 3) & 1)*16;

    #pragma unroll
    for (int ks = 0; ks < 4; ks++) {
        const uint32_t koff = (uint32_t)ks*32;
        uint32_t ah[4], al[4];
        ldm_x4(aBase + koff, ah[0], ah[1], ah[2], ah[3]);
        ldm_x4(aBase + (CKV_VTL - CKV_VTH) + koff, al[0], al[1], al[2], al[3]);
        uint32_t bw[4][4];
        #pragma unroll
        for (int p = 0; p < 4; p++) {
            const uint32_t ba = bBase + (uint32_t)p*16*144 + koff;
            ldm_x4(ba, bw[p][0], bw[p][1], bw[p][2], bw[p][3]);
        }
        #pragma unroll
        for (int nt = 0; nt < 8; nt++) {
            const uint32_t* bp = &bw[nt >> 1][(nt & 1)*2];
            float* d = acc[nt];
            mma16816h(d[0], d[1], d[2], d[3], ah[0], ah[1], ah[2], ah[3], bp[0], bp[1]);
            mma16816h(d[0], d[1], d[2], d[3], al[0], al[1], al[2], al[3], bp[0], bp[1]);
        }
    }
    const int g = lane >> 2, tq = lane & 3;
    float* out = kvT + (size_t)blk * (F_*HD_);
    #pragma unroll
    for (int nt = 0; nt < 8; nt++) {
        const int f = wn*64 + nt*8 + tq*2;
        const int d0 = wm*16 + g;
        *(float2*)(out + (size_t)d0*F_ + f)     = make_float2(acc[nt][0], acc[nt][1]);
        *(float2*)(out + (size_t)(d0+8)*F_ + f) = make_float2(acc[nt][2], acc[nt][3]);
    }
}

// ---------------- phase B: exclusive cumsum -> single fp16 -------------------
__global__ __launch_bounds__(1024)
void kv_scan_kernel(const float* __restrict__ kvT, __half* __restrict__ ST)
{
    const int blk = blockIdx.x;
    const int bh = blk >> 3, seg = blk & 7;
    const int e = seg*1024 + threadIdx.x;
    size_t base = (size_t)bh * N_ * (F_*HD_) + e;
    float acc = 0.f;
    for (int n = 0; n < N_; n++) {
        size_t idx = base + (size_t)n * (F_*HD_);
        ST[idx] = __float2half_rn(acc);
        acc += kvT[idx];
    }
}

// ---------------- phase C: out = q@S_excl + tril(q@k^T)@v  (single fp16) -----
#define CO_Q   0u          // [64 c][128 f] pitch 272 = 17408
#define CO_K   17408u      // k [c][f]; later ST [d][f]
#define CO_VT  34816u      // vT [64 d][64 c] pitch 144 = 9216
#define CO_SC  44032u      // masked scores [64 c][64 m] pitch 144 = 9216
#define CO_SMEM 53248u

__global__ __launch_bounds__(256, 2)
void chunk_out_kernel(const __half* __restrict__ qfh,
                      const __half* __restrict__ kfh,
                      const __half* __restrict__ vh,
                      const __half* __restrict__ ST,
                      __half* __restrict__ oh, __half* __restrict__ ol)
{
    extern __shared__ __align__(16) char smem[];
    const uint32_t sb = smem_u32(smem);
    const int blk = blockIdx.x;
    const int n = blk & 31, bh = blk >> 5;
    const int b = bh >> 4, h = bh & 15;
    const int tid = threadIdx.x, wid = tid >> 5, lane = tid & 31;

    // q, k single (row-major [c][f], pitch 272)
    {
        const int c = tid >> 2, fg = (tid & 3) * 32;
        const size_t src = ((size_t)bh*T_ + n*C_ + c)*F_ + fg;
        uint4* dq = (uint4*)(smem + CO_Q + c*272 + fg*2);
        uint4* dk = (uint4*)(smem + CO_K + c*272 + fg*2);
        #pragma unroll
        for (int q = 0; q < 4; q++) {
            dq[q] = *(const uint4*)(qfh + src + q*8);
            dk[q] = *(const uint4*)(kfh + src + q*8);
        }
    }
    // v -> vT single
    {
        const int c = tid >> 2, dg = (tid & 3) * 16;
        const size_t src = ((size_t)(b*T_) + n*C_ + c)*D_ + h*HD_ + dg;
        union { uint4 u; __half bb[8]; } r;
        #pragma unroll
        for (int q = 0; q < 2; q++) {
            r.u = *(const uint4*)(vh + src + q*8);
            #pragma unroll
            for (int i = 0; i < 8; i++)
                *(__half*)(smem + CO_VT + (dg+q*8+i)*144 + c*2) = r.bb[i];
        }
    }
    __syncthreads();

    const int wm = wid & 3, wn = wid >> 2;
    const int g = lane >> 2, tq = lane & 3;

    const uint32_t aQ = sb + CO_Q + (uint32_t)(wm*16 + (lane & 15))*272 + (uint32_t)(lane >> 4)*16;
    const uint32_t bK = sb + CO_K + (uint32_t)(wn*32 + ((lane >> 4) & 1)*8 + (lane & 7))*272
                      + (uint32_t)((lane >> 3) & 1)*16;

    // ---- scores = q @ k^T ----
    float sacc[4][4];
    #pragma unroll
    for (int i = 0; i < 4; i++)
        #pragma unroll
        for (int j = 0; j < 4; j++) sacc[i][j] = 0.f;

    #pragma unroll
    for (int ks = 0; ks < 8; ks++) {
        const uint32_t koff = (uint32_t)ks*32;
        uint32_t ah[4];
        ldm_x4(aQ + koff, ah[0], ah[1], ah[2], ah[3]);
        uint32_t bw[2][4];
        #pragma unroll
        for (int p = 0; p < 2; p++) {
            const uint32_t ba = bK + (uint32_t)p*16*272 + koff;
            ldm_x4(ba, bw[p][0], bw[p][1], bw[p][2], bw[p][3]);
        }
        #pragma unroll
        for (int nt = 0; nt < 4; nt++) {
            const uint32_t* bp = &bw[nt >> 1][(nt & 1)*2];
            float* d = sacc[nt];
            mma16816h(d[0], d[1], d[2], d[3], ah[0], ah[1], ah[2], ah[3], bp[0], bp[1]);
        }
    }
    // mask (m <= c), store single-fp16 scores
    #pragma unroll
    for (int nt = 0; nt < 4; nt++) {
        const int colb = wn*32 + nt*8 + tq*2;
        const int r0 = wm*16 + g, r1 = r0 + 8;
        float v00 = (colb     <= r0) ? sacc[nt][0] : 0.f;
        float v01 = (colb + 1 <= r0) ? sacc[nt][1] : 0.f;
        float v10 = (colb     <= r1) ? sacc[nt][2] : 0.f;
        float v11 = (colb + 1 <= r1) ? sacc[nt][3] : 0.f;
        *(__half2*)(smem + CO_SC + r0*144 + colb*2) =
            __halves2half2(__float2half_rn(v00), __float2half_rn(v01));
        *(__half2*)(smem + CO_SC + r1*144 + colb*2) =
            __halves2half2(__float2half_rn(v10), __float2half_rn(v11));
    }
    __syncthreads();

    // load S_excl^T [d][f] single into K region
    {
        const int d = tid >> 2, fg = (tid & 3) * 32;
        const size_t src = (size_t)blk*(F_*HD_) + d*F_ + fg;
        uint4* dh = (uint4*)(smem + CO_K + d*272 + fg*2);
        #pragma unroll
        for (int q = 0; q < 4; q++)
            dh[q] = *(const uint4*)(ST + src + q*8);
    }
    __syncthreads();

    // ---- out = q @ S_excl + scores @ v ----
    float oacc[4][4];
    #pragma unroll
    for (int i = 0; i < 4; i++)
        #pragma unroll
        for (int j = 0; j < 4; j++) oacc[i][j] = 0.f;

    #pragma unroll
    for (int ks = 0; ks < 8; ks++) {     // inter
        const uint32_t koff = (uint32_t)ks*32;
        uint32_t ah[4];
        ldm_x4(aQ + koff, ah[0], ah[1], ah[2], ah[3]);
        uint32_t bw[2][4];
        #pragma unroll
        for (int p = 0; p < 2; p++) {
            const uint32_t ba = bK + (uint32_t)p*16*272 + koff;
            ldm_x4(ba, bw[p][0], bw[p][1], bw[p][2], bw[p][3]);
        }
        #pragma unroll
        for (int nt = 0; nt < 4; nt++) {
            const uint32_t* bp = &bw[nt >> 1][(nt & 1)*2];
            float* d = oacc[nt];
            mma16816h(d[0], d[1], d[2], d[3], ah[0], ah[1], ah[2], ah[3], bp[0], bp[1]);
        }
    }
    {   // intra: A = scores single, B = vT single
        const uint32_t aS = sb + CO_SC + (uint32_t)(wm*16 + (lane & 15))*144
                          + (uint32_t)(lane >> 4)*16;
        const uint32_t bV = sb + CO_VT + (uint32_t)(wn*32 + ((lane >> 4) & 1)*8 + (lane & 7))*144
                          + (uint32_t)((lane >> 3) & 1)*16;
        #pragma unroll
        for (int ks = 0; ks < 4; ks++) {
            const uint32_t koff = (uint32_t)ks*32;
            uint32_t ah[4];
            ldm_x4(aS + koff, ah[0], ah[1], ah[2], ah[3]);
            uint32_t bw[2][4];
            #pragma unroll
            for (int p = 0; p < 2; p++) {
                const uint32_t ba = bV + (uint32_t)p*16*144 + koff;
                ldm_x4(ba, bw[p][0], bw[p][1], bw[p][2], bw[p][3]);
            }
            #pragma unroll
            for (int nt = 0; nt < 4; nt++) {
                const uint32_t* bp = &bw[nt >> 1][(nt & 1)*2];
                float* d = oacc[nt];
                mma16816h(d[0], d[1], d[2], d[3], ah[0], ah[1], ah[2], ah[3], bp[0], bp[1]);
            }
        }
    }

    // write o as fp16 hi/lo in [B,T,H*HD] layout
    #pragma unroll
    for (int nt = 0; nt < 4; nt++) {
        const int dcol = wn*32 + nt*8 + tq*2;
        const int r0 = wm*16 + g;
        #pragma unroll
        for (int half = 0; half < 2; half++) {
            const int r = r0 + half*8;
            const float va = oacc[nt][half*2], vb = oacc[nt][half*2+1];
            __half ha, la, hb, lb;
            hsplit(va, ha, la); hsplit(vb, hb, lb);
            const size_t oidx = ((size_t)(b*T_) + n*C_ + r)*D_ + h*HD_ + dcol;
            *(__half2*)(oh + oidx) = __halves2half2(ha, hb);
            *(__half2*)(ol + oidx) = __halves2half2(la, lb);
        }
    }
}

// ---------------- launcher ----------------------------------------------------
extern "C" void kernel_launch(void* const* d_in, const int* in_sizes, int n_in,
                              void* d_out, int out_size)
{
    const float* hs   = (const float*)d_in[0];
    const float* res  = (const float*)d_in[1];
    const float* nw   = (const float*)d_in[2];
    const float* w_q  = (const float*)d_in[3];
    const float* w_k  = (const float*)d_in[4];
    const float* w_v  = (const float*)d_in[5];
    const float* w_o  = (const float*)d_in[6];
    const float* hqw  = (const float*)d_in[7];
    const float* hqb  = (const float*)d_in[8];
    const float* hkw  = (const float*)d_in[9];
    const float* hkb  = (const float*)d_in[10];
    float* out = (float*)d_out;

    float *pkv;
    __half *pxh, *pxl, *poh, *pol, *pwT, *pwo;
    __half *pqfh, *pkfh, *pvh, *pvl, *pST;
    cudaGetSymbolAddress((void**)&pkv,  g_kv);
    cudaGetSymbolAddress((void**)&pxh,  g_xh);
    cudaGetSymbolAddress((void**)&pxl,  g_xl);
    cudaGetSymbolAddress((void**)&poh,  g_oh);
    cudaGetSymbolAddress((void**)&pol,  g_ol);
    cudaGetSymbolAddress((void**)&pwT,  g_wT);
    cudaGetSymbolAddress((void**)&pwo,  g_woT);
    cudaGetSymbolAddress((void**)&pqfh, g_qfh);
    cudaGetSymbolAddress((void**)&pkfh, g_kfh);
    cudaGetSymbolAddress((void**)&pvh,  g_vh);
    cudaGetSymbolAddress((void**)&pvl,  g_vl);
    cudaGetSymbolAddress((void**)&pST,  g_ST);

    const int fsmem = (128*65 + 64*64) * sizeof(float);   // 49664
    cudaFuncSetAttribute(weightprep_kernel,
                         cudaFuncAttributeMaxDynamicSharedMemorySize, fsmem);
    cudaFuncSetAttribute(gemm_qkv,
                         cudaFuncAttributeMaxDynamicSharedMemorySize, GSMEM3);
    cudaFuncSetAttribute(gemm_o,
                         cudaFuncAttributeMaxDynamicSharedMemorySize, GSMEM3);
    cudaFuncSetAttribute(chunk_kv_kernel,
                         cudaFuncAttributeMaxDynamicSharedMemorySize, CKV_SMEM);
    cudaFuncSetAttribute(chunk_out_kernel,
                         cudaFuncAttributeMaxDynamicSharedMemorySize, CO_SMEM);

    // 1) weight prep (fold hedgehog into q/k; transpose v, o) -> fp16
    weightprep_kernel<<<dim3(16, 8, 4), 256, fsmem>>>(w_q, w_k, w_v, w_o, hqw, hkw, pwT, pwo);

    // 2+3) fused add + RMSNorm (two halves -> keeps gemm_qkv as launch #4)
    addnorm_kernel<<<BT_/2, 256>>>(hs, res, nw, out + (size_t)BT_*D_, pxh, pxl, 0);
    addnorm_kernel<<<BT_/2, 256>>>(hs, res, nw, out + (size_t)BT_*D_, pxh, pxl, BT_/2);

    // 4) fused QKV projection + hedgehog epilogue (q/k single-x, v split-x)
    dim3 qkvgrid(24, BT_/128);
    gemm_qkv<<<qkvgrid, 256, GSMEM3>>>(pxh, pxl, pwT, hqb, hkb,
                                       pqfh, pkfh, pvh, pvl);

    // 5) chunked linear attention (fp16 tensor cores)
    chunk_kv_kernel<<<NCHUNK_, 256, CKV_SMEM>>>(pkfh, pvh, pvl, pkv);
    kv_scan_kernel<<<512, 1024>>>(pkv, pST);
    chunk_out_kernel<<<NCHUNK_, 256, CO_SMEM>>>(pqfh, pkfh, pvh, pST, poh, pol);

    // 6) output projection (fp16x2)
    gemm_o<<<dim3(8, BT_/128), 256, GSMEM3>>>(poh, pol, pwo, out);
}

// round 11
// speedup vs baseline: 5.0235x; 1.3767x over previous
#include <cuda_runtime.h>
#include <cuda_bf16.h>
#include <cuda_fp16.h>
#include <stdint.h>
#include <math.h>

// Problem constants
#define B_  4
#define T_  2048
#define D_  1024
#define H_  16
#define HD_ 64
#define F_  128
#define C_  64
#define N_  32
#define BT_ (B_*T_)        // 8192
#define BHT_ (B_*H_*T_)    // 131072
#define NCHUNK_ (B_*H_*N_) // 2048

// ---------------- scratch (device globals) ----------------------------------
__device__ float g_kv[NCHUNK_*F_*HD_];          // kv^T per chunk: [d][f]
__device__ __half g_ST [NCHUNK_*F_*HD_];        // S_excl^T single fp16
__device__ __half g_qfh[BHT_*F_];               // q features single fp16
__device__ __half g_kfh[BHT_*F_];               // k features single fp16
__device__ __half g_vh [BT_*D_];                // v single fp16
__device__ __half g_xh [BT_*D_];                // x single fp16
__device__ __half g_oh [BT_*D_];                // attention out single fp16
__device__ __half g_wT [3*D_*D_];               // fused qkv weights, fp16 single
__device__ __half g_woT[D_*D_];                 // o weights, fp16 single

// ---------------- PTX helpers ------------------------------------------------
__device__ __forceinline__ uint32_t smem_u32(const void* p) {
    uint32_t a;
    asm("{ .reg .u64 t; cvta.to.shared.u64 t, %1; cvt.u32.u64 %0, t; }" : "=r"(a) : "l"(p));
    return a;
}
__device__ __forceinline__ void cp_async16(uint32_t saddr, const void* gaddr) {
    asm volatile("cp.async.cg.shared.global [%0], [%1], 16;" :: "r"(saddr), "l"(gaddr));
}
__device__ __forceinline__ void cp_commit() {
    asm volatile("cp.async.commit_group;" ::: "memory");
}
template <int NN>
__device__ __forceinline__ void cp_wait() {
    asm volatile("cp.async.wait_group %0;" :: "n"(NN) : "memory");
}
__device__ __forceinline__ void ldm_x4(uint32_t addr, uint32_t& r0, uint32_t& r1,
                                       uint32_t& r2, uint32_t& r3) {
    asm volatile("ldmatrix.sync.aligned.m8n8.x4.shared.b16 {%0,%1,%2,%3}, [%4];"
                 : "=r"(r0), "=r"(r1), "=r"(r2), "=r"(r3) : "r"(addr));
}
__device__ __forceinline__ void mma16816h(float& d0, float& d1, float& d2, float& d3,
                                          uint32_t a0, uint32_t a1, uint32_t a2, uint32_t a3,
                                          uint32_t b0, uint32_t b1) {
    asm volatile("mma.sync.aligned.m16n8k16.row.col.f32.f16.f16.f32 "
                 "{%0,%1,%2,%3}, {%4,%5,%6,%7}, {%8,%9}, {%0,%1,%2,%3};"
                 : "+f"(d0), "+f"(d1), "+f"(d2), "+f"(d3)
                 : "r"(a0), "r"(a1), "r"(a2), "r"(a3), "r"(b0), "r"(b1));
}

// ---------------- weight prep: fold/transpose -> fp16, z-dispatched ----------
__global__ __launch_bounds__(256)
void weightprep_kernel(const float* __restrict__ wq, const float* __restrict__ wk,
                       const float* __restrict__ wv, const float* __restrict__ wo,
                       const float* __restrict__ hqw, const float* __restrict__ hkw,
                       __half* __restrict__ wT, __half* __restrict__ woT)
{
    extern __shared__ float fsm[];
    float* Wb = fsm;               // [128][65]
    float* hh = fsm + 128*65;      // [64][64]
    const int z = blockIdx.z;
    const float* W   = (z==0) ? wq : (z==1) ? wk : (z==2) ? wv : wo;
    const float* hhw = (z==0) ? hqw : (z==1) ? hkw : nullptr;
    __half* dst = (z==3) ? woT : wT;
    const int rowOff = (z==0) ? 0 : (z==1) ? 1024 : (z==2) ? 2048 : 0;

    const int h = blockIdx.x, kb = blockIdx.y;
    const int tid = threadIdx.x;
    for (int i = tid; i < 8192; i += 256) {
        int r = i >> 6, d = i & 63;
        Wb[r*65 + d] = W[(size_t)(kb*128 + r)*D_ + h*64 + d];
    }
    if (hhw)
        for (int i = tid; i < 4096; i += 256) hh[i] = hhw[i];
    __syncthreads();

    const int kk = tid & 127;
    const int e0 = (tid >> 7) * 32;
    float acc[32];
    if (hhw) {
        #pragma unroll
        for (int e = 0; e < 32; e++) acc[e] = 0.f;
        for (int d = 0; d < 64; d++) {
            float wv2 = Wb[kk*65 + d];
            #pragma unroll
            for (int e = 0; e < 32; e++)
                acc[e] = fmaf(wv2, hh[(e0+e)*64 + d], acc[e]);
        }
    } else {
        #pragma unroll
        for (int e = 0; e < 32; e++) acc[e] = Wb[kk*65 + e0 + e];
    }
    #pragma unroll
    for (int e = 0; e < 32; e++) {
        size_t idx = (size_t)(rowOff + h*64 + e0 + e)*D_ + kb*128 + kk;
        dst[idx] = __float2half_rn(acc[e]);
    }
}

// ---------------- fused add + RMSNorm -> resid + fp16 x ----------------------
__global__ __launch_bounds__(256)
void addnorm_kernel(const float* __restrict__ hs, const float* __restrict__ res,
                    const float* __restrict__ w, float* __restrict__ resid_out,
                    __half* __restrict__ xh, int rowOff)
{
    __shared__ float red[8];
    const int row = blockIdx.x + rowOff;
    const int t = threadIdx.x;
    const float4* h4 = (const float4*)(hs  + (size_t)row*D_);
    const float4* r4 = (const float4*)(res + (size_t)row*D_);
    float4*      ro4 = (float4*)(resid_out + (size_t)row*D_);

    float4 h = h4[t], r = r4[t];
    float4 s = make_float4(h.x+r.x, h.y+r.y, h.z+r.z, h.w+r.w);
    ro4[t] = s;
    float ss = s.x*s.x + s.y*s.y + s.z*s.z + s.w*s.w;
    #pragma unroll
    for (int o = 16; o; o >>= 1) ss += __shfl_xor_sync(0xffffffffu, ss, o);
    if ((t & 31) == 0) red[t >> 5] = ss;
    __syncthreads();
    float tot = 0.f;
    #pragma unroll
    for (int i = 0; i < 8; i++) tot += red[i];
    float rstd = rsqrtf(tot * (1.0f/1024.0f) + 1e-5f);
    float4 wv = ((const float4*)w)[t];
    size_t idx = (size_t)row*D_ + t*4;
    *(__half2*)(xh+idx)   = __halves2half2(__float2half_rn(s.x*rstd*wv.x),
                                           __float2half_rn(s.y*rstd*wv.y));
    *(__half2*)(xh+idx+2) = __halves2half2(__float2half_rn(s.z*rstd*wv.z),
                                           __float2half_rn(s.w*rstd*wv.w));
}

// ---------------- fp16 fused QKV GEMM + hedgehog epilogue ---------------------
// All CTAs single-fp16 A and W. Stage = A + W = 2 matrices.
#define PITCH 40
#define MAT_BYTES (128*PITCH*2)          // 10240
#define STAGE3 (2*MAT_BYTES)             // 20480
#define GSMEM3 (3*STAGE3)                // 61440

__global__ __launch_bounds__(256, 2)
void gemm_qkv(const __half* __restrict__ Ah, const __half* __restrict__ W,
              const float* __restrict__ biasq, const float* __restrict__ biask,
              __half* __restrict__ Qfh, __half* __restrict__ Kfh,
              __half* __restrict__ Vh)
{
    extern __shared__ __align__(16) char smem[];
    const uint32_t sbase = smem_u32(smem);
    const int tid = threadIdx.x, wid = tid >> 5, lane = tid & 31;
    const int bx = blockIdx.x, by = blockIdx.y;
    const int wm = wid & 1, wn = wid >> 1;

    const int lrow = tid >> 1;
    const int lc   = (tid & 1) * 2;
    const size_t gA = (size_t)(by*128 + lrow) * D_;
    const size_t gB = (size_t)(bx*128 + lrow) * D_;
    const uint32_t sRow = (uint32_t)lrow * 80;

    float acc[4][4][4];
    #pragma unroll
    for (int i = 0; i < 4; i++)
        #pragma unroll
        for (int j = 0; j < 4; j++)
            #pragma unroll
            for (int l = 0; l < 4; l++) acc[i][j][l] = 0.f;

    #define PREFETCH(kt, buf) do {                                              \
        const int k0 = (kt) * 32;                                               \
        const uint32_t b0 = sbase + (uint32_t)(buf) * STAGE3;                   \
        _Pragma("unroll")                                                       \
        for (int u = 0; u < 2; u++) {                                           \
            const int c = lc + u;                                               \
            const uint32_t so = sRow + (uint32_t)c * 16;                        \
            const size_t go = (size_t)k0 + c * 8;                               \
            cp_async16(b0 + 0*MAT_BYTES + so, Ah + gA + go);                    \
            cp_async16(b0 + 1*MAT_BYTES + so, W  + gB + go);                    \
        }                                                                       \
        cp_commit();                                                            \
    } while (0)

    PREFETCH(0, 0);
    PREFETCH(1, 1);

    const uint32_t aRow = (uint32_t)(wm*64 + (lane & 15)) * 80 + (uint32_t)(lane >> 4) * 16;
    const uint32_t bRow = (uint32_t)(wn*32 + ((lane >> 4) & 1)*8 + (lane & 7)) * 80
                        + (uint32_t)((lane >> 3) & 1) * 16;

    const int TILES = D_ / 32;   // 32
    int buf = 0;
    #pragma unroll 1
    for (int kt = 0; kt < TILES; kt++) {
        if (kt == TILES - 1) cp_wait<0>(); else cp_wait<1>();
        __syncthreads();
        if (kt + 2 < TILES) {
            int b2 = buf + 2; if (b2 >= 3) b2 -= 3;
            PREFETCH(kt + 2, b2);
        }
        const uint32_t sb = sbase + (uint32_t)buf * STAGE3;

        #pragma unroll
        for (int kk = 0; kk < 2; kk++) {
            const uint32_t koff = (uint32_t)kk * 32;
            uint32_t bw[2][4];
            #pragma unroll
            for (int nt2 = 0; nt2 < 2; nt2++) {
                const uint32_t ba = bRow + (uint32_t)nt2 * 16 * 80 + koff;
                ldm_x4(sb + 1*MAT_BYTES + ba, bw[nt2][0], bw[nt2][1], bw[nt2][2], bw[nt2][3]);
            }
            #pragma unroll
            for (int mt = 0; mt < 4; mt++) {
                const uint32_t aa = aRow + (uint32_t)mt * 16 * 80 + koff;
                uint32_t ah[4];
                ldm_x4(sb + aa, ah[0], ah[1], ah[2], ah[3]);
                #pragma unroll
                for (int nt = 0; nt < 4; nt++) {
                    const uint32_t* bp = &bw[nt >> 1][(nt & 1) * 2];
                    float* d = acc[mt][nt];
                    mma16816h(d[0], d[1], d[2], d[3], ah[0], ah[1], ah[2], ah[3], bp[0], bp[1]);
                }
            }
        }
        buf++; if (buf == 3) buf = 0;
    }
    #undef PREFETCH
    __syncthreads();    // smem reuse below

    const int g = lane >> 2, tq = lane & 3;

    if (bx < 16) {
        // -------- hedgehog epilogue: bias + softmax([y,-y]) -> fp16 ----------
        const int isQ = (bx < 8);
        const float* bias = isQ ? biasq : biask;
        const float scale = isQ ? 0.08838834764831845f : 1.0f;
        __half* fh = isQ ? Qfh : Kfh;
        float* smax = (float*)smem;          // [4][128]
        float* ssum = smax + 512;            // [4][128]
        #pragma unroll
        for (int mt = 0; mt < 4; mt++) {
            float pm0 = 0.f, pm1 = 0.f;
            #pragma unroll
            for (int nt = 0; nt < 4; nt++) {
                const int cb = (wn*32 + nt*8 + tq*2) & 63;
                const float b0 = bias[cb], b1 = bias[cb + 1];
                float* d = acc[mt][nt];
                d[0] += b0; d[1] += b1; d[2] += b0; d[3] += b1;
                pm0 = fmaxf(pm0, fmaxf(fabsf(d[0]), fabsf(d[1])));
                pm1 = fmaxf(pm1, fmaxf(fabsf(d[2]), fabsf(d[3])));
            }
            pm0 = fmaxf(pm0, __shfl_xor_sync(0xffffffffu, pm0, 1));
            pm0 = fmaxf(pm0, __shfl_xor_sync(0xffffffffu, pm0, 2));
            pm1 = fmaxf(pm1, __shfl_xor_sync(0xffffffffu, pm1, 1));
            pm1 = fmaxf(pm1, __shfl_xor_sync(0xffffffffu, pm1, 2));
            if (tq == 0) {
                smax[wn*128 + wm*64 + mt*16 + g]     = pm0;
                smax[wn*128 + wm*64 + mt*16 + g + 8] = pm1;
            }
        }
        __syncthreads();
        float mrow[4][2];
        #pragma unroll
        for (int mt = 0; mt < 4; mt++) {
            #pragma unroll
            for (int half = 0; half < 2; half++) {
                const int r = wm*64 + mt*16 + g + half*8;
                mrow[mt][half] = fmaxf(smax[wn*128 + r], smax[(wn^1)*128 + r]);
            }
        }
        #pragma unroll
        for (int mt = 0; mt < 4; mt++) {
            float s0 = 0.f, s1 = 0.f;
            #pragma unroll
            for (int nt = 0; nt < 4; nt++) {
                const float* d = acc[mt][nt];
                s0 += __expf(d[0]-mrow[mt][0]) + __expf(-d[0]-mrow[mt][0])
                    + __expf(d[1]-mrow[mt][0]) + __expf(-d[1]-mrow[mt][0]);
                s1 += __expf(d[2]-mrow[mt][1]) + __expf(-d[2]-mrow[mt][1])
                    + __expf(d[3]-mrow[mt][1]) + __expf(-d[3]-mrow[mt][1]);
            }
            s0 += __shfl_xor_sync(0xffffffffu, s0, 1);
            s0 += __shfl_xor_sync(0xffffffffu, s0, 2);
            s1 += __shfl_xor_sync(0xffffffffu, s1, 1);
            s1 += __shfl_xor_sync(0xffffffffu, s1, 2);
            if (tq == 0) {
                ssum[wn*128 + wm*64 + mt*16 + g]     = s0;
                ssum[wn*128 + wm*64 + mt*16 + g + 8] = s1;
            }
        }
        __syncthreads();
        const int hloc = (bx & 7)*2 + (wn >> 1);
        #pragma unroll
        for (int mt = 0; mt < 4; mt++) {
            #pragma unroll
            for (int half = 0; half < 2; half++) {
                const int r = wm*64 + mt*16 + g + half*8;
                const float z = ssum[wn*128 + r] + ssum[(wn^1)*128 + r];
                const float inv = scale / z;
                const float mm = mrow[mt][half];
                const int rowg = by*128 + r;
                const int bb = rowg >> 11, tt = rowg & 2047;
                const size_t base = ((size_t)(bb*H_ + hloc)*T_ + tt)*F_;
                #pragma unroll
                for (int nt = 0; nt < 4; nt++) {
                    const int f = (wn*32 + nt*8 + tq*2) & 63;
                    const float y0 = acc[mt][nt][half*2], y1 = acc[mt][nt][half*2+1];
                    const float p0 = __expf(y0 - mm)*inv,  p1 = __expf(y1 - mm)*inv;
                    const float n0 = __expf(-y0 - mm)*inv, n1 = __expf(-y1 - mm)*inv;
                    *(__half2*)(fh + base + f) =
                        __halves2half2(__float2half_rn(p0), __float2half_rn(p1));
                    *(__half2*)(fh + base + 64 + f) =
                        __halves2half2(__float2half_rn(n0), __float2half_rn(n1));
                }
            }
        }
    } else {
        // -------- v epilogue: single fp16 ----
        const int colbase = (bx - 16)*128;
        #pragma unroll
        for (int mt = 0; mt < 4; mt++) {
            const int r0 = by*128 + wm*64 + mt*16 + g;
            #pragma unroll
            for (int nt = 0; nt < 4; nt++) {
                const int col = colbase + wn*32 + nt*8 + tq*2;
                float* d = acc[mt][nt];
                *(__half2*)(Vh + (size_t)r0*D_ + col) =
                    __halves2half2(__float2half_rn(d[0]), __float2half_rn(d[1]));
                *(__half2*)(Vh + (size_t)(r0+8)*D_ + col) =
                    __halves2half2(__float2half_rn(d[2]), __float2half_rn(d[3]));
            }
        }
    }
}

// ---------------- fp16 GEMM (fp32 out; o-projection, single-x) ---------------
__global__ __launch_bounds__(256, 2)
void gemm_o(const __half* __restrict__ Ah, const __half* __restrict__ W,
            float* __restrict__ Cout)
{
    extern __shared__ __align__(16) char smem[];
    const uint32_t sbase = smem_u32(smem);
    const int tid = threadIdx.x, wid = tid >> 5, lane = tid & 31;
    const int bx = blockIdx.x, by = blockIdx.y;
    const int wm = wid & 1, wn = wid >> 1;

    const int lrow = tid >> 1;
    const int lc   = (tid & 1) * 2;
    const size_t gA = (size_t)(by*128 + lrow) * D_;
    const size_t gB = (size_t)(bx*128 + lrow) * D_;
    const uint32_t sRow = (uint32_t)lrow * 80;

    float acc[4][4][4];
    #pragma unroll
    for (int i = 0; i < 4; i++)
        #pragma unroll
        for (int j = 0; j < 4; j++)
            #pragma unroll
            for (int l = 0; l < 4; l++) acc[i][j][l] = 0.f;

    #define PREFETCH(kt, buf) do {                                              \
        const int k0 = (kt) * 32;                                               \
        const uint32_t b0 = sbase + (uint32_t)(buf) * STAGE3;                   \
        _Pragma("unroll")                                                       \
        for (int u = 0; u < 2; u++) {                                           \
            const int c = lc + u;                                               \
            const uint32_t so = sRow + (uint32_t)c * 16;                        \
            const size_t go = (size_t)k0 + c * 8;                               \
            cp_async16(b0 + 0*MAT_BYTES + so, Ah + gA + go);                    \
            cp_async16(b0 + 1*MAT_BYTES + so, W  + gB + go);                    \
        }                                                                       \
        cp_commit();                                                            \
    } while (0)

    PREFETCH(0, 0);
    PREFETCH(1, 1);

    const uint32_t aRow = (uint32_t)(wm*64 + (lane & 15)) * 80 + (uint32_t)(lane >> 4) * 16;
    const uint32_t bRow = (uint32_t)(wn*32 + ((lane >> 4) & 1)*8 + (lane & 7)) * 80
                        + (uint32_t)((lane >> 3) & 1) * 16;

    const int TILES = D_ / 32;
    int buf = 0;
    #pragma unroll 1
    for (int kt = 0; kt < TILES; kt++) {
        if (kt == TILES - 1) cp_wait<0>(); else cp_wait<1>();
        __syncthreads();
        if (kt + 2 < TILES) {
            int b2 = buf + 2; if (b2 >= 3) b2 -= 3;
            PREFETCH(kt + 2, b2);
        }
        const uint32_t sb = sbase + (uint32_t)buf * STAGE3;

        #pragma unroll
        for (int kk = 0; kk < 2; kk++) {
            const uint32_t koff = (uint32_t)kk * 32;
            uint32_t bw[2][4];
            #pragma unroll
            for (int nt2 = 0; nt2 < 2; nt2++) {
                const uint32_t ba = bRow + (uint32_t)nt2 * 16 * 80 + koff;
                ldm_x4(sb + 1*MAT_BYTES + ba, bw[nt2][0], bw[nt2][1], bw[nt2][2], bw[nt2][3]);
            }
            #pragma unroll
            for (int mt = 0; mt < 4; mt++) {
                const uint32_t aa = aRow + (uint32_t)mt * 16 * 80 + koff;
                uint32_t ah[4];
                ldm_x4(sb + aa, ah[0], ah[1], ah[2], ah[3]);
                #pragma unroll
                for (int nt = 0; nt < 4; nt++) {
                    const uint32_t* bp = &bw[nt >> 1][(nt & 1) * 2];
                    float* d = acc[mt][nt];
                    mma16816h(d[0], d[1], d[2], d[3], ah[0], ah[1], ah[2], ah[3], bp[0], bp[1]);
                }
            }
        }
        buf++; if (buf == 3) buf = 0;
    }
    #undef PREFETCH

    const int g = lane >> 2, tq = lane & 3;
    #pragma unroll
    for (int mt = 0; mt < 4; mt++) {
        const int r0 = by*128 + wm*64 + mt*16 + g;
        #pragma unroll
        for (int nt = 0; nt < 4; nt++) {
            const int col = bx*128 + wn*32 + nt*8 + tq*2;
            float* d = acc[mt][nt];
            *(float2*)(Cout + (size_t)r0*D_ + col)     = make_float2(d[0], d[1]);
            *(float2*)(Cout + (size_t)(r0+8)*D_ + col) = make_float2(d[2], d[3]);
        }
    }
}

// ---------------- phase A: kv^T[d][f] = sum_c v[c,d] k[c,f]  (single fp16) ---
#define CKV_KT  0u                         // [128 f][64 c] pitch 144 = 18432
#define CKV_VT  18432u                     // [64 d][64 c] pitch 144 = 9216
#define CKV_SMEM 27648u

__global__ __launch_bounds__(256, 2)
void chunk_kv_kernel(const __half* __restrict__ kfh,
                     const __half* __restrict__ vh,
                     float* __restrict__ kvT)
{
    extern __shared__ __align__(16) char smem[];
    const uint32_t sb = smem_u32(smem);
    const int blk = blockIdx.x;
    const int n = blk & 31, bh = blk >> 5;
    const int b = bh >> 4, h = bh & 15;
    const int tid = threadIdx.x, wid = tid >> 5, lane = tid & 31;

    {
        const int c = tid >> 2, fg = (tid & 3) * 32;
        const size_t src = ((size_t)bh*T_ + n*C_ + c)*F_ + fg;
        union { uint4 u; __half b[8]; } r;
        #pragma unroll
        for (int q = 0; q < 4; q++) {
            r.u = *(const uint4*)(kfh + src + q*8);
            #pragma unroll
            for (int i = 0; i < 8; i++)
                *(__half*)(smem + CKV_KT + (fg+q*8+i)*144 + c*2) = r.b[i];
        }
    }
    {
        const int c = tid >> 2, dg = (tid & 3) * 16;
        const size_t src = ((size_t)(b*T_) + n*C_ + c)*D_ + h*HD_ + dg;
        union { uint4 u; __half b[8]; } r;
        #pragma unroll
        for (int q = 0; q < 2; q++) {
            r.u = *(const uint4*)(vh + src + q*8);
            #pragma unroll
            for (int i = 0; i < 8; i++)
                *(__half*)(smem + CKV_VT + (dg+q*8+i)*144 + c*2) = r.b[i];
        }
    }
    __syncthreads();

    const int wm = wid & 3, wn = wid >> 2;
    float acc[8][4];
    #pragma unroll
    for (int i = 0; i < 8; i++)
        #pragma unroll
        for (int j = 0; j < 4; j++) acc[i][j] = 0.f;

    const uint32_t aBase = sb + CKV_VT + (uint32_t)(wm*16 + (lane & 15))*144
                         + (uint32_t)(lane >> 4)*16;
    const uint32_t bBase = sb + CKV_KT + (uint32_t)(wn*64 + ((lane >> 4) & 1)*8 + (lane & 7))*144
                         + (uint32_t)((lane >> 3) & 1)*16;

    #pragma unroll
    for (int ks = 0; ks < 4; ks++) {
        const uint32_t koff = (uint32_t)ks*32;
        uint32_t ah[4];
        ldm_x4(aBase + koff, ah[0], ah[1], ah[2], ah[3]);
        uint32_t bw[4][4];
        #pragma unroll
        for (int p = 0; p < 4; p++) {
            const uint32_t ba = bBase + (uint32_t)p*16*144 + koff;
            ldm_x4(ba, bw[p][0], bw[p][1], bw[p][2], bw[p][3]);
        }
        #pragma unroll
        for (int nt = 0; nt < 8; nt++) {
            const uint32_t* bp = &bw[nt >> 1][(nt & 1)*2];
            float* d = acc[nt];
            mma16816h(d[0], d[1], d[2], d[3], ah[0], ah[1], ah[2], ah[3], bp[0], bp[1]);
        }
    }
    const int g = lane >> 2, tq = lane & 3;
    float* out = kvT + (size_t)blk * (F_*HD_);
    #pragma unroll
    for (int nt = 0; nt < 8; nt++) {
        const int f = wn*64 + nt*8 + tq*2;
        const int d0 = wm*16 + g;
        *(float2*)(out + (size_t)d0*F_ + f)     = make_float2(acc[nt][0], acc[nt][1]);
        *(float2*)(out + (size_t)(d0+8)*F_ + f) = make_float2(acc[nt][2], acc[nt][3]);
    }
}

// ---------------- phase B: exclusive cumsum -> single fp16 -------------------
__global__ __launch_bounds__(1024)
void kv_scan_kernel(const float* __restrict__ kvT, __half* __restrict__ ST)
{
    const int blk = blockIdx.x;
    const int bh = blk >> 3, seg = blk & 7;
    const int e = seg*1024 + threadIdx.x;
    size_t base = (size_t)bh * N_ * (F_*HD_) + e;
    float acc = 0.f;
    for (int n = 0; n < N_; n++) {
        size_t idx = base + (size_t)n * (F_*HD_);
        ST[idx] = __float2half_rn(acc);
        acc += kvT[idx];
    }
}

// ---------------- phase C: out = q@S_excl + tril(q@k^T)@v  (single fp16) -----
#define CO_Q   0u          // [64 c][128 f] pitch 272 = 17408
#define CO_K   17408u      // k [c][f]; later ST [d][f]
#define CO_VT  34816u      // vT [64 d][64 c] pitch 144 = 9216
#define CO_SC  44032u      // masked scores [64 c][64 m] pitch 144 = 9216
#define CO_SMEM 53248u

__global__ __launch_bounds__(256, 2)
void chunk_out_kernel(const __half* __restrict__ qfh,
                      const __half* __restrict__ kfh,
                      const __half* __restrict__ vh,
                      const __half* __restrict__ ST,
                      __half* __restrict__ oh)
{
    extern __shared__ __align__(16) char smem[];
    const uint32_t sb = smem_u32(smem);
    const int blk = blockIdx.x;
    const int n = blk & 31, bh = blk >> 5;
    const int b = bh >> 4, h = bh & 15;
    const int tid = threadIdx.x, wid = tid >> 5, lane = tid & 31;

    {
        const int c = tid >> 2, fg = (tid & 3) * 32;
        const size_t src = ((size_t)bh*T_ + n*C_ + c)*F_ + fg;
        uint4* dq = (uint4*)(smem + CO_Q + c*272 + fg*2);
        uint4* dk = (uint4*)(smem + CO_K + c*272 + fg*2);
        #pragma unroll
        for (int q = 0; q < 4; q++) {
            dq[q] = *(const uint4*)(qfh + src + q*8);
            dk[q] = *(const uint4*)(kfh + src + q*8);
        }
    }
    {
        const int c = tid >> 2, dg = (tid & 3) * 16;
        const size_t src = ((size_t)(b*T_) + n*C_ + c)*D_ + h*HD_ + dg;
        union { uint4 u; __half bb[8]; } r;
        #pragma unroll
        for (int q = 0; q < 2; q++) {
            r.u = *(const uint4*)(vh + src + q*8);
            #pragma unroll
            for (int i = 0; i < 8; i++)
                *(__half*)(smem + CO_VT + (dg+q*8+i)*144 + c*2) = r.bb[i];
        }
    }
    __syncthreads();

    const int wm = wid & 3, wn = wid >> 2;
    const int g = lane >> 2, tq = lane & 3;

    const uint32_t aQ = sb + CO_Q + (uint32_t)(wm*16 + (lane & 15))*272 + (uint32_t)(lane >> 4)*16;
    const uint32_t bK = sb + CO_K + (uint32_t)(wn*32 + ((lane >> 4) & 1)*8 + (lane & 7))*272
                      + (uint32_t)((lane >> 3) & 1)*16;

    // ---- scores = q @ k^T ----
    float sacc[4][4];
    #pragma unroll
    for (int i = 0; i < 4; i++)
        #pragma unroll
        for (int j = 0; j < 4; j++) sacc[i][j] = 0.f;

    #pragma unroll
    for (int ks = 0; ks < 8; ks++) {
        const uint32_t koff = (uint32_t)ks*32;
        uint32_t ah[4];
        ldm_x4(aQ + koff, ah[0], ah[1], ah[2], ah[3]);
        uint32_t bw[2][4];
        #pragma unroll
        for (int p = 0; p < 2; p++) {
            const uint32_t ba = bK + (uint32_t)p*16*272 + koff;
            ldm_x4(ba, bw[p][0], bw[p][1], bw[p][2], bw[p][3]);
        }
        #pragma unroll
        for (int nt = 0; nt < 4; nt++) {
            const uint32_t* bp = &bw[nt >> 1][(nt & 1)*2];
            float* d = sacc[nt];
            mma16816h(d[0], d[1], d[2], d[3], ah[0], ah[1], ah[2], ah[3], bp[0], bp[1]);
        }
    }
    #pragma unroll
    for (int nt = 0; nt < 4; nt++) {
        const int colb = wn*32 + nt*8 + tq*2;
        const int r0 = wm*16 + g, r1 = r0 + 8;
        float v00 = (colb     <= r0) ? sacc[nt][0] : 0.f;
        float v01 = (colb + 1 <= r0) ? sacc[nt][1] : 0.f;
        float v10 = (colb     <= r1) ? sacc[nt][2] : 0.f;
        float v11 = (colb + 1 <= r1) ? sacc[nt][3] : 0.f;
        *(__half2*)(smem + CO_SC + r0*144 + colb*2) =
            __halves2half2(__float2half_rn(v00), __float2half_rn(v01));
        *(__half2*)(smem + CO_SC + r1*144 + colb*2) =
            __halves2half2(__float2half_rn(v10), __float2half_rn(v11));
    }
    __syncthreads();

    {
        const int d = tid >> 2, fg = (tid & 3) * 32;
        const size_t src = (size_t)blk*(F_*HD_) + d*F_ + fg;
        uint4* dh = (uint4*)(smem + CO_K + d*272 + fg*2);
        #pragma unroll
        for (int q = 0; q < 4; q++)
            dh[q] = *(const uint4*)(ST + src + q*8);
    }
    __syncthreads();

    // ---- out = q @ S_excl + scores @ v ----
    float oacc[4][4];
    #pragma unroll
    for (int i = 0; i < 4; i++)
        #pragma unroll
        for (int j = 0; j < 4; j++) oacc[i][j] = 0.f;

    #pragma unroll
    for (int ks = 0; ks < 8; ks++) {     // inter
        const uint32_t koff = (uint32_t)ks*32;
        uint32_t ah[4];
        ldm_x4(aQ + koff, ah[0], ah[1], ah[2], ah[3]);
        uint32_t bw[2][4];
        #pragma unroll
        for (int p = 0; p < 2; p++) {
            const uint32_t ba = bK + (uint32_t)p*16*272 + koff;
            ldm_x4(ba, bw[p][0], bw[p][1], bw[p][2], bw[p][3]);
        }
        #pragma unroll
        for (int nt = 0; nt < 4; nt++) {
            const uint32_t* bp = &bw[nt >> 1][(nt & 1)*2];
            float* d = oacc[nt];
            mma16816h(d[0], d[1], d[2], d[3], ah[0], ah[1], ah[2], ah[3], bp[0], bp[1]);
        }
    }
    {   // intra
        const uint32_t aS = sb + CO_SC + (uint32_t)(wm*16 + (lane & 15))*144
                          + (uint32_t)(lane >> 4)*16;
        const uint32_t bV = sb + CO_VT + (uint32_t)(wn*32 + ((lane >> 4) & 1)*8 + (lane & 7))*144
                          + (uint32_t)((lane >> 3) & 1)*16;
        #pragma unroll
        for (int ks = 0; ks < 4; ks++) {
            const uint32_t koff = (uint32_t)ks*32;
            uint32_t ah[4];
            ldm_x4(aS + koff, ah[0], ah[1], ah[2], ah[3]);
            uint32_t bw[2][4];
            #pragma unroll
            for (int p = 0; p < 2; p++) {
                const uint32_t ba = bV + (uint32_t)p*16*144 + koff;
                ldm_x4(ba, bw[p][0], bw[p][1], bw[p][2], bw[p][3]);
            }
            #pragma unroll
            for (int nt = 0; nt < 4; nt++) {
                const uint32_t* bp = &bw[nt >> 1][(nt & 1)*2];
                float* d = oacc[nt];
                mma16816h(d[0], d[1], d[2], d[3], ah[0], ah[1], ah[2], ah[3], bp[0], bp[1]);
            }
        }
    }

    // write o single fp16 in [B,T,H*HD] layout
    #pragma unroll
    for (int nt = 0; nt < 4; nt++) {
        const int dcol = wn*32 + nt*8 + tq*2;
        const int r0 = wm*16 + g;
        #pragma unroll
        for (int half = 0; half < 2; half++) {
            const int r = r0 + half*8;
            const size_t oidx = ((size_t)(b*T_) + n*C_ + r)*D_ + h*HD_ + dcol;
            *(__half2*)(oh + oidx) =
                __halves2half2(__float2half_rn(oacc[nt][half*2]),
                               __float2half_rn(oacc[nt][half*2+1]));
        }
    }
}

// ---------------- launcher ----------------------------------------------------
extern "C" void kernel_launch(void* const* d_in, const int* in_sizes, int n_in,
                              void* d_out, int out_size)
{
    const float* hs   = (const float*)d_in[0];
    const float* res  = (const float*)d_in[1];
    const float* nw   = (const float*)d_in[2];
    const float* w_q  = (const float*)d_in[3];
    const float* w_k  = (const float*)d_in[4];
    const float* w_v  = (const float*)d_in[5];
    const float* w_o  = (const float*)d_in[6];
    const float* hqw  = (const float*)d_in[7];
    const float* hqb  = (const float*)d_in[8];
    const float* hkw  = (const float*)d_in[9];
    const float* hkb  = (const float*)d_in[10];
    float* out = (float*)d_out;

    float *pkv;
    __half *pxh, *poh, *pwT, *pwo, *pqfh, *pkfh, *pvh, *pST;
    cudaGetSymbolAddress((void**)&pkv,  g_kv);
    cudaGetSymbolAddress((void**)&pxh,  g_xh);
    cudaGetSymbolAddress((void**)&poh,  g_oh);
    cudaGetSymbolAddress((void**)&pwT,  g_wT);
    cudaGetSymbolAddress((void**)&pwo,  g_woT);
    cudaGetSymbolAddress((void**)&pqfh, g_qfh);
    cudaGetSymbolAddress((void**)&pkfh, g_kfh);
    cudaGetSymbolAddress((void**)&pvh,  g_vh);
    cudaGetSymbolAddress((void**)&pST,  g_ST);

    const int fsmem = (128*65 + 64*64) * sizeof(float);   // 49664
    cudaFuncSetAttribute(weightprep_kernel,
                         cudaFuncAttributeMaxDynamicSharedMemorySize, fsmem);
    cudaFuncSetAttribute(gemm_qkv,
                         cudaFuncAttributeMaxDynamicSharedMemorySize, GSMEM3);
    cudaFuncSetAttribute(gemm_o,
                         cudaFuncAttributeMaxDynamicSharedMemorySize, GSMEM3);
    cudaFuncSetAttribute(chunk_kv_kernel,
                         cudaFuncAttributeMaxDynamicSharedMemorySize, CKV_SMEM);
    cudaFuncSetAttribute(chunk_out_kernel,
                         cudaFuncAttributeMaxDynamicSharedMemorySize, CO_SMEM);

    // 1) weight prep (fold hedgehog into q/k; transpose v, o) -> fp16
    weightprep_kernel<<<dim3(16, 8, 4), 256, fsmem>>>(w_q, w_k, w_v, w_o, hqw, hkw, pwT, pwo);

    // 2+3) fused add + RMSNorm (two halves -> keeps gemm_qkv as launch #4)
    addnorm_kernel<<<BT_/2, 256>>>(hs, res, nw, out + (size_t)BT_*D_, pxh, 0);
    addnorm_kernel<<<BT_/2, 256>>>(hs, res, nw, out + (size_t)BT_*D_, pxh, BT_/2);

    // 4) fused QKV projection + hedgehog epilogue (all single fp16)
    dim3 qkvgrid(24, BT_/128);
    gemm_qkv<<<qkvgrid, 256, GSMEM3>>>(pxh, pwT, hqb, hkb, pqfh, pkfh, pvh);

    // 5) chunked linear attention (single fp16 tensor cores)
    chunk_kv_kernel<<<NCHUNK_, 256, CKV_SMEM>>>(pkfh, pvh, pkv);
    kv_scan_kernel<<<512, 1024>>>(pkv, pST);
    chunk_out_kernel<<<NCHUNK_, 256, CO_SMEM>>>(pqfh, pkfh, pvh, pST, poh);

    // 6) output projection (single fp16)
    gemm_o<<<dim3(8, BT_/128), 256, GSMEM3>>>(poh, pwo, out);
}